// round 1
// baseline (speedup 1.0000x reference)
#include <cuda_runtime.h>
#include <math.h>

#define TT 262144
#define DD 128
#define HH 256
#define AA 8

// ---------------- scratch (device globals; no allocation allowed) ----------------
__device__ float  g_v0[TT];
__device__ float  g_v1[TT];
__device__ float  g_adv[TT];
__device__ double g_part[8][2];     // per-scan-block {sum, sumsq}
__device__ float  g_mean, g_isd;    // mean, 1/(std+1e-7)
__device__ double g_closs;          // critic loss = sum adv^2
__device__ float  g_apart[4096];    // per actor-block partial of sum(min(...))

__device__ __forceinline__ float fast_tanh(float x) {
    float y;
    asm("tanh.approx.f32 %0, %1;" : "=f"(y) : "f"(x));
    return y;
}

// ---------------- fused critic: out[t] = tanh(X@Wc1+bc1)@Wc2 + bc2 ----------------
// BM=64 rows, BN=256 (full H), BK=16. 256 threads: 8 warps (ty=row group), 32 lanes (tx=col group).
// Each thread: 8x8 microtile. Epilogue: tanh + dot with Wc2, warp shuffle reduce.
__global__ __launch_bounds__(256) void critic_kernel(
    const float* __restrict__ X,
    const float* __restrict__ Wc1, const float* __restrict__ bc1,
    const float* __restrict__ Wc2, const float* __restrict__ bc2,
    int which)
{
    __shared__ float As[16][68];      // [k][m], padded
    __shared__ float Bs[16][256];     // [k][n]
    __shared__ float b1s[256];
    __shared__ float w2s[256];

    const int tid = threadIdx.x;
    const int tx  = tid & 31;
    const int ty  = tid >> 5;
    const int t0  = blockIdx.x * 64;

    b1s[tid] = bc1[tid];
    w2s[tid] = Wc2[tid];

    float acc[8][8];
    #pragma unroll
    for (int r = 0; r < 8; r++)
        #pragma unroll
        for (int c = 0; c < 8; c++) acc[r][c] = 0.f;

    for (int k0 = 0; k0 < DD; k0 += 16) {
        // A tile: 64 rows x 16 k, transposed into As[k][m]
        {
            int i = tid >> 2, jq = tid & 3;
            float4 v = *reinterpret_cast<const float4*>(&X[(size_t)(t0 + i) * DD + k0 + jq * 4]);
            As[jq * 4 + 0][i] = v.x;
            As[jq * 4 + 1][i] = v.y;
            As[jq * 4 + 2][i] = v.z;
            As[jq * 4 + 3][i] = v.w;
        }
        // B tile: 16 k x 256 n
        #pragma unroll
        for (int q = 0; q < 4; q++) {
            int idx = tid + q * 256;          // float4 index, 1024 total
            int j = idx >> 6, c4 = idx & 63;
            float4 v = *reinterpret_cast<const float4*>(&Wc1[(size_t)(k0 + j) * HH + c4 * 4]);
            *reinterpret_cast<float4*>(&Bs[j][c4 * 4]) = v;
        }
        __syncthreads();
        #pragma unroll
        for (int k = 0; k < 16; k++) {
            float a[8], b[8];
            #pragma unroll
            for (int r = 0; r < 8; r++) a[r] = As[k][ty * 8 + r];
            #pragma unroll
            for (int c = 0; c < 8; c++) b[c] = Bs[k][tx * 8 + c];
            #pragma unroll
            for (int r = 0; r < 8; r++)
                #pragma unroll
                for (int c = 0; c < 8; c++) acc[r][c] = fmaf(a[r], b[c], acc[r][c]);
        }
        __syncthreads();
    }

    float* out = which ? g_v1 : g_v0;
    const float bc2v = bc2[0];
    #pragma unroll
    for (int r = 0; r < 8; r++) {
        float pv = 0.f;
        #pragma unroll
        for (int c = 0; c < 8; c++) {
            float h = fast_tanh(acc[r][c] + b1s[tx * 8 + c]);
            pv = fmaf(h, w2s[tx * 8 + c], pv);
        }
        #pragma unroll
        for (int off = 16; off > 0; off >>= 1)
            pv += __shfl_xor_sync(0xffffffffu, pv, off);
        if (tx == 0) out[t0 + ty * 8 + r] = pv + bc2v;
    }
}

// ---------------- GAE scan + advantage + partial stats ----------------
// 1024 chunks of C=256; lookahead W=1024 makes truncation below fp32 precision (c^1025 ~ 5e-28).
__global__ void scan_kernel(const float* __restrict__ reward)
{
    const int C = 256, W = 1024;
    const int chunk = blockIdx.x * blockDim.x + threadIdx.x;   // 8 blocks x 128 = 1024
    const int t0 = chunk * C;
    const int start = min(TT, t0 + C + W);
    const float GAM  = 0.99f;
    const float CFAC = (float)(0.99 * 0.95);

    float g = 0.f;
    double s = 0.0, s2 = 0.0;
    for (int t = start - 1; t >= t0; --t) {
        float delta = reward[t] + GAM * g_v1[t] - g_v0[t];
        g = fmaf(CFAC, g, delta);
        if (t < t0 + C) {
            float adv = g - g_v0[t];
            g_adv[t] = adv;
            s  += (double)adv;
            s2 += (double)adv * (double)adv;
        }
    }

    __shared__ double sh[128][2];
    sh[threadIdx.x][0] = s;
    sh[threadIdx.x][1] = s2;
    __syncthreads();
    for (int off = 64; off > 0; off >>= 1) {
        if (threadIdx.x < off) {
            sh[threadIdx.x][0] += sh[threadIdx.x + off][0];
            sh[threadIdx.x][1] += sh[threadIdx.x + off][1];
        }
        __syncthreads();
    }
    if (threadIdx.x == 0) {
        g_part[blockIdx.x][0] = sh[0][0];
        g_part[blockIdx.x][1] = sh[0][1];
    }
}

__global__ void stats_kernel()
{
    if (threadIdx.x == 0) {
        double S = 0.0, S2 = 0.0;
        for (int i = 0; i < 8; i++) { S += g_part[i][0]; S2 += g_part[i][1]; }
        double mean = S / (double)TT;
        double var  = (S2 - S * S / (double)TT) / (double)(TT - 1);
        double sd   = sqrt(var);
        g_mean  = (float)mean;
        g_isd   = (float)(1.0 / (sd + 1e-7));
        g_closs = S2;
    }
}

// ---------------- fused actor: h=tanh(X@W1+b1); mu=h@Wmu+bmu; lv=h@Wlv+blv; PPO terms ----------------
__global__ __launch_bounds__(256) void actor_kernel(
    const float* __restrict__ X,
    const float* __restrict__ W1,  const float* __restrict__ b1,
    const float* __restrict__ Wmu, const float* __restrict__ bmu,
    const float* __restrict__ Wlv, const float* __restrict__ blv,
    const float* __restrict__ action, const float* __restrict__ beta_lp)
{
    __shared__ float As[16][68];
    __shared__ float Bs[16][256];
    __shared__ float b1s[256];
    __shared__ float wmus[256 * 8];
    __shared__ float wlvs[256 * 8];
    __shared__ float bmus[8], blvs[8];
    __shared__ float wred[8];

    const int tid = threadIdx.x;
    const int tx  = tid & 31;
    const int ty  = tid >> 5;
    const int t0  = blockIdx.x * 64;

    b1s[tid] = b1[tid];
    #pragma unroll
    for (int q = 0; q < 8; q++) {
        wmus[tid + q * 256] = Wmu[tid + q * 256];
        wlvs[tid + q * 256] = Wlv[tid + q * 256];
    }
    if (tid < 8) { bmus[tid] = bmu[tid]; blvs[tid] = blv[tid]; }

    const float mean = g_mean;
    const float isd  = g_isd;

    float acc[8][8];
    #pragma unroll
    for (int r = 0; r < 8; r++)
        #pragma unroll
        for (int c = 0; c < 8; c++) acc[r][c] = 0.f;

    for (int k0 = 0; k0 < DD; k0 += 16) {
        {
            int i = tid >> 2, jq = tid & 3;
            float4 v = *reinterpret_cast<const float4*>(&X[(size_t)(t0 + i) * DD + k0 + jq * 4]);
            As[jq * 4 + 0][i] = v.x;
            As[jq * 4 + 1][i] = v.y;
            As[jq * 4 + 2][i] = v.z;
            As[jq * 4 + 3][i] = v.w;
        }
        #pragma unroll
        for (int q = 0; q < 4; q++) {
            int idx = tid + q * 256;
            int j = idx >> 6, c4 = idx & 63;
            float4 v = *reinterpret_cast<const float4*>(&W1[(size_t)(k0 + j) * HH + c4 * 4]);
            *reinterpret_cast<float4*>(&Bs[j][c4 * 4]) = v;
        }
        __syncthreads();
        #pragma unroll
        for (int k = 0; k < 16; k++) {
            float a[8], b[8];
            #pragma unroll
            for (int r = 0; r < 8; r++) a[r] = As[k][ty * 8 + r];
            #pragma unroll
            for (int c = 0; c < 8; c++) b[c] = Bs[k][tx * 8 + c];
            #pragma unroll
            for (int r = 0; r < 8; r++)
                #pragma unroll
                for (int c = 0; c < 8; c++) acc[r][c] = fmaf(a[r], b[c], acc[r][c]);
        }
        __syncthreads();
    }

    // tanh in place (bias add first)
    #pragma unroll
    for (int r = 0; r < 8; r++)
        #pragma unroll
        for (int c = 0; c < 8; c++)
            acc[r][c] = fast_tanh(acc[r][c] + b1s[tx * 8 + c]);

    const float HLOG2PI = 0.9189385332046727f;  // 0.5*log(2*pi)
    float wsum = 0.f;

    #pragma unroll
    for (int r = 0; r < 8; r++) {
        float pm[8], pl[8];
        #pragma unroll
        for (int a = 0; a < 8; a++) {
            float m = 0.f, l = 0.f;
            #pragma unroll
            for (int jj = 0; jj < 8; jj++) {
                int j = tx * 8 + jj;
                m = fmaf(acc[r][jj], wmus[j * 8 + a], m);
                l = fmaf(acc[r][jj], wlvs[j * 8 + a], l);
            }
            pm[a] = m; pl[a] = l;
        }
        #pragma unroll
        for (int a = 0; a < 8; a++) {
            #pragma unroll
            for (int off = 16; off > 0; off >>= 1) {
                pm[a] += __shfl_xor_sync(0xffffffffu, pm[a], off);
                pl[a] += __shfl_xor_sync(0xffffffffu, pl[a], off);
            }
        }
        if (tx == 0) {
            const int t = t0 + ty * 8 + r;
            float lpsum = 0.f;
            #pragma unroll
            for (int a = 0; a < 8; a++) {
                float mu = pm[a] + bmus[a];
                float lv = pl[a] + blvs[a];
                float d  = action[(size_t)t * AA + a] - mu;
                float lp = -0.5f * d * d * expf(-lv) - 0.5f * lv - HLOG2PI;
                lpsum += lp - beta_lp[(size_t)t * AA + a];
            }
            float ratio = expf(lpsum);
            float ahat  = (g_adv[t] - mean) * isd;
            float rc    = fminf(fmaxf(ratio, 0.8f), 1.2f);
            wsum += fminf(ratio * ahat, rc * ahat);
        }
    }
    if (tx == 0) wred[ty] = wsum;
    __syncthreads();
    if (tid == 0) {
        float bsum = 0.f;
        #pragma unroll
        for (int w = 0; w < 8; w++) bsum += wred[w];
        g_apart[blockIdx.x] = bsum;
    }
}

// ---------------- final reduce: out = critic_loss - sum(min terms) ----------------
__global__ void final_kernel(float* __restrict__ out)
{
    __shared__ double sh[256];
    double s = 0.0;
    for (int i = threadIdx.x; i < 4096; i += 256) s += (double)g_apart[i];
    sh[threadIdx.x] = s;
    __syncthreads();
    for (int off = 128; off > 0; off >>= 1) {
        if (threadIdx.x < off) sh[threadIdx.x] += sh[threadIdx.x + off];
        __syncthreads();
    }
    if (threadIdx.x == 0) out[0] = (float)(g_closs - sh[0]);
}

// ---------------- launch ----------------
extern "C" void kernel_launch(void* const* d_in, const int* in_sizes, int n_in,
                              void* d_out, int out_size)
{
    const float* state      = (const float*)d_in[0];
    const float* next_state = (const float*)d_in[1];
    const float* action     = (const float*)d_in[2];
    const float* beta_lp    = (const float*)d_in[3];
    const float* reward     = (const float*)d_in[4];
    const float* W1         = (const float*)d_in[5];
    const float* b1         = (const float*)d_in[6];
    const float* Wmu        = (const float*)d_in[7];
    const float* bmu        = (const float*)d_in[8];
    const float* Wlv        = (const float*)d_in[9];
    const float* blv        = (const float*)d_in[10];
    const float* Wc1        = (const float*)d_in[11];
    const float* bc1        = (const float*)d_in[12];
    const float* Wc2        = (const float*)d_in[13];
    const float* bc2        = (const float*)d_in[14];
    float* out = (float*)d_out;

    critic_kernel<<<TT / 64, 256>>>(state,      Wc1, bc1, Wc2, bc2, 0);
    critic_kernel<<<TT / 64, 256>>>(next_state, Wc1, bc1, Wc2, bc2, 1);
    scan_kernel<<<8, 128>>>(reward);
    stats_kernel<<<1, 32>>>();
    actor_kernel<<<TT / 64, 256>>>(state, W1, b1, Wmu, bmu, Wlv, blv, action, beta_lp);
    final_kernel<<<1, 256>>>(out);
}

// round 3
// speedup vs baseline: 3.5219x; 3.5219x over previous
#include <cuda_runtime.h>
#include <math.h>

#define TT 262144
#define DD 128
#define HH 256
#define AA 8
#define NBLK (TT / 128)   // 2048 blocks of 128 rows

// ---------------- scratch (device globals; no allocation allowed) ----------------
__device__ float  g_v0[TT];
__device__ float  g_v1[TT];
__device__ float  g_adv[TT];
__device__ double g_part[8][2];
__device__ float  g_mean, g_isd;
__device__ double g_closs;
__device__ float  g_apart[NBLK];

__device__ __forceinline__ float fast_tanh(float x) {
    float y;
    asm("tanh.approx.f32 %0, %1;" : "=f"(y) : "f"(x));
    return y;
}
__device__ __forceinline__ unsigned int to_tf32(float f) {
    unsigned int u;
    asm("cvt.rna.tf32.f32 %0, %1;" : "=r"(u) : "f"(f));
    return u;
}

#define MMA_TF32(d, a, b) \
    asm volatile("mma.sync.aligned.m16n8k8.row.col.f32.tf32.tf32.f32 " \
                 "{%0,%1,%2,%3}, {%4,%5,%6,%7}, {%8,%9}, {%0,%1,%2,%3};" \
                 : "+f"((d)[0]), "+f"((d)[1]), "+f"((d)[2]), "+f"((d)[3]) \
                 : "r"((a)[0]), "r"((a)[1]), "r"((a)[2]), "r"((a)[3]), \
                   "r"((b)[0]), "r"((b)[1]))

// smem geometry (tf32 words)
#define LDA 132              // A: 128 x 132
#define LDB 260              // B: 128 x 260
#define A_WORDS (128 * LDA)  // 16896 words = 67584 B
#define B_OFF   A_WORDS
#define B_WORDS (128 * LDB)  // 33280 words = 133120 B
#define W2_OFF  (A_WORDS + B_WORDS)  // 50176 words = 200704 B
#define LDW 24               // Wcat: 256 x 24
#define LDH 260              // H: 128 x 260 (reuses A/B space)

#define CRITIC_DSM (W2_OFF * 4)                 // 200704
#define ACTOR_DSM  ((W2_OFF + 256 * LDW) * 4)   // 225280

// load X(128xDD) and W(DDxHH) tiles into smem as tf32
__device__ __forceinline__ void load_tiles(
    unsigned int* As, unsigned int* Bs,
    const float* __restrict__ Xblk, const float* __restrict__ W, int tid)
{
    #pragma unroll
    for (int i = tid; i < 128 * 32; i += 256) {          // A: 4096 float4
        int r = i >> 5, c4 = i & 31;
        float4 v = *reinterpret_cast<const float4*>(&Xblk[(size_t)r * DD + c4 * 4]);
        uint4 u = make_uint4(to_tf32(v.x), to_tf32(v.y), to_tf32(v.z), to_tf32(v.w));
        *reinterpret_cast<uint4*>(&As[r * LDA + c4 * 4]) = u;
    }
    #pragma unroll
    for (int i = tid; i < 128 * 64; i += 256) {          // B: 8192 float4
        int r = i >> 6, c4 = i & 63;
        float4 v = *reinterpret_cast<const float4*>(&W[(size_t)r * HH + c4 * 4]);
        uint4 u = make_uint4(to_tf32(v.x), to_tf32(v.y), to_tf32(v.z), to_tf32(v.w));
        *reinterpret_cast<uint4*>(&Bs[r * LDB + c4 * 4]) = u;
    }
}

// main 128x256x128 tf32 mma: C[4][8][4] accumulators
__device__ __forceinline__ void mma_main(
    float C[4][8][4], const unsigned int* As, const unsigned int* Bs,
    int wm, int wn, int qr, int qc)
{
    #pragma unroll 4
    for (int kk = 0; kk < 16; kk++) {
        unsigned int a[4][4];
        #pragma unroll
        for (int mt = 0; mt < 4; mt++) {
            const unsigned int* ap = As + (wm * 64 + mt * 16 + qr) * LDA + kk * 8 + qc;
            a[mt][0] = ap[0];
            a[mt][1] = ap[8 * LDA];
            a[mt][2] = ap[4];
            a[mt][3] = ap[8 * LDA + 4];
        }
        unsigned int b[8][2];
        #pragma unroll
        for (int nt = 0; nt < 8; nt++) {
            const unsigned int* bp = Bs + (kk * 8 + qc) * LDB + wn * 64 + nt * 8 + qr;
            b[nt][0] = bp[0];
            b[nt][1] = bp[4 * LDB];
        }
        #pragma unroll
        for (int mt = 0; mt < 4; mt++)
            #pragma unroll
            for (int nt = 0; nt < 8; nt++)
                MMA_TF32(C[mt][nt], a[mt], b[nt]);
    }
}

// ---------------- critic: value[t] = tanh(X@Wc1+bc1)@Wc2 + bc2 ----------------
__global__ __launch_bounds__(256, 1) void critic_kernel(
    const float* __restrict__ state, const float* __restrict__ next_state,
    const float* __restrict__ Wc1, const float* __restrict__ bc1,
    const float* __restrict__ Wc2, const float* __restrict__ bc2)
{
    extern __shared__ unsigned int dsm[];
    unsigned int* As = dsm;
    unsigned int* Bs = dsm + B_OFF;
    __shared__ float b1s[256], w2s[256];
    __shared__ float red[128][5];

    const int tid = threadIdx.x;
    const int lane = tid & 31, warp = tid >> 5;
    const int wm = warp >> 2, wn = warp & 3;
    const int qr = lane >> 2, qc = lane & 3;
    const int t0 = blockIdx.x * 128;
    const float* X = blockIdx.y ? next_state : state;
    float* out = blockIdx.y ? g_v1 : g_v0;

    b1s[tid] = bc1[tid];
    w2s[tid] = Wc2[tid];
    load_tiles(As, Bs, X + (size_t)t0 * DD, Wc1, tid);
    __syncthreads();

    float C[4][8][4];
    #pragma unroll
    for (int mt = 0; mt < 4; mt++)
        #pragma unroll
        for (int nt = 0; nt < 8; nt++)
            #pragma unroll
            for (int q = 0; q < 4; q++) C[mt][nt][q] = 0.f;

    mma_main(C, As, Bs, wm, wn, qr, qc);

    // epilogue: per-row sum of tanh(c + b1) * w2 over this warp's 64 cols
    #pragma unroll
    for (int mt = 0; mt < 4; mt++) {
        float plo = 0.f, phi = 0.f;
        #pragma unroll
        for (int nt = 0; nt < 8; nt++) {
            int c0 = wn * 64 + nt * 8 + 2 * qc;
            plo = fmaf(fast_tanh(C[mt][nt][0] + b1s[c0]),     w2s[c0],     plo);
            plo = fmaf(fast_tanh(C[mt][nt][1] + b1s[c0 + 1]), w2s[c0 + 1], plo);
            phi = fmaf(fast_tanh(C[mt][nt][2] + b1s[c0]),     w2s[c0],     phi);
            phi = fmaf(fast_tanh(C[mt][nt][3] + b1s[c0 + 1]), w2s[c0 + 1], phi);
        }
        plo += __shfl_xor_sync(0xffffffffu, plo, 1);
        plo += __shfl_xor_sync(0xffffffffu, plo, 2);
        phi += __shfl_xor_sync(0xffffffffu, phi, 1);
        phi += __shfl_xor_sync(0xffffffffu, phi, 2);
        if (qc == 0) {
            red[wm * 64 + mt * 16 + qr][wn]     = plo;
            red[wm * 64 + mt * 16 + qr + 8][wn] = phi;
        }
    }
    __syncthreads();
    if (tid < 128)
        out[t0 + tid] = red[tid][0] + red[tid][1] + red[tid][2] + red[tid][3] + bc2[0];
}

// ---------------- GAE scan + advantage + partial stats ----------------
__global__ void scan_kernel(const float* __restrict__ reward)
{
    const int C = 256, W = 1024;
    const int chunk = blockIdx.x * blockDim.x + threadIdx.x;   // 1024 chunks
    const int t0 = chunk * C;
    const int start = min(TT, t0 + C + W);
    const float GAM  = 0.99f;
    const float CFAC = (float)(0.99 * 0.95);

    float g = 0.f;
    double s = 0.0, s2 = 0.0;
    for (int t = start - 1; t >= t0; --t) {
        float delta = reward[t] + GAM * g_v1[t] - g_v0[t];
        g = fmaf(CFAC, g, delta);
        if (t < t0 + C) {
            float adv = g - g_v0[t];
            g_adv[t] = adv;
            s  += (double)adv;
            s2 += (double)adv * (double)adv;
        }
    }

    __shared__ double sh[128][2];
    sh[threadIdx.x][0] = s;
    sh[threadIdx.x][1] = s2;
    __syncthreads();
    for (int off = 64; off > 0; off >>= 1) {
        if (threadIdx.x < off) {
            sh[threadIdx.x][0] += sh[threadIdx.x + off][0];
            sh[threadIdx.x][1] += sh[threadIdx.x + off][1];
        }
        __syncthreads();
    }
    if (threadIdx.x == 0) {
        g_part[blockIdx.x][0] = sh[0][0];
        g_part[blockIdx.x][1] = sh[0][1];
    }
}

__global__ void stats_kernel()
{
    if (threadIdx.x == 0) {
        double S = 0.0, S2 = 0.0;
        for (int i = 0; i < 8; i++) { S += g_part[i][0]; S2 += g_part[i][1]; }
        double mean = S / (double)TT;
        double var  = (S2 - S * S / (double)TT) / (double)(TT - 1);
        double sd   = sqrt(var);
        g_mean  = (float)mean;
        g_isd   = (float)(1.0 / (sd + 1e-7));
        g_closs = S2;
    }
}

// ---------------- actor: fused two-layer MLP + PPO loss terms ----------------
__global__ __launch_bounds__(256, 1) void actor_kernel(
    const float* __restrict__ X,
    const float* __restrict__ W1,  const float* __restrict__ b1,
    const float* __restrict__ Wmu, const float* __restrict__ bmu,
    const float* __restrict__ Wlv, const float* __restrict__ blv,
    const float* __restrict__ action, const float* __restrict__ beta_lp)
{
    extern __shared__ unsigned int dsm[];
    unsigned int* As = dsm;
    unsigned int* Bs = dsm + B_OFF;
    unsigned int* Hs = dsm;                 // reuses A/B space after phase 1
    unsigned int* Ws2 = dsm + W2_OFF;       // 256 x 24
    __shared__ float b1s[256];
    __shared__ float bmus[8], blvs[8];
    __shared__ float wred[8];

    const int tid = threadIdx.x;
    const int lane = tid & 31, warp = tid >> 5;
    const int wm = warp >> 2, wn = warp & 3;
    const int qr = lane >> 2, qc = lane & 3;
    const int t0 = blockIdx.x * 128;

    b1s[tid] = b1[tid];
    if (tid < 8) { bmus[tid] = bmu[tid]; blvs[tid] = blv[tid]; }
    // Wcat = [Wmu | Wlv] as tf32, 256 x 16 padded to 24
    for (int i = tid; i < 2048; i += 256) {
        int k = i >> 3, a = i & 7;
        Ws2[k * LDW + a]     = to_tf32(Wmu[i]);
        Ws2[k * LDW + 8 + a] = to_tf32(Wlv[i]);
    }
    load_tiles(As, Bs, X + (size_t)t0 * DD, W1, tid);
    __syncthreads();

    float C[4][8][4];
    #pragma unroll
    for (int mt = 0; mt < 4; mt++)
        #pragma unroll
        for (int nt = 0; nt < 8; nt++)
            #pragma unroll
            for (int q = 0; q < 4; q++) C[mt][nt][q] = 0.f;

    mma_main(C, As, Bs, wm, wn, qr, qc);

    __syncthreads();   // everyone done reading As/Bs before overwriting with H

    // h = tanh(acc + b1) -> smem (tf32)
    #pragma unroll
    for (int mt = 0; mt < 4; mt++) {
        int r0 = wm * 64 + mt * 16 + qr;
        #pragma unroll
        for (int nt = 0; nt < 8; nt++) {
            int c0 = wn * 64 + nt * 8 + 2 * qc;
            uint2 lo = make_uint2(to_tf32(fast_tanh(C[mt][nt][0] + b1s[c0])),
                                  to_tf32(fast_tanh(C[mt][nt][1] + b1s[c0 + 1])));
            uint2 hi = make_uint2(to_tf32(fast_tanh(C[mt][nt][2] + b1s[c0])),
                                  to_tf32(fast_tanh(C[mt][nt][3] + b1s[c0 + 1])));
            *reinterpret_cast<uint2*>(&Hs[r0 * LDH + c0])       = lo;
            *reinterpret_cast<uint2*>(&Hs[(r0 + 8) * LDH + c0]) = hi;
        }
    }
    __syncthreads();

    // phase 2: P = h @ Wcat  (m16 per warp, n16, k=256)
    float P[2][4];
    #pragma unroll
    for (int nt = 0; nt < 2; nt++)
        #pragma unroll
        for (int q = 0; q < 4; q++) P[nt][q] = 0.f;

    #pragma unroll 4
    for (int kk = 0; kk < 32; kk++) {
        unsigned int a[4];
        const unsigned int* ap = Hs + (warp * 16 + qr) * LDH + kk * 8 + qc;
        a[0] = ap[0];
        a[1] = ap[8 * LDH];
        a[2] = ap[4];
        a[3] = ap[8 * LDH + 4];
        unsigned int b0[2], b1f[2];
        const unsigned int* bp = Ws2 + (kk * 8 + qc) * LDW + qr;
        b0[0]  = bp[0];
        b0[1]  = bp[4 * LDW];
        b1f[0] = bp[8];
        b1f[1] = bp[4 * LDW + 8];
        MMA_TF32(P[0], a, b0);
        MMA_TF32(P[1], a, b1f);
    }

    // PPO epilogue
    const float HLOG2PI = 0.9189385332046727f;
    const float mean = g_mean;
    const float isd  = g_isd;
    const int r0 = t0 + warp * 16 + qr;
    const int r1 = r0 + 8;
    const int a0 = 2 * qc;

    float2 act0 = *reinterpret_cast<const float2*>(&action[(size_t)r0 * AA + a0]);
    float2 bet0 = *reinterpret_cast<const float2*>(&beta_lp[(size_t)r0 * AA + a0]);
    float2 act1 = *reinterpret_cast<const float2*>(&action[(size_t)r1 * AA + a0]);
    float2 bet1 = *reinterpret_cast<const float2*>(&beta_lp[(size_t)r1 * AA + a0]);

    float mu00 = P[0][0] + bmus[a0], mu01 = P[0][1] + bmus[a0 + 1];
    float lv00 = P[1][0] + blvs[a0], lv01 = P[1][1] + blvs[a0 + 1];
    float mu10 = P[0][2] + bmus[a0], mu11 = P[0][3] + bmus[a0 + 1];
    float lv10 = P[1][2] + blvs[a0], lv11 = P[1][3] + blvs[a0 + 1];

    float d;
    float s_lo, s_hi;
    d = act0.x - mu00; s_lo  = -0.5f * d * d * __expf(-lv00) - 0.5f * lv00 - HLOG2PI - bet0.x;
    d = act0.y - mu01; s_lo += -0.5f * d * d * __expf(-lv01) - 0.5f * lv01 - HLOG2PI - bet0.y;
    d = act1.x - mu10; s_hi  = -0.5f * d * d * __expf(-lv10) - 0.5f * lv10 - HLOG2PI - bet1.x;
    d = act1.y - mu11; s_hi += -0.5f * d * d * __expf(-lv11) - 0.5f * lv11 - HLOG2PI - bet1.y;

    s_lo += __shfl_xor_sync(0xffffffffu, s_lo, 1);
    s_lo += __shfl_xor_sync(0xffffffffu, s_lo, 2);
    s_hi += __shfl_xor_sync(0xffffffffu, s_hi, 1);
    s_hi += __shfl_xor_sync(0xffffffffu, s_hi, 2);

    float term = 0.f;
    if (qc == 0) {
        float ratio = __expf(s_lo);
        float ahat  = (g_adv[r0] - mean) * isd;
        float rc    = fminf(fmaxf(ratio, 0.8f), 1.2f);
        term += fminf(ratio * ahat, rc * ahat);
        ratio = __expf(s_hi);
        ahat  = (g_adv[r1] - mean) * isd;
        rc    = fminf(fmaxf(ratio, 0.8f), 1.2f);
        term += fminf(ratio * ahat, rc * ahat);
    }
    #pragma unroll
    for (int off = 16; off > 0; off >>= 1)
        term += __shfl_xor_sync(0xffffffffu, term, off);
    if (lane == 0) wred[warp] = term;
    __syncthreads();
    if (tid == 0) {
        float bsum = 0.f;
        #pragma unroll
        for (int w = 0; w < 8; w++) bsum += wred[w];
        g_apart[blockIdx.x] = bsum;
    }
}

// ---------------- final reduce ----------------
__global__ void final_kernel(float* __restrict__ out)
{
    __shared__ double sh[256];
    double s = 0.0;
    for (int i = threadIdx.x; i < NBLK; i += 256) s += (double)g_apart[i];
    sh[threadIdx.x] = s;
    __syncthreads();
    for (int off = 128; off > 0; off >>= 1) {
        if (threadIdx.x < off) sh[threadIdx.x] += sh[threadIdx.x + off];
        __syncthreads();
    }
    if (threadIdx.x == 0) out[0] = (float)(g_closs - sh[0]);
}

// ---------------- launch ----------------
extern "C" void kernel_launch(void* const* d_in, const int* in_sizes, int n_in,
                              void* d_out, int out_size)
{
    const float* state      = (const float*)d_in[0];
    const float* next_state = (const float*)d_in[1];
    const float* action     = (const float*)d_in[2];
    const float* beta_lp    = (const float*)d_in[3];
    const float* reward     = (const float*)d_in[4];
    const float* W1         = (const float*)d_in[5];
    const float* b1         = (const float*)d_in[6];
    const float* Wmu        = (const float*)d_in[7];
    const float* bmu        = (const float*)d_in[8];
    const float* Wlv        = (const float*)d_in[9];
    const float* blv        = (const float*)d_in[10];
    const float* Wc1        = (const float*)d_in[11];
    const float* bc1        = (const float*)d_in[12];
    const float* Wc2        = (const float*)d_in[13];
    const float* bc2        = (const float*)d_in[14];
    float* out = (float*)d_out;

    cudaFuncSetAttribute(critic_kernel, cudaFuncAttributeMaxDynamicSharedMemorySize, CRITIC_DSM);
    cudaFuncSetAttribute(actor_kernel,  cudaFuncAttributeMaxDynamicSharedMemorySize, ACTOR_DSM);

    critic_kernel<<<dim3(NBLK, 2), 256, CRITIC_DSM>>>(state, next_state, Wc1, bc1, Wc2, bc2);
    scan_kernel<<<8, 128>>>(reward);
    stats_kernel<<<1, 32>>>();
    actor_kernel<<<NBLK, 256, ACTOR_DSM>>>(state, W1, b1, Wmu, bmu, Wlv, blv, action, beta_lp);
    final_kernel<<<1, 256>>>(out);
}

// round 4
// speedup vs baseline: 4.3345x; 1.2308x over previous
#include <cuda_runtime.h>
#include <cuda_fp16.h>
#include <math.h>

#define TT 262144
#define DD 128
#define HH 256
#define AA 8
#define NBLK (TT / 128)   // 2048 blocks of 128 rows

// ---------------- scratch (device globals; no allocation allowed) ----------------
__device__ float  g_v0[TT];
__device__ float  g_v1[TT];
__device__ float  g_adv[TT];
__device__ double g_part[32][2];
__device__ float  g_mean, g_isd;
__device__ double g_closs;
__device__ float  g_apart[NBLK];

__device__ __forceinline__ float fast_tanh(float x) {
    float y;
    asm("tanh.approx.f32 %0, %1;" : "=f"(y) : "f"(x));
    return y;
}

#define MMA_TF32(d, a, b) \
    asm volatile("mma.sync.aligned.m16n8k8.row.col.f32.tf32.tf32.f32 " \
                 "{%0,%1,%2,%3}, {%4,%5,%6,%7}, {%8,%9}, {%0,%1,%2,%3};" \
                 : "+f"((d)[0]), "+f"((d)[1]), "+f"((d)[2]), "+f"((d)[3]) \
                 : "r"((a)[0]), "r"((a)[1]), "r"((a)[2]), "r"((a)[3]), \
                   "r"((b)[0]), "r"((b)[1]))

#define MMA_F16(d, a0, a1, a2, a3, b0, b1) \
    asm volatile("mma.sync.aligned.m16n8k16.row.col.f32.f16.f16.f32 " \
                 "{%0,%1,%2,%3}, {%4,%5,%6,%7}, {%8,%9}, {%0,%1,%2,%3};" \
                 : "+f"((d)[0]), "+f"((d)[1]), "+f"((d)[2]), "+f"((d)[3]) \
                 : "r"(a0), "r"(a1), "r"(a2), "r"(a3), "r"(b0), "r"(b1))

__device__ __forceinline__ void cp_async16(void* dst, const void* src) {
    unsigned int s = (unsigned int)__cvta_generic_to_shared(dst);
    asm volatile("cp.async.cg.shared.global [%0], [%1], 16;\n" :: "r"(s), "l"(src));
}
#define CP_COMMIT() asm volatile("cp.async.commit_group;\n" ::: "memory")
#define CP_WAIT(n)  asm volatile("cp.async.wait_group %0;\n" :: "n"(n) : "memory")

// ---------------- smem geometry (32-bit words) ----------------
// K-chunked: A chunk 128x32 (pad 36), B chunk 32x256 (pad 264), double-buffered.
#define LDA 36
#define LDB 264
#define A_CH_WORDS (128 * LDA)          // 4608
#define B_CH_WORDS (32 * LDB)           // 8448
#define PERBUF (A_CH_WORDS + B_CH_WORDS)  // 13056
#define BUF_WORDS (2 * PERBUF)            // 26112 words = 104448 B

#define LDH2 264                          // H: 128 x 264 halves (reuses buffer region)
#define WT_OFF BUF_WORDS                  // WcatT: 16 x 264 halves after buffers

#define CRITIC_DSM (BUF_WORDS * 4)                     // 104448
#define ACTOR_DSM  (BUF_WORDS * 4 + 16 * LDH2 * 2)     // 104448 + 8448 = 112896

// async-load one K chunk (A: rows 128 x 32 floats, B: 32 x 256 floats)
__device__ __forceinline__ void load_chunk(
    unsigned int* buf, const float* __restrict__ Xblk, const float* __restrict__ W,
    int k0, int tid)
{
    unsigned int* As = buf;
    unsigned int* Bs = buf + A_CH_WORDS;
    #pragma unroll
    for (int q = 0; q < 2; q++) {
        int i = tid + q * 512;            // 1024 float4s
        int r = i >> 3, c4 = i & 7;
        cp_async16(&As[r * LDA + c4 * 4], &Xblk[(size_t)r * DD + k0 + c4 * 4]);
    }
    #pragma unroll
    for (int q = 0; q < 4; q++) {
        int i = tid + q * 512;            // 2048 float4s
        int r = i >> 6, c4 = i & 63;
        cp_async16(&Bs[r * LDB + c4 * 4], &W[(size_t)(k0 + r) * HH + c4 * 4]);
    }
}

// mma over one 32-wide K chunk; warp tile 32x64, C[2][8][4]
__device__ __forceinline__ void mma_chunk(
    float C[2][8][4], const unsigned int* buf, int wm, int wn, int qr, int qc)
{
    const unsigned int* As = buf;
    const unsigned int* Bs = buf + A_CH_WORDS;
    #pragma unroll
    for (int kk = 0; kk < 4; kk++) {
        unsigned int a[2][4];
        #pragma unroll
        for (int mt = 0; mt < 2; mt++) {
            const unsigned int* ap = As + (wm * 32 + mt * 16 + qr) * LDA + kk * 8 + qc;
            a[mt][0] = ap[0];
            a[mt][1] = ap[8 * LDA];
            a[mt][2] = ap[4];
            a[mt][3] = ap[8 * LDA + 4];
        }
        unsigned int b[8][2];
        #pragma unroll
        for (int nt = 0; nt < 8; nt++) {
            const unsigned int* bp = Bs + (kk * 8 + qc) * LDB + wn * 64 + nt * 8 + qr;
            b[nt][0] = bp[0];
            b[nt][1] = bp[4 * LDB];
        }
        #pragma unroll
        for (int mt = 0; mt < 2; mt++)
            #pragma unroll
            for (int nt = 0; nt < 8; nt++)
                MMA_TF32(C[mt][nt], a[mt], b[nt]);
    }
}

// full pipelined 128x256x128 GEMM into C
__device__ __forceinline__ void gemm_pipelined(
    float C[2][8][4], unsigned int* dsm,
    const float* __restrict__ Xblk, const float* __restrict__ W,
    int tid, int wm, int wn, int qr, int qc)
{
    load_chunk(dsm,          Xblk, W, 0,  tid); CP_COMMIT();
    load_chunk(dsm + PERBUF, Xblk, W, 32, tid); CP_COMMIT();

    #pragma unroll
    for (int mt = 0; mt < 2; mt++)
        #pragma unroll
        for (int nt = 0; nt < 8; nt++)
            #pragma unroll
            for (int q = 0; q < 4; q++) C[mt][nt][q] = 0.f;

    #pragma unroll
    for (int c = 0; c < 4; c++) {
        if (c < 3) { CP_WAIT(1); } else { CP_WAIT(0); }
        __syncthreads();
        mma_chunk(C, dsm + (c & 1) * PERBUF, wm, wn, qr, qc);
        __syncthreads();
        if (c + 2 < 4) {
            load_chunk(dsm + (c & 1) * PERBUF, Xblk, W, (c + 2) * 32, tid);
            CP_COMMIT();
        }
    }
}

// ---------------- critic: value[t] = tanh(X@Wc1+bc1)@Wc2 + bc2 ----------------
__global__ __launch_bounds__(512, 1) void critic_kernel(
    const float* __restrict__ state, const float* __restrict__ next_state,
    const float* __restrict__ Wc1, const float* __restrict__ bc1,
    const float* __restrict__ Wc2, const float* __restrict__ bc2)
{
    extern __shared__ unsigned int dsm[];
    __shared__ float b1s[256], w2s[256];
    __shared__ float red[128][4];

    const int tid = threadIdx.x;
    const int lane = tid & 31, warp = tid >> 5;
    const int wm = warp >> 2, wn = warp & 3;
    const int qr = lane >> 2, qc = lane & 3;
    const int t0 = blockIdx.x * 128;
    const float* X = blockIdx.y ? next_state : state;
    float* out = blockIdx.y ? g_v1 : g_v0;

    if (tid < 256) { b1s[tid] = bc1[tid]; w2s[tid] = Wc2[tid]; }

    float C[2][8][4];
    gemm_pipelined(C, dsm, X + (size_t)t0 * DD, Wc1, tid, wm, wn, qr, qc);

    // epilogue: per-row sum of tanh(c + b1) * w2
    #pragma unroll
    for (int mt = 0; mt < 2; mt++) {
        float plo = 0.f, phi = 0.f;
        #pragma unroll
        for (int nt = 0; nt < 8; nt++) {
            int c0 = wn * 64 + nt * 8 + 2 * qc;
            plo = fmaf(fast_tanh(C[mt][nt][0] + b1s[c0]),     w2s[c0],     plo);
            plo = fmaf(fast_tanh(C[mt][nt][1] + b1s[c0 + 1]), w2s[c0 + 1], plo);
            phi = fmaf(fast_tanh(C[mt][nt][2] + b1s[c0]),     w2s[c0],     phi);
            phi = fmaf(fast_tanh(C[mt][nt][3] + b1s[c0 + 1]), w2s[c0 + 1], phi);
        }
        plo += __shfl_xor_sync(0xffffffffu, plo, 1);
        plo += __shfl_xor_sync(0xffffffffu, plo, 2);
        phi += __shfl_xor_sync(0xffffffffu, phi, 1);
        phi += __shfl_xor_sync(0xffffffffu, phi, 2);
        if (qc == 0) {
            red[wm * 32 + mt * 16 + qr][wn]     = plo;
            red[wm * 32 + mt * 16 + qr + 8][wn] = phi;
        }
    }
    __syncthreads();
    if (tid < 128)
        out[t0 + tid] = red[tid][0] + red[tid][1] + red[tid][2] + red[tid][3] + bc2[0];
}

// ---------------- GAE scan + advantage + partial stats ----------------
__global__ void scan_kernel(const float* __restrict__ reward)
{
    const int C = 256, W = 1024;
    const int chunk = blockIdx.x * 32 + threadIdx.x;   // 32 blocks x 32 = 1024 chunks
    const int t0 = chunk * C;
    const int start = min(TT, t0 + C + W);
    const float GAM  = 0.99f;
    const float CFAC = (float)(0.99 * 0.95);

    float g = 0.f;
    double s = 0.0, s2 = 0.0;
    for (int t = start - 1; t >= t0; --t) {
        float delta = reward[t] + GAM * g_v1[t] - g_v0[t];
        g = fmaf(CFAC, g, delta);
        if (t < t0 + C) {
            float adv = g - g_v0[t];
            g_adv[t] = adv;
            s  += (double)adv;
            s2 += (double)adv * (double)adv;
        }
    }
    #pragma unroll
    for (int off = 16; off > 0; off >>= 1) {
        s  += __shfl_down_sync(0xffffffffu, s, off);
        s2 += __shfl_down_sync(0xffffffffu, s2, off);
    }
    if (threadIdx.x == 0) {
        g_part[blockIdx.x][0] = s;
        g_part[blockIdx.x][1] = s2;
    }
}

__global__ void stats_kernel()
{
    if (threadIdx.x == 0) {
        double S = 0.0, S2 = 0.0;
        for (int i = 0; i < 32; i++) { S += g_part[i][0]; S2 += g_part[i][1]; }
        double mean = S / (double)TT;
        double var  = (S2 - S * S / (double)TT) / (double)(TT - 1);
        double sd   = sqrt(var);
        g_mean  = (float)mean;
        g_isd   = (float)(1.0 / (sd + 1e-7));
        g_closs = S2;
    }
}

// ---------------- actor: fused two-layer MLP + PPO loss terms ----------------
__global__ __launch_bounds__(512, 1) void actor_kernel(
    const float* __restrict__ X,
    const float* __restrict__ W1,  const float* __restrict__ b1,
    const float* __restrict__ Wmu, const float* __restrict__ bmu,
    const float* __restrict__ Wlv, const float* __restrict__ blv,
    const float* __restrict__ action, const float* __restrict__ beta_lp)
{
    extern __shared__ unsigned int dsm[];
    __half* Hh = reinterpret_cast<__half*>(dsm);            // 128 x 264 halves (reuses buffers)
    __half* WT = reinterpret_cast<__half*>(dsm + WT_OFF);   // 16 x 264 halves: [a][k]=Wmu, [8+a][k]=Wlv
    __shared__ float b1s[256];
    __shared__ float bmus[8], blvs[8];
    __shared__ float wred[8];

    const int tid = threadIdx.x;
    const int lane = tid & 31, warp = tid >> 5;
    const int wm = warp >> 2, wn = warp & 3;
    const int qr = lane >> 2, qc = lane & 3;
    const int t0 = blockIdx.x * 128;

    if (tid < 256) b1s[tid] = b1[tid];
    if (tid < 8) { bmus[tid] = bmu[tid]; blvs[tid] = blv[tid]; }
    for (int i = tid; i < 2048; i += 512) {           // transpose weights to [n][k] halves
        int a = i & 7, k = i >> 3;
        WT[a * LDH2 + k]       = __float2half(Wmu[k * AA + a]);
        WT[(8 + a) * LDH2 + k] = __float2half(Wlv[k * AA + a]);
    }

    float C[2][8][4];
    gemm_pipelined(C, dsm, X + (size_t)t0 * DD, W1, tid, wm, wn, qr, qc);

    __syncthreads();   // all mma reads of buffers done before H overwrites them

    // h = tanh(acc + b1) -> smem as half2
    #pragma unroll
    for (int mt = 0; mt < 2; mt++) {
        int r0 = wm * 32 + mt * 16 + qr;
        #pragma unroll
        for (int nt = 0; nt < 8; nt++) {
            int c0 = wn * 64 + nt * 8 + 2 * qc;
            __half2 lo = __floats2half2_rn(fast_tanh(C[mt][nt][0] + b1s[c0]),
                                           fast_tanh(C[mt][nt][1] + b1s[c0 + 1]));
            __half2 hi = __floats2half2_rn(fast_tanh(C[mt][nt][2] + b1s[c0]),
                                           fast_tanh(C[mt][nt][3] + b1s[c0 + 1]));
            *reinterpret_cast<__half2*>(&Hh[r0 * LDH2 + c0])       = lo;
            *reinterpret_cast<__half2*>(&Hh[(r0 + 8) * LDH2 + c0]) = hi;
        }
    }
    __syncthreads();

    // phase 2 (warps 0..7): P = h @ [Wmu | Wlv], fp16 mma m16n8k16, k=256
    if (warp < 8) {
        float P[2][4];
        #pragma unroll
        for (int g = 0; g < 2; g++)
            #pragma unroll
            for (int q = 0; q < 4; q++) P[g][q] = 0.f;

        #pragma unroll
        for (int ks = 0; ks < 16; ks++) {
            const __half* hp = Hh + (warp * 16 + qr) * LDH2 + ks * 16 + 2 * qc;
            unsigned int a0 = *reinterpret_cast<const unsigned int*>(hp);
            unsigned int a1 = *reinterpret_cast<const unsigned int*>(hp + 8 * LDH2);
            unsigned int a2 = *reinterpret_cast<const unsigned int*>(hp + 8);
            unsigned int a3 = *reinterpret_cast<const unsigned int*>(hp + 8 * LDH2 + 8);
            const __half* bp = WT + qr * LDH2 + ks * 16 + 2 * qc;
            unsigned int bm0 = *reinterpret_cast<const unsigned int*>(bp);
            unsigned int bm1 = *reinterpret_cast<const unsigned int*>(bp + 8);
            unsigned int bl0 = *reinterpret_cast<const unsigned int*>(bp + 8 * LDH2);
            unsigned int bl1 = *reinterpret_cast<const unsigned int*>(bp + 8 * LDH2 + 8);
            MMA_F16(P[0], a0, a1, a2, a3, bm0, bm1);
            MMA_F16(P[1], a0, a1, a2, a3, bl0, bl1);
        }

        // PPO epilogue
        const float HLOG2PI = 0.9189385332046727f;
        const float mean = g_mean;
        const float isd  = g_isd;
        const int r0 = t0 + warp * 16 + qr;
        const int r1 = r0 + 8;
        const int a0i = 2 * qc;

        float2 act0 = *reinterpret_cast<const float2*>(&action[(size_t)r0 * AA + a0i]);
        float2 bet0 = *reinterpret_cast<const float2*>(&beta_lp[(size_t)r0 * AA + a0i]);
        float2 act1 = *reinterpret_cast<const float2*>(&action[(size_t)r1 * AA + a0i]);
        float2 bet1 = *reinterpret_cast<const float2*>(&beta_lp[(size_t)r1 * AA + a0i]);

        float mu00 = P[0][0] + bmus[a0i], mu01 = P[0][1] + bmus[a0i + 1];
        float lv00 = P[1][0] + blvs[a0i], lv01 = P[1][1] + blvs[a0i + 1];
        float mu10 = P[0][2] + bmus[a0i], mu11 = P[0][3] + bmus[a0i + 1];
        float lv10 = P[1][2] + blvs[a0i], lv11 = P[1][3] + blvs[a0i + 1];

        float d, s_lo, s_hi;
        d = act0.x - mu00; s_lo  = -0.5f * d * d * __expf(-lv00) - 0.5f * lv00 - HLOG2PI - bet0.x;
        d = act0.y - mu01; s_lo += -0.5f * d * d * __expf(-lv01) - 0.5f * lv01 - HLOG2PI - bet0.y;
        d = act1.x - mu10; s_hi  = -0.5f * d * d * __expf(-lv10) - 0.5f * lv10 - HLOG2PI - bet1.x;
        d = act1.y - mu11; s_hi += -0.5f * d * d * __expf(-lv11) - 0.5f * lv11 - HLOG2PI - bet1.y;

        s_lo += __shfl_xor_sync(0xffffffffu, s_lo, 1);
        s_lo += __shfl_xor_sync(0xffffffffu, s_lo, 2);
        s_hi += __shfl_xor_sync(0xffffffffu, s_hi, 1);
        s_hi += __shfl_xor_sync(0xffffffffu, s_hi, 2);

        float term = 0.f;
        if (qc == 0) {
            float ratio = __expf(s_lo);
            float ahat  = (g_adv[r0] - mean) * isd;
            float rc    = fminf(fmaxf(ratio, 0.8f), 1.2f);
            term += fminf(ratio * ahat, rc * ahat);
            ratio = __expf(s_hi);
            ahat  = (g_adv[r1] - mean) * isd;
            rc    = fminf(fmaxf(ratio, 0.8f), 1.2f);
            term += fminf(ratio * ahat, rc * ahat);
        }
        #pragma unroll
        for (int off = 16; off > 0; off >>= 1)
            term += __shfl_xor_sync(0xffffffffu, term, off);
        if (lane == 0) wred[warp] = term;
    }
    __syncthreads();
    if (tid == 0) {
        float bsum = 0.f;
        #pragma unroll
        for (int w = 0; w < 8; w++) bsum += wred[w];
        g_apart[blockIdx.x] = bsum;
    }
}

// ---------------- final reduce ----------------
__global__ void final_kernel(float* __restrict__ out)
{
    __shared__ double sh[256];
    double s = 0.0;
    for (int i = threadIdx.x; i < NBLK; i += 256) s += (double)g_apart[i];
    sh[threadIdx.x] = s;
    __syncthreads();
    for (int off = 128; off > 0; off >>= 1) {
        if (threadIdx.x < off) sh[threadIdx.x] += sh[threadIdx.x + off];
        __syncthreads();
    }
    if (threadIdx.x == 0) out[0] = (float)(g_closs - sh[0]);
}

// ---------------- launch ----------------
extern "C" void kernel_launch(void* const* d_in, const int* in_sizes, int n_in,
                              void* d_out, int out_size)
{
    const float* state      = (const float*)d_in[0];
    const float* next_state = (const float*)d_in[1];
    const float* action     = (const float*)d_in[2];
    const float* beta_lp    = (const float*)d_in[3];
    const float* reward     = (const float*)d_in[4];
    const float* W1         = (const float*)d_in[5];
    const float* b1         = (const float*)d_in[6];
    const float* Wmu        = (const float*)d_in[7];
    const float* bmu        = (const float*)d_in[8];
    const float* Wlv        = (const float*)d_in[9];
    const float* blv        = (const float*)d_in[10];
    const float* Wc1        = (const float*)d_in[11];
    const float* bc1        = (const float*)d_in[12];
    const float* Wc2        = (const float*)d_in[13];
    const float* bc2        = (const float*)d_in[14];
    float* out = (float*)d_out;

    cudaFuncSetAttribute(critic_kernel, cudaFuncAttributeMaxDynamicSharedMemorySize, CRITIC_DSM);
    cudaFuncSetAttribute(actor_kernel,  cudaFuncAttributeMaxDynamicSharedMemorySize, ACTOR_DSM);

    critic_kernel<<<dim3(NBLK, 2), 512, CRITIC_DSM>>>(state, next_state, Wc1, bc1, Wc2, bc2);
    scan_kernel<<<32, 32>>>(reward);
    stats_kernel<<<1, 32>>>();
    actor_kernel<<<NBLK, 512, ACTOR_DSM>>>(state, W1, b1, Wmu, bmu, Wlv, blv, action, beta_lp);
    final_kernel<<<1, 256>>>(out);
}

// round 5
// speedup vs baseline: 4.6602x; 1.0751x over previous
#include <cuda_runtime.h>
#include <math.h>

#define TT 262144
#define DD 128
#define HH 256
#define AA 8
#define NBLK (TT / 128)   // 2048 blocks of 128 rows

// ---------------- scratch (device globals; no allocation allowed) ----------------
__device__ float  g_v0[TT];
__device__ float  g_delta[TT];
__device__ float  g_adv[TT];
__device__ float  g_ratio[TT];
__device__ double g_part[32][2];
__device__ float  g_mean, g_isd;
__device__ double g_closs;
__device__ double g_lpart[256];

__device__ __forceinline__ float fast_tanh(float x) {
    float y;
    asm("tanh.approx.f32 %0, %1;" : "=f"(y) : "f"(x));
    return y;
}
__device__ __forceinline__ unsigned int to_tf32(float f) {
    unsigned int u;
    asm("cvt.rna.tf32.f32 %0, %1;" : "=r"(u) : "f"(f));
    return u;
}

#define MMA_TF32(d, a, b) \
    asm volatile("mma.sync.aligned.m16n8k8.row.col.f32.tf32.tf32.f32 " \
                 "{%0,%1,%2,%3}, {%4,%5,%6,%7}, {%8,%9}, {%0,%1,%2,%3};" \
                 : "+f"((d)[0]), "+f"((d)[1]), "+f"((d)[2]), "+f"((d)[3]) \
                 : "r"((a)[0]), "r"((a)[1]), "r"((a)[2]), "r"((a)[3]), \
                   "r"((b)[0]), "r"((b)[1]))

__device__ __forceinline__ void cp_async16(void* dst, const void* src) {
    unsigned int s = (unsigned int)__cvta_generic_to_shared(dst);
    asm volatile("cp.async.cg.shared.global [%0], [%1], 16;\n" :: "r"(s), "l"(src));
}
#define CP_COMMIT() asm volatile("cp.async.commit_group;\n" ::: "memory")
#define CP_WAIT(n)  asm volatile("cp.async.wait_group %0;\n" :: "n"(n) : "memory")

// ---------------- smem geometry (32-bit words) ----------------
#define LDA 36
#define LDB 264
#define A_CH_WORDS (128 * LDA)             // 4608
#define B_CH_WORDS (32 * LDB)              // 8448
#define PERBUF (A_CH_WORDS + B_CH_WORDS)   // 13056
#define DSM_WORDS (4 * PERBUF)             // 52224 words = 208896 B
#define FWD_DSM (DSM_WORDS * 4)

// phase-2 overlay (inside buffer region, used after all GEMM chunks consumed)
#define LDH 260
#define H_WORDS (128 * LDH)                // 33280
#define LDW 24                             // Wcat: 256 x 24 (conflict-free)

// async-load one K chunk (A: 128 x 32 floats, B: 32 x 256 floats) — 512 threads
__device__ __forceinline__ void load_chunk(
    unsigned int* buf, const float* __restrict__ Xblk, const float* __restrict__ W,
    int k0, int tid)
{
    unsigned int* As = buf;
    unsigned int* Bs = buf + A_CH_WORDS;
    #pragma unroll
    for (int q = 0; q < 2; q++) {
        int i = tid + q * 512;             // 1024 float4s
        int r = i >> 3, c4 = i & 7;
        cp_async16(&As[r * LDA + c4 * 4], &Xblk[(size_t)r * DD + k0 + c4 * 4]);
    }
    #pragma unroll
    for (int q = 0; q < 4; q++) {
        int i = tid + q * 512;             // 2048 float4s
        int r = i >> 6, c4 = i & 63;
        cp_async16(&Bs[r * LDB + c4 * 4], &W[(size_t)(k0 + r) * HH + c4 * 4]);
    }
}

// mma over one 32-wide K chunk; warp tile 32x64, C[2][8][4]
__device__ __forceinline__ void mma_chunk(
    float C[2][8][4], const unsigned int* buf, int wm, int wn, int qr, int qc)
{
    const unsigned int* As = buf;
    const unsigned int* Bs = buf + A_CH_WORDS;
    #pragma unroll
    for (int kk = 0; kk < 4; kk++) {
        unsigned int a[2][4];
        #pragma unroll
        for (int mt = 0; mt < 2; mt++) {
            const unsigned int* ap = As + (wm * 32 + mt * 16 + qr) * LDA + kk * 8 + qc;
            a[mt][0] = ap[0];
            a[mt][1] = ap[8 * LDA];
            a[mt][2] = ap[4];
            a[mt][3] = ap[8 * LDA + 4];
        }
        unsigned int b[8][2];
        #pragma unroll
        for (int nt = 0; nt < 8; nt++) {
            const unsigned int* bp = Bs + (kk * 8 + qc) * LDB + wn * 64 + nt * 8 + qr;
            b[nt][0] = bp[0];
            b[nt][1] = bp[4 * LDB];
        }
        #pragma unroll
        for (int mt = 0; mt < 2; mt++)
            #pragma unroll
            for (int nt = 0; nt < 8; nt++)
                MMA_TF32(C[mt][nt], a[mt], b[nt]);
    }
}

// ---------------- fused forward: critic(state), critic(next), actor ----------------
__global__ __launch_bounds__(512, 1) void fwd_kernel(
    const float* __restrict__ state, const float* __restrict__ next_state,
    const float* __restrict__ reward,
    const float* __restrict__ Wc1, const float* __restrict__ bc1,
    const float* __restrict__ Wc2, const float* __restrict__ bc2,
    const float* __restrict__ W1,  const float* __restrict__ b1,
    const float* __restrict__ Wmu, const float* __restrict__ bmu,
    const float* __restrict__ Wlv, const float* __restrict__ blv,
    const float* __restrict__ action, const float* __restrict__ beta_lp)
{
    extern __shared__ unsigned int dsm[];
    __shared__ float cb1s[256], cw2s[256], ab1s[256];
    __shared__ float bmus[8], blvs[8];

    const int tid = threadIdx.x;
    const int lane = tid & 31, warp = tid >> 5;
    const int wm = warp >> 2, wn = warp & 3;
    const int qr = lane >> 2, qc = lane & 3;
    const int t0 = blockIdx.x * 128;
    const float* A0 = state + (size_t)t0 * DD;
    const float* A1 = next_state + (size_t)t0 * DD;

    if (tid < 256) { cb1s[tid] = bc1[tid]; cw2s[tid] = Wc2[tid]; ab1s[tid] = b1[tid]; }
    if (tid < 8) { bmus[tid] = bmu[tid]; blvs[tid] = blv[tid]; }

    // chunk schedule: c in 0..11; gemm g=c>>2; k0=(c&3)*32
    // g=0: state@Wc1   g=1: next@Wc1   g=2: state@W1
    auto issue = [&](int c) {
        int g = c >> 2, k0 = (c & 3) * 32;
        const float* Xb = (g == 1) ? A1 : A0;
        const float* Wb = (g == 2) ? W1 : Wc1;
        load_chunk(dsm + (c & 3) * PERBUF, Xb, Wb, k0, tid);
        CP_COMMIT();
    };

    issue(0); issue(1); issue(2);

    float* red = reinterpret_cast<float*>(dsm + 3 * PERBUF);   // [128][4] overlay in buf3
    float v0val = 0.f;
    float C[2][8][4];

    #pragma unroll 1
    for (int g = 0; g < 3; g++) {
        #pragma unroll
        for (int mt = 0; mt < 2; mt++)
            #pragma unroll
            for (int nt = 0; nt < 8; nt++)
                #pragma unroll
                for (int q = 0; q < 4; q++) C[mt][nt][q] = 0.f;

        #pragma unroll
        for (int cc = 0; cc < 4; cc++) {
            int c = g * 4 + cc;
            CP_WAIT(2);
            __syncthreads();
            mma_chunk(C, dsm + (c & 3) * PERBUF, wm, wn, qr, qc);
            if (c < 9) issue(c + 3);
            else       CP_COMMIT();     // empty group keeps wait-count uniform
        }

        if (g < 2) {
            // critic epilogue: v = sum_j tanh(C+b)*w2  (buf3 chunk consumed; red overlay safe)
            __syncthreads();
            #pragma unroll
            for (int mt = 0; mt < 2; mt++) {
                float plo = 0.f, phi = 0.f;
                #pragma unroll
                for (int nt = 0; nt < 8; nt++) {
                    int c0 = wn * 64 + nt * 8 + 2 * qc;
                    plo = fmaf(fast_tanh(C[mt][nt][0] + cb1s[c0]),     cw2s[c0],     plo);
                    plo = fmaf(fast_tanh(C[mt][nt][1] + cb1s[c0 + 1]), cw2s[c0 + 1], plo);
                    phi = fmaf(fast_tanh(C[mt][nt][2] + cb1s[c0]),     cw2s[c0],     phi);
                    phi = fmaf(fast_tanh(C[mt][nt][3] + cb1s[c0 + 1]), cw2s[c0 + 1], phi);
                }
                plo += __shfl_xor_sync(0xffffffffu, plo, 1);
                plo += __shfl_xor_sync(0xffffffffu, plo, 2);
                phi += __shfl_xor_sync(0xffffffffu, phi, 1);
                phi += __shfl_xor_sync(0xffffffffu, phi, 2);
                if (qc == 0) {
                    red[(wm * 32 + mt * 16 + qr) * 4 + wn]       = plo;
                    red[(wm * 32 + mt * 16 + qr + 8) * 4 + wn]   = phi;
                }
            }
            __syncthreads();
            if (tid < 128) {
                float v = red[tid * 4] + red[tid * 4 + 1] + red[tid * 4 + 2] + red[tid * 4 + 3] + bc2[0];
                if (g == 0) {
                    v0val = v;
                    g_v0[t0 + tid] = v;
                } else {
                    g_delta[t0 + tid] = reward[t0 + tid] + 0.99f * v - v0val;
                }
            }
        }
    }

    // ---------------- actor epilogue ----------------
    __syncthreads();                        // all GEMM reads of buffers done
    unsigned int* Hs  = dsm;                // 128 x 260 tf32 overlay
    unsigned int* Ws2 = dsm + H_WORDS;      // 256 x 24 tf32 overlay

    // h = tanh(acc + b1) -> smem tf32
    #pragma unroll
    for (int mt = 0; mt < 2; mt++) {
        int r0 = wm * 32 + mt * 16 + qr;
        #pragma unroll
        for (int nt = 0; nt < 8; nt++) {
            int c0 = wn * 64 + nt * 8 + 2 * qc;
            uint2 lo = make_uint2(to_tf32(fast_tanh(C[mt][nt][0] + ab1s[c0])),
                                  to_tf32(fast_tanh(C[mt][nt][1] + ab1s[c0 + 1])));
            uint2 hi = make_uint2(to_tf32(fast_tanh(C[mt][nt][2] + ab1s[c0])),
                                  to_tf32(fast_tanh(C[mt][nt][3] + ab1s[c0 + 1])));
            *reinterpret_cast<uint2*>(&Hs[r0 * LDH + c0])       = lo;
            *reinterpret_cast<uint2*>(&Hs[(r0 + 8) * LDH + c0]) = hi;
        }
    }
    // Wcat = [Wmu | Wlv] tf32, 256 x 16 padded to 24
    for (int i = tid; i < 2048; i += 512) {
        int k = i >> 3, a = i & 7;
        Ws2[k * LDW + a]     = to_tf32(Wmu[i]);
        Ws2[k * LDW + 8 + a] = to_tf32(Wlv[i]);
    }
    __syncthreads();

    // phase 2 (warps 0..7): P = h @ Wcat, tf32 m16n8k8, k=256
    if (warp < 8) {
        float P[2][4];
        #pragma unroll
        for (int gg = 0; gg < 2; gg++)
            #pragma unroll
            for (int q = 0; q < 4; q++) P[gg][q] = 0.f;

        #pragma unroll 4
        for (int kk = 0; kk < 32; kk++) {
            unsigned int a[4];
            const unsigned int* ap = Hs + (warp * 16 + qr) * LDH + kk * 8 + qc;
            a[0] = ap[0];
            a[1] = ap[8 * LDH];
            a[2] = ap[4];
            a[3] = ap[8 * LDH + 4];
            unsigned int b0[2], b1f[2];
            const unsigned int* bp = Ws2 + (kk * 8 + qc) * LDW + qr;
            b0[0]  = bp[0];
            b0[1]  = bp[4 * LDW];
            b1f[0] = bp[8];
            b1f[1] = bp[4 * LDW + 8];
            MMA_TF32(P[0], a, b0);
            MMA_TF32(P[1], a, b1f);
        }

        const float HLOG2PI = 0.9189385332046727f;
        const int r0 = t0 + warp * 16 + qr;
        const int r1 = r0 + 8;
        const int a0i = 2 * qc;

        float2 act0 = *reinterpret_cast<const float2*>(&action[(size_t)r0 * AA + a0i]);
        float2 bet0 = *reinterpret_cast<const float2*>(&beta_lp[(size_t)r0 * AA + a0i]);
        float2 act1 = *reinterpret_cast<const float2*>(&action[(size_t)r1 * AA + a0i]);
        float2 bet1 = *reinterpret_cast<const float2*>(&beta_lp[(size_t)r1 * AA + a0i]);

        float mu00 = P[0][0] + bmus[a0i], mu01 = P[0][1] + bmus[a0i + 1];
        float lv00 = P[1][0] + blvs[a0i], lv01 = P[1][1] + blvs[a0i + 1];
        float mu10 = P[0][2] + bmus[a0i], mu11 = P[0][3] + bmus[a0i + 1];
        float lv10 = P[1][2] + blvs[a0i], lv11 = P[1][3] + blvs[a0i + 1];

        float d, s_lo, s_hi;
        d = act0.x - mu00; s_lo  = -0.5f * d * d * __expf(-lv00) - 0.5f * lv00 - HLOG2PI - bet0.x;
        d = act0.y - mu01; s_lo += -0.5f * d * d * __expf(-lv01) - 0.5f * lv01 - HLOG2PI - bet0.y;
        d = act1.x - mu10; s_hi  = -0.5f * d * d * __expf(-lv10) - 0.5f * lv10 - HLOG2PI - bet1.x;
        d = act1.y - mu11; s_hi += -0.5f * d * d * __expf(-lv11) - 0.5f * lv11 - HLOG2PI - bet1.y;

        s_lo += __shfl_xor_sync(0xffffffffu, s_lo, 1);
        s_lo += __shfl_xor_sync(0xffffffffu, s_lo, 2);
        s_hi += __shfl_xor_sync(0xffffffffu, s_hi, 1);
        s_hi += __shfl_xor_sync(0xffffffffu, s_hi, 2);

        if (qc == 0) {
            g_ratio[r0] = __expf(s_lo);
            g_ratio[r1] = __expf(s_hi);
        }
    }
}

// ---------------- GAE scan + advantage + partial stats ----------------
__global__ void scan_kernel()
{
    const int C = 256, W = 1024;
    const int chunk = blockIdx.x * 32 + threadIdx.x;   // 1024 chunks
    const int t0 = chunk * C;
    const int start = min(TT, t0 + C + W);
    const float CFAC = (float)(0.99 * 0.95);

    float g = 0.f;
    double s = 0.0, s2 = 0.0;
    for (int t = start - 1; t >= t0; --t) {
        g = fmaf(CFAC, g, g_delta[t]);
        if (t < t0 + C) {
            float adv = g - g_v0[t];
            g_adv[t] = adv;
            s  += (double)adv;
            s2 += (double)adv * (double)adv;
        }
    }
    #pragma unroll
    for (int off = 16; off > 0; off >>= 1) {
        s  += __shfl_down_sync(0xffffffffu, s, off);
        s2 += __shfl_down_sync(0xffffffffu, s2, off);
    }
    if (threadIdx.x == 0) {
        g_part[blockIdx.x][0] = s;
        g_part[blockIdx.x][1] = s2;
    }
}

__global__ void stats_kernel()
{
    if (threadIdx.x == 0) {
        double S = 0.0, S2 = 0.0;
        for (int i = 0; i < 32; i++) { S += g_part[i][0]; S2 += g_part[i][1]; }
        double mean = S / (double)TT;
        double var  = (S2 - S * S / (double)TT) / (double)(TT - 1);
        double sd   = sqrt(var);
        g_mean  = (float)mean;
        g_isd   = (float)(1.0 / (sd + 1e-7));
        g_closs = S2;
    }
}

// ---------------- actor loss pass: sum min(ratio*ahat, clip(ratio)*ahat) ----------------
__global__ void loss_kernel()
{
    const float mean = g_mean, isd = g_isd;
    double s = 0.0;
    for (int t = blockIdx.x * 256 + threadIdx.x; t < TT; t += 256 * 256) {
        float ratio = g_ratio[t];
        float ahat  = (g_adv[t] - mean) * isd;
        float rc    = fminf(fmaxf(ratio, 0.8f), 1.2f);
        s += (double)fminf(ratio * ahat, rc * ahat);
    }
    __shared__ double sh[256];
    sh[threadIdx.x] = s;
    __syncthreads();
    for (int off = 128; off > 0; off >>= 1) {
        if (threadIdx.x < off) sh[threadIdx.x] += sh[threadIdx.x + off];
        __syncthreads();
    }
    if (threadIdx.x == 0) g_lpart[blockIdx.x] = sh[0];
}

__global__ void final_kernel(float* __restrict__ out)
{
    __shared__ double sh[256];
    sh[threadIdx.x] = g_lpart[threadIdx.x];
    __syncthreads();
    for (int off = 128; off > 0; off >>= 1) {
        if (threadIdx.x < off) sh[threadIdx.x] += sh[threadIdx.x + off];
        __syncthreads();
    }
    if (threadIdx.x == 0) out[0] = (float)(g_closs - sh[0]);
}

// ---------------- launch ----------------
extern "C" void kernel_launch(void* const* d_in, const int* in_sizes, int n_in,
                              void* d_out, int out_size)
{
    const float* state      = (const float*)d_in[0];
    const float* next_state = (const float*)d_in[1];
    const float* action     = (const float*)d_in[2];
    const float* beta_lp    = (const float*)d_in[3];
    const float* reward     = (const float*)d_in[4];
    const float* W1         = (const float*)d_in[5];
    const float* b1         = (const float*)d_in[6];
    const float* Wmu        = (const float*)d_in[7];
    const float* bmu        = (const float*)d_in[8];
    const float* Wlv        = (const float*)d_in[9];
    const float* blv        = (const float*)d_in[10];
    const float* Wc1        = (const float*)d_in[11];
    const float* bc1        = (const float*)d_in[12];
    const float* Wc2        = (const float*)d_in[13];
    const float* bc2        = (const float*)d_in[14];
    float* out = (float*)d_out;

    cudaFuncSetAttribute(fwd_kernel, cudaFuncAttributeMaxDynamicSharedMemorySize, FWD_DSM);

    fwd_kernel<<<NBLK, 512, FWD_DSM>>>(state, next_state, reward,
                                       Wc1, bc1, Wc2, bc2, W1, b1,
                                       Wmu, bmu, Wlv, blv, action, beta_lp);
    scan_kernel<<<32, 32>>>();
    stats_kernel<<<1, 32>>>();
    loss_kernel<<<256, 256>>>();
    final_kernel<<<1, 256>>>(out);
}

// round 7
// speedup vs baseline: 4.6656x; 1.0012x over previous
#include <cuda_runtime.h>
#include <math.h>

#define TT 262144
#define DD 128
#define HH 256
#define AA 8
#define NBLK (TT / 128)   // 2048 blocks of 128 rows

// ---------------- scratch (device globals; no allocation allowed) ----------------
__device__ float  g_v0[TT];
__device__ float  g_delta[TT];
__device__ float  g_adv[TT];
__device__ float  g_ratio[TT];
__device__ double g_part[32][2];
__device__ float  g_mean, g_isd;
__device__ double g_closs;
__device__ double g_lpart[256];

__device__ __forceinline__ float fast_tanh(float x) {
    float y;
    asm("tanh.approx.f32 %0, %1;" : "=f"(y) : "f"(x));
    return y;
}
__device__ __forceinline__ unsigned int to_tf32(float f) {
    unsigned int u;
    asm("cvt.rna.tf32.f32 %0, %1;" : "=r"(u) : "f"(f));
    return u;
}

#define MMA_TF32(d, a, b) \
    asm volatile("mma.sync.aligned.m16n8k8.row.col.f32.tf32.tf32.f32 " \
                 "{%0,%1,%2,%3}, {%4,%5,%6,%7}, {%8,%9}, {%0,%1,%2,%3};" \
                 : "+f"((d)[0]), "+f"((d)[1]), "+f"((d)[2]), "+f"((d)[3]) \
                 : "r"((a)[0]), "r"((a)[1]), "r"((a)[2]), "r"((a)[3]), \
                   "r"((b)[0]), "r"((b)[1]))

__device__ __forceinline__ void cp_async16(void* dst, const void* src) {
    unsigned int s = (unsigned int)__cvta_generic_to_shared(dst);
    asm volatile("cp.async.cg.shared.global [%0], [%1], 16;\n" :: "r"(s), "l"(src));
}
#define CP_COMMIT() asm volatile("cp.async.commit_group;\n" ::: "memory")
#define CP_WAIT(n)  asm volatile("cp.async.wait_group %0;\n" :: "n"(n) : "memory")

// ---------------- smem geometry (32-bit words) ----------------
#define LDA 36
#define LDB 264
#define A_CH_WORDS (128 * LDA)             // 4608
#define B_CH_WORDS (32 * LDB)              // 8448
#define PERBUF (A_CH_WORDS + B_CH_WORDS)   // 13056
#define DSM_WORDS (4 * PERBUF)             // 52224 words = 208896 B
#define FWD_DSM (DSM_WORDS * 4)

// phase-2 overlay (inside buffer region, used after all GEMM chunks consumed)
#define LDH 260
#define H_WORDS (128 * LDH)                // 33280
#define LDW 24                             // Wcat: 256 x 24 (conflict-free)

// async-load one K chunk (A: 128 x 32 floats, B: 32 x 256 floats) — 512 threads
__device__ __forceinline__ void load_chunk(
    unsigned int* buf, const float* __restrict__ Xblk, const float* __restrict__ W,
    int k0, int tid)
{
    unsigned int* As = buf;
    unsigned int* Bs = buf + A_CH_WORDS;
    #pragma unroll
    for (int q = 0; q < 2; q++) {
        int i = tid + q * 512;             // 1024 float4s
        int r = i >> 3, c4 = i & 7;
        cp_async16(&As[r * LDA + c4 * 4], &Xblk[(size_t)r * DD + k0 + c4 * 4]);
    }
    #pragma unroll
    for (int q = 0; q < 4; q++) {
        int i = tid + q * 512;             // 2048 float4s
        int r = i >> 6, c4 = i & 63;
        cp_async16(&Bs[r * LDB + c4 * 4], &W[(size_t)(k0 + r) * HH + c4 * 4]);
    }
}

// mma over one 32-wide K chunk; warp tile 32x64, C[2][8][4]
__device__ __forceinline__ void mma_chunk(
    float C[2][8][4], const unsigned int* buf, int wm, int wn, int qr, int qc)
{
    const unsigned int* As = buf;
    const unsigned int* Bs = buf + A_CH_WORDS;
    #pragma unroll
    for (int kk = 0; kk < 4; kk++) {
        unsigned int a[2][4];
        #pragma unroll
        for (int mt = 0; mt < 2; mt++) {
            const unsigned int* ap = As + (wm * 32 + mt * 16 + qr) * LDA + kk * 8 + qc;
            a[mt][0] = ap[0];
            a[mt][1] = ap[8 * LDA];
            a[mt][2] = ap[4];
            a[mt][3] = ap[8 * LDA + 4];
        }
        unsigned int b[8][2];
        #pragma unroll
        for (int nt = 0; nt < 8; nt++) {
            const unsigned int* bp = Bs + (kk * 8 + qc) * LDB + wn * 64 + nt * 8 + qr;
            b[nt][0] = bp[0];
            b[nt][1] = bp[4 * LDB];
        }
        #pragma unroll
        for (int mt = 0; mt < 2; mt++)
            #pragma unroll
            for (int nt = 0; nt < 8; nt++)
                MMA_TF32(C[mt][nt], a[mt], b[nt]);
    }
}

// ---------------- fused forward: critic(state), critic(next), actor ----------------
__global__ __launch_bounds__(512, 1) void fwd_kernel(
    const float* __restrict__ state, const float* __restrict__ next_state,
    const float* __restrict__ reward,
    const float* __restrict__ Wc1, const float* __restrict__ bc1,
    const float* __restrict__ Wc2, const float* __restrict__ bc2,
    const float* __restrict__ W1,  const float* __restrict__ b1,
    const float* __restrict__ Wmu, const float* __restrict__ bmu,
    const float* __restrict__ Wlv, const float* __restrict__ blv,
    const float* __restrict__ action, const float* __restrict__ beta_lp)
{
    extern __shared__ unsigned int dsm[];
    __shared__ float cb1s[256], cw2s[256], ab1s[256];
    __shared__ float bmus[8], blvs[8];

    const int tid = threadIdx.x;
    const int lane = tid & 31, warp = tid >> 5;
    const int wm = warp >> 2, wn = warp & 3;
    const int qr = lane >> 2, qc = lane & 3;
    const int t0 = blockIdx.x * 128;
    const float* A0 = state + (size_t)t0 * DD;
    const float* A1 = next_state + (size_t)t0 * DD;

    if (tid < 256) { cb1s[tid] = bc1[tid]; cw2s[tid] = Wc2[tid]; ab1s[tid] = b1[tid]; }
    if (tid < 8) { bmus[tid] = bmu[tid]; blvs[tid] = blv[tid]; }

    // chunk schedule: c in 0..11; gemm g=c>>2; k0=(c&3)*32
    // g=0: state@Wc1   g=1: next@Wc1   g=2: state@W1
    auto issue = [&](int c) {
        int g = c >> 2, k0 = (c & 3) * 32;
        const float* Xb = (g == 1) ? A1 : A0;
        const float* Wb = (g == 2) ? W1 : Wc1;
        load_chunk(dsm + (c & 3) * PERBUF, Xb, Wb, k0, tid);
        CP_COMMIT();
    };

    issue(0); issue(1); issue(2);

    float* red = reinterpret_cast<float*>(dsm + 3 * PERBUF);   // [128][4] overlay in buf3
    float v0val = 0.f;
    float C[2][8][4];

    #pragma unroll 1
    for (int g = 0; g < 3; g++) {
        #pragma unroll
        for (int mt = 0; mt < 2; mt++)
            #pragma unroll
            for (int nt = 0; nt < 8; nt++)
                #pragma unroll
                for (int q = 0; q < 4; q++) C[mt][nt][q] = 0.f;

        #pragma unroll
        for (int cc = 0; cc < 4; cc++) {
            int c = g * 4 + cc;
            CP_WAIT(2);
            __syncthreads();
            mma_chunk(C, dsm + (c & 3) * PERBUF, wm, wn, qr, qc);
            if (c < 9) issue(c + 3);
            else       CP_COMMIT();     // empty group keeps wait-count uniform
        }

        if (g < 2) {
            // critic epilogue: v = sum_j tanh(C+b)*w2  (buf3 chunk consumed; red overlay safe)
            __syncthreads();
            #pragma unroll
            for (int mt = 0; mt < 2; mt++) {
                float plo = 0.f, phi = 0.f;
                #pragma unroll
                for (int nt = 0; nt < 8; nt++) {
                    int c0 = wn * 64 + nt * 8 + 2 * qc;
                    plo = fmaf(fast_tanh(C[mt][nt][0] + cb1s[c0]),     cw2s[c0],     plo);
                    plo = fmaf(fast_tanh(C[mt][nt][1] + cb1s[c0 + 1]), cw2s[c0 + 1], plo);
                    phi = fmaf(fast_tanh(C[mt][nt][2] + cb1s[c0]),     cw2s[c0],     phi);
                    phi = fmaf(fast_tanh(C[mt][nt][3] + cb1s[c0 + 1]), cw2s[c0 + 1], phi);
                }
                plo += __shfl_xor_sync(0xffffffffu, plo, 1);
                plo += __shfl_xor_sync(0xffffffffu, plo, 2);
                phi += __shfl_xor_sync(0xffffffffu, phi, 1);
                phi += __shfl_xor_sync(0xffffffffu, phi, 2);
                if (qc == 0) {
                    red[(wm * 32 + mt * 16 + qr) * 4 + wn]       = plo;
                    red[(wm * 32 + mt * 16 + qr + 8) * 4 + wn]   = phi;
                }
            }
            __syncthreads();
            if (tid < 128) {
                float v = red[tid * 4] + red[tid * 4 + 1] + red[tid * 4 + 2] + red[tid * 4 + 3] + bc2[0];
                if (g == 0) {
                    v0val = v;
                    g_v0[t0 + tid] = v;
                } else {
                    g_delta[t0 + tid] = reward[t0 + tid] + 0.99f * v - v0val;
                }
            }
        }
    }

    // ---------------- actor epilogue ----------------
    __syncthreads();                        // all GEMM reads of buffers done
    unsigned int* Hs  = dsm;                // 128 x 260 tf32 overlay
    unsigned int* Ws2 = dsm + H_WORDS;      // 256 x 24 tf32 overlay

    // h = tanh(acc + b1) -> smem tf32
    #pragma unroll
    for (int mt = 0; mt < 2; mt++) {
        int r0 = wm * 32 + mt * 16 + qr;
        #pragma unroll
        for (int nt = 0; nt < 8; nt++) {
            int c0 = wn * 64 + nt * 8 + 2 * qc;
            uint2 lo = make_uint2(to_tf32(fast_tanh(C[mt][nt][0] + ab1s[c0])),
                                  to_tf32(fast_tanh(C[mt][nt][1] + ab1s[c0 + 1])));
            uint2 hi = make_uint2(to_tf32(fast_tanh(C[mt][nt][2] + ab1s[c0])),
                                  to_tf32(fast_tanh(C[mt][nt][3] + ab1s[c0 + 1])));
            *reinterpret_cast<uint2*>(&Hs[r0 * LDH + c0])       = lo;
            *reinterpret_cast<uint2*>(&Hs[(r0 + 8) * LDH + c0]) = hi;
        }
    }
    // Wcat = [Wmu | Wlv] tf32, 256 x 16 padded to 24
    for (int i = tid; i < 2048; i += 512) {
        int k = i >> 3, a = i & 7;
        Ws2[k * LDW + a]     = to_tf32(Wmu[i]);
        Ws2[k * LDW + 8 + a] = to_tf32(Wlv[i]);
    }
    __syncthreads();

    // phase 2 (warps 0..7): P = h @ Wcat, tf32 m16n8k8, k=256
    if (warp < 8) {
        float P[2][4];
        #pragma unroll
        for (int gg = 0; gg < 2; gg++)
            #pragma unroll
            for (int q = 0; q < 4; q++) P[gg][q] = 0.f;

        #pragma unroll 4
        for (int kk = 0; kk < 32; kk++) {
            unsigned int a[4];
            const unsigned int* ap = Hs + (warp * 16 + qr) * LDH + kk * 8 + qc;
            a[0] = ap[0];
            a[1] = ap[8 * LDH];
            a[2] = ap[4];
            a[3] = ap[8 * LDH + 4];
            unsigned int b0[2], b1f[2];
            const unsigned int* bp = Ws2 + (kk * 8 + qc) * LDW + qr;
            b0[0]  = bp[0];
            b0[1]  = bp[4 * LDW];
            b1f[0] = bp[8];
            b1f[1] = bp[4 * LDW + 8];
            MMA_TF32(P[0], a, b0);
            MMA_TF32(P[1], a, b1f);
        }

        const float HLOG2PI = 0.9189385332046727f;
        const int r0 = t0 + warp * 16 + qr;
        const int r1 = r0 + 8;
        const int a0i = 2 * qc;

        float2 act0 = *reinterpret_cast<const float2*>(&action[(size_t)r0 * AA + a0i]);
        float2 bet0 = *reinterpret_cast<const float2*>(&beta_lp[(size_t)r0 * AA + a0i]);
        float2 act1 = *reinterpret_cast<const float2*>(&action[(size_t)r1 * AA + a0i]);
        float2 bet1 = *reinterpret_cast<const float2*>(&beta_lp[(size_t)r1 * AA + a0i]);

        float mu00 = P[0][0] + bmus[a0i], mu01 = P[0][1] + bmus[a0i + 1];
        float lv00 = P[1][0] + blvs[a0i], lv01 = P[1][1] + blvs[a0i + 1];
        float mu10 = P[0][2] + bmus[a0i], mu11 = P[0][3] + bmus[a0i + 1];
        float lv10 = P[1][2] + blvs[a0i], lv11 = P[1][3] + blvs[a0i + 1];

        float d, s_lo, s_hi;
        d = act0.x - mu00; s_lo  = -0.5f * d * d * __expf(-lv00) - 0.5f * lv00 - HLOG2PI - bet0.x;
        d = act0.y - mu01; s_lo += -0.5f * d * d * __expf(-lv01) - 0.5f * lv01 - HLOG2PI - bet0.y;
        d = act1.x - mu10; s_hi  = -0.5f * d * d * __expf(-lv10) - 0.5f * lv10 - HLOG2PI - bet1.x;
        d = act1.y - mu11; s_hi += -0.5f * d * d * __expf(-lv11) - 0.5f * lv11 - HLOG2PI - bet1.y;

        s_lo += __shfl_xor_sync(0xffffffffu, s_lo, 1);
        s_lo += __shfl_xor_sync(0xffffffffu, s_lo, 2);
        s_hi += __shfl_xor_sync(0xffffffffu, s_hi, 1);
        s_hi += __shfl_xor_sync(0xffffffffu, s_hi, 2);

        if (qc == 0) {
            g_ratio[r0] = __expf(s_lo);
            g_ratio[r1] = __expf(s_hi);
        }
    }
}

// ---------------- GAE scan + advantage + partial stats ----------------
__global__ void scan_kernel()
{
    const int C = 256, W = 1024;
    const int chunk = blockIdx.x * 32 + threadIdx.x;   // 1024 chunks
    const int t0 = chunk * C;
    const int start = min(TT, t0 + C + W);
    const float CFAC = (float)(0.99 * 0.95);

    float g = 0.f;
    double s = 0.0, s2 = 0.0;
    for (int t = start - 1; t >= t0; --t) {
        g = fmaf(CFAC, g, g_delta[t]);
        if (t < t0 + C) {
            float adv = g - g_v0[t];
            g_adv[t] = adv;
            s  += (double)adv;
            s2 += (double)adv * (double)adv;
        }
    }
    #pragma unroll
    for (int off = 16; off > 0; off >>= 1) {
        s  += __shfl_down_sync(0xffffffffu, s, off);
        s2 += __shfl_down_sync(0xffffffffu, s2, off);
    }
    if (threadIdx.x == 0) {
        g_part[blockIdx.x][0] = s;
        g_part[blockIdx.x][1] = s2;
    }
}

__global__ void stats_kernel()
{
    if (threadIdx.x == 0) {
        double S = 0.0, S2 = 0.0;
        for (int i = 0; i < 32; i++) { S += g_part[i][0]; S2 += g_part[i][1]; }
        double mean = S / (double)TT;
        double var  = (S2 - S * S / (double)TT) / (double)(TT - 1);
        double sd   = sqrt(var);
        g_mean  = (float)mean;
        g_isd   = (float)(1.0 / (sd + 1e-7));
        g_closs = S2;
    }
}

// ---------------- actor loss pass: sum min(ratio*ahat, clip(ratio)*ahat) ----------------
__global__ void loss_kernel()
{
    const float mean = g_mean, isd = g_isd;
    double s = 0.0;
    for (int t = blockIdx.x * 256 + threadIdx.x; t < TT; t += 256 * 256) {
        float ratio = g_ratio[t];
        float ahat  = (g_adv[t] - mean) * isd;
        float rc    = fminf(fmaxf(ratio, 0.8f), 1.2f);
        s += (double)fminf(ratio * ahat, rc * ahat);
    }
    __shared__ double sh[256];
    sh[threadIdx.x] = s;
    __syncthreads();
    for (int off = 128; off > 0; off >>= 1) {
        if (threadIdx.x < off) sh[threadIdx.x] += sh[threadIdx.x + off];
        __syncthreads();
    }
    if (threadIdx.x == 0) g_lpart[blockIdx.x] = sh[0];
}

__global__ void final_kernel(float* __restrict__ out)
{
    __shared__ double sh[256];
    sh[threadIdx.x] = g_lpart[threadIdx.x];
    __syncthreads();
    for (int off = 128; off > 0; off >>= 1) {
        if (threadIdx.x < off) sh[threadIdx.x] += sh[threadIdx.x + off];
        __syncthreads();
    }
    if (threadIdx.x == 0) out[0] = (float)(g_closs - sh[0]);
}

// ---------------- launch ----------------
extern "C" void kernel_launch(void* const* d_in, const int* in_sizes, int n_in,
                              void* d_out, int out_size)
{
    const float* state      = (const float*)d_in[0];
    const float* next_state = (const float*)d_in[1];
    const float* action     = (const float*)d_in[2];
    const float* beta_lp    = (const float*)d_in[3];
    const float* reward     = (const float*)d_in[4];
    const float* W1         = (const float*)d_in[5];
    const float* b1         = (const float*)d_in[6];
    const float* Wmu        = (const float*)d_in[7];
    const float* bmu        = (const float*)d_in[8];
    const float* Wlv        = (const float*)d_in[9];
    const float* blv        = (const float*)d_in[10];
    const float* Wc1        = (const float*)d_in[11];
    const float* bc1        = (const float*)d_in[12];
    const float* Wc2        = (const float*)d_in[13];
    const float* bc2        = (const float*)d_in[14];
    float* out = (float*)d_out;

    cudaFuncSetAttribute(fwd_kernel, cudaFuncAttributeMaxDynamicSharedMemorySize, FWD_DSM);

    fwd_kernel<<<NBLK, 512, FWD_DSM>>>(state, next_state, reward,
                                       Wc1, bc1, Wc2, bc2, W1, b1,
                                       Wmu, bmu, Wlv, blv, action, beta_lp);
    scan_kernel<<<32, 32>>>();
    stats_kernel<<<1, 32>>>();
    loss_kernel<<<256, 256>>>();
    final_kernel<<<1, 256>>>(out);
}

// round 10
// speedup vs baseline: 6.0342x; 1.2933x over previous
#include <cuda_runtime.h>
#include <cuda_bf16.h>
#include <cstdint>
#include <math.h>

#define TT 262144
#define DD 128
#define HH 256
#define AA 8
#define NBLK (TT / 128)

// ---------------- scratch (device globals; no allocation allowed) ----------------
__device__ float  g_v0[TT];
__device__ float  g_delta[TT];
__device__ float  g_adv[TT];
__device__ float  g_ratio[TT];
__device__ double g_part[32][2];
__device__ float  g_mean, g_isd;
__device__ double g_closs;
__device__ double g_lpart[256];

// pre-converted bf16 weights, [n][k] layout, pitch 136 (main) / 264 (heads)
__device__ __align__(16) __nv_bfloat16 g_Bc[256 * 136];   // Wc1
__device__ __align__(16) __nv_bfloat16 g_Bw[256 * 136];   // W1
__device__ __align__(16) __nv_bfloat16 g_Bp[16 * 264];    // [Wmu | Wlv]

__device__ __forceinline__ float fast_tanh(float x) {
    float y;
    asm("tanh.approx.f32 %0, %1;" : "=f"(y) : "f"(x));
    return y;
}

#define MMA_BF16(d, a, b) \
    asm volatile("mma.sync.aligned.m16n8k16.row.col.f32.bf16.bf16.f32 " \
                 "{%0,%1,%2,%3}, {%4,%5,%6,%7}, {%8,%9}, {%0,%1,%2,%3};" \
                 : "+f"((d)[0]), "+f"((d)[1]), "+f"((d)[2]), "+f"((d)[3]) \
                 : "r"((a)[0]), "r"((a)[1]), "r"((a)[2]), "r"((a)[3]), \
                   "r"((b)[0]), "r"((b)[1]))

__device__ __forceinline__ void cp_async16(void* dst, const void* src) {
    unsigned int s = (unsigned int)__cvta_generic_to_shared(dst);
    asm volatile("cp.async.cg.shared.global [%0], [%1], 16;\n" :: "r"(s), "l"(src));
}
#define CP_COMMIT() asm volatile("cp.async.commit_group;\n" ::: "memory")
#define CP_WAIT0()  asm volatile("cp.async.wait_group 0;\n" ::: "memory")

// ---------------- smem layout (bytes) ----------------
// A pitch = 136 halves (272B); B pitch = 136; H/Wcat pitch = 264
#define LDAH 136
#define LDHH 264
#define SM_A0   0
#define SM_A1   34816
#define SM_BC   69632
#define SM_BW   139264
#define SM_WC   208896
#define SM_RED  217344
#define SM_VROW 219392
#define FWD_SMEM 219904
#define SM_H    0            // h overlay: 128 x 264 halves = 67584B over A0+A1

// ---------------- prep: convert weights to bf16 [n][k] ----------------
__global__ void prep_kernel(const float* __restrict__ Wc1, const float* __restrict__ W1,
                            const float* __restrict__ Wmu, const float* __restrict__ Wlv)
{
    int g = blockIdx.x * 256 + threadIdx.x;                 // 16384 threads
    for (int i = g; i < 128 * 256; i += 16384) {
        int k = i >> 8, n = i & 255;                        // W[k][n] row-major
        g_Bc[n * LDAH + k] = __float2bfloat16(Wc1[i]);
        g_Bw[n * LDAH + k] = __float2bfloat16(W1[i]);
    }
    for (int i = g; i < 256 * 16; i += 16384) {
        int k = i >> 4, n = i & 15;
        float v = (n < 8) ? Wmu[k * 8 + n] : Wlv[k * 8 + (n - 8)];
        g_Bp[n * LDHH + k] = __float2bfloat16(v);
    }
}

// full-K (128) bf16 GEMM accumulate: warp tile 32x64
__device__ __forceinline__ void mma_full(
    float C[2][8][4], const __nv_bfloat16* As, const __nv_bfloat16* Bs,
    int wm, int wn, int qr, int qc)
{
    #pragma unroll
    for (int kb = 0; kb < 8; kb++) {
        const int kb16 = kb * 16;
        unsigned int a[2][4];
        #pragma unroll
        for (int mt = 0; mt < 2; mt++) {
            const __nv_bfloat16* ap = As + (wm * 32 + mt * 16 + qr) * LDAH + kb16 + 2 * qc;
            a[mt][0] = *reinterpret_cast<const unsigned int*>(ap);
            a[mt][1] = *reinterpret_cast<const unsigned int*>(ap + 8 * LDAH);
            a[mt][2] = *reinterpret_cast<const unsigned int*>(ap + 8);
            a[mt][3] = *reinterpret_cast<const unsigned int*>(ap + 8 * LDAH + 8);
        }
        unsigned int b[8][2];
        #pragma unroll
        for (int nt = 0; nt < 8; nt++) {
            const __nv_bfloat16* bp = Bs + (wn * 64 + nt * 8 + qr) * LDAH + kb16 + 2 * qc;
            b[nt][0] = *reinterpret_cast<const unsigned int*>(bp);
            b[nt][1] = *reinterpret_cast<const unsigned int*>(bp + 8);
        }
        #pragma unroll
        for (int mt = 0; mt < 2; mt++)
            #pragma unroll
            for (int nt = 0; nt < 8; nt++)
                MMA_BF16(C[mt][nt], a[mt], b[nt]);
    }
}

// ---------------- fused forward ----------------
__global__ __launch_bounds__(512, 1) void fwd_kernel(
    const float* __restrict__ state, const float* __restrict__ next_state,
    const float* __restrict__ reward,
    const float* __restrict__ bc1, const float* __restrict__ Wc2, const float* __restrict__ bc2,
    const float* __restrict__ b1,  const float* __restrict__ bmu, const float* __restrict__ blv,
    const float* __restrict__ action, const float* __restrict__ beta_lp)
{
    extern __shared__ unsigned char dsm[];
    __shared__ float cb1s[256], cw2s[256], ab1s[256];
    __shared__ float bmus[8], blvs[8];

    const int tid = threadIdx.x;
    const int lane = tid & 31, warp = tid >> 5;
    const int wm = warp >> 2, wn = warp & 3;
    const int qr = lane >> 2, qc = lane & 3;
    const int t0 = blockIdx.x * 128;

    __nv_bfloat16* A0 = reinterpret_cast<__nv_bfloat16*>(dsm + SM_A0);
    __nv_bfloat16* A1 = reinterpret_cast<__nv_bfloat16*>(dsm + SM_A1);
    __nv_bfloat16* BC = reinterpret_cast<__nv_bfloat16*>(dsm + SM_BC);
    __nv_bfloat16* BW = reinterpret_cast<__nv_bfloat16*>(dsm + SM_BW);
    __nv_bfloat16* WC = reinterpret_cast<__nv_bfloat16*>(dsm + SM_WC);
    __nv_bfloat16* Hs = reinterpret_cast<__nv_bfloat16*>(dsm + SM_H);
    float* red  = reinterpret_cast<float*>(dsm + SM_RED);
    float* vrow = reinterpret_cast<float*>(dsm + SM_VROW);

    if (tid < 256) { cb1s[tid] = bc1[tid]; cw2s[tid] = Wc2[tid]; ab1s[tid] = b1[tid]; }
    if (tid < 8)   { bmus[tid] = bmu[tid]; blvs[tid] = blv[tid]; }

    // stage weights (identity bf16 copies, L2-hot)
    {
        const unsigned char* src_c = reinterpret_cast<const unsigned char*>(g_Bc);
        const unsigned char* src_w = reinterpret_cast<const unsigned char*>(g_Bw);
        const unsigned char* src_p = reinterpret_cast<const unsigned char*>(g_Bp);
        for (int i = tid; i < 4352; i += 512) cp_async16(dsm + SM_BC + i * 16, src_c + i * 16);
        for (int i = tid; i < 4352; i += 512) cp_async16(dsm + SM_BW + i * 16, src_w + i * 16);
        for (int i = tid; i < 528;  i += 512) cp_async16(dsm + SM_WC + i * 16, src_p + i * 16);
        CP_COMMIT();
    }

    // stage A tiles: f32 -> bf16, padded-136 layout
    const float* S0 = state + (size_t)t0 * DD;
    const float* S1 = next_state + (size_t)t0 * DD;
    #pragma unroll
    for (int q = 0; q < 8; q++) {
        int idx = tid + q * 512;            // 4096 float4 per matrix
        int r = idx >> 5, c4 = idx & 31;
        float4 v0 = *reinterpret_cast<const float4*>(&S0[(size_t)r * DD + c4 * 4]);
        float4 v1 = *reinterpret_cast<const float4*>(&S1[(size_t)r * DD + c4 * 4]);
        __nv_bfloat162 p00 = __floats2bfloat162_rn(v0.x, v0.y);
        __nv_bfloat162 p01 = __floats2bfloat162_rn(v0.z, v0.w);
        __nv_bfloat162 p10 = __floats2bfloat162_rn(v1.x, v1.y);
        __nv_bfloat162 p11 = __floats2bfloat162_rn(v1.z, v1.w);
        *reinterpret_cast<__nv_bfloat162*>(&A0[r * LDAH + c4 * 4])     = p00;
        *reinterpret_cast<__nv_bfloat162*>(&A0[r * LDAH + c4 * 4 + 2]) = p01;
        *reinterpret_cast<__nv_bfloat162*>(&A1[r * LDAH + c4 * 4])     = p10;
        *reinterpret_cast<__nv_bfloat162*>(&A1[r * LDAH + c4 * 4 + 2]) = p11;
    }
    CP_WAIT0();
    __syncthreads();

    float C[2][8][4];
    float v0val = 0.f;

    // ---- GEMM 0: critic(state) ----
    #pragma unroll
    for (int mt = 0; mt < 2; mt++)
        #pragma unroll
        for (int nt = 0; nt < 8; nt++)
            #pragma unroll
            for (int q = 0; q < 4; q++) C[mt][nt][q] = 0.f;
    mma_full(C, A0, BC, wm, wn, qr, qc);

    #pragma unroll
    for (int mt = 0; mt < 2; mt++) {
        float plo = 0.f, phi = 0.f;
        #pragma unroll
        for (int nt = 0; nt < 8; nt++) {
            int c0 = wn * 64 + nt * 8 + 2 * qc;
            plo = fmaf(fast_tanh(C[mt][nt][0] + cb1s[c0]),     cw2s[c0],     plo);
            plo = fmaf(fast_tanh(C[mt][nt][1] + cb1s[c0 + 1]), cw2s[c0 + 1], plo);
            phi = fmaf(fast_tanh(C[mt][nt][2] + cb1s[c0]),     cw2s[c0],     phi);
            phi = fmaf(fast_tanh(C[mt][nt][3] + cb1s[c0 + 1]), cw2s[c0 + 1], phi);
        }
        plo += __shfl_xor_sync(0xffffffffu, plo, 1);
        plo += __shfl_xor_sync(0xffffffffu, plo, 2);
        phi += __shfl_xor_sync(0xffffffffu, phi, 1);
        phi += __shfl_xor_sync(0xffffffffu, phi, 2);
        if (qc == 0) {
            red[(wm * 32 + mt * 16 + qr) * 4 + wn]     = plo;
            red[(wm * 32 + mt * 16 + qr + 8) * 4 + wn] = phi;
        }
    }
    __syncthreads();
    if (tid < 128) {
        float v = red[tid * 4] + red[tid * 4 + 1] + red[tid * 4 + 2] + red[tid * 4 + 3] + bc2[0];
        vrow[tid] = v;
        g_v0[t0 + tid] = v;
    }

    // ---- GEMM 1: critic(next_state) ----
    #pragma unroll
    for (int mt = 0; mt < 2; mt++)
        #pragma unroll
        for (int nt = 0; nt < 8; nt++)
            #pragma unroll
            for (int q = 0; q < 4; q++) C[mt][nt][q] = 0.f;
    mma_full(C, A1, BC, wm, wn, qr, qc);

    __syncthreads();     // red reuse safe
    #pragma unroll
    for (int mt = 0; mt < 2; mt++) {
        float plo = 0.f, phi = 0.f;
        #pragma unroll
        for (int nt = 0; nt < 8; nt++) {
            int c0 = wn * 64 + nt * 8 + 2 * qc;
            plo = fmaf(fast_tanh(C[mt][nt][0] + cb1s[c0]),     cw2s[c0],     plo);
            plo = fmaf(fast_tanh(C[mt][nt][1] + cb1s[c0 + 1]), cw2s[c0 + 1], plo);
            phi = fmaf(fast_tanh(C[mt][nt][2] + cb1s[c0]),     cw2s[c0],     phi);
            phi = fmaf(fast_tanh(C[mt][nt][3] + cb1s[c0 + 1]), cw2s[c0 + 1], phi);
        }
        plo += __shfl_xor_sync(0xffffffffu, plo, 1);
        plo += __shfl_xor_sync(0xffffffffu, plo, 2);
        phi += __shfl_xor_sync(0xffffffffu, phi, 1);
        phi += __shfl_xor_sync(0xffffffffu, phi, 2);
        if (qc == 0) {
            red[(wm * 32 + mt * 16 + qr) * 4 + wn]     = plo;
            red[(wm * 32 + mt * 16 + qr + 8) * 4 + wn] = phi;
        }
    }
    __syncthreads();
    if (tid < 128) {
        float v1 = red[tid * 4] + red[tid * 4 + 1] + red[tid * 4 + 2] + red[tid * 4 + 3] + bc2[0];
        g_delta[t0 + tid] = reward[t0 + tid] + 0.99f * v1 - vrow[tid];
    }

    // ---- GEMM 2: actor layer 1 ----
    #pragma unroll
    for (int mt = 0; mt < 2; mt++)
        #pragma unroll
        for (int nt = 0; nt < 8; nt++)
            #pragma unroll
            for (int q = 0; q < 4; q++) C[mt][nt][q] = 0.f;
    mma_full(C, A0, BW, wm, wn, qr, qc);

    __syncthreads();     // all warps done reading A0/A1 before h overlay
    #pragma unroll
    for (int mt = 0; mt < 2; mt++) {
        int r0 = wm * 32 + mt * 16 + qr;
        #pragma unroll
        for (int nt = 0; nt < 8; nt++) {
            int c0 = wn * 64 + nt * 8 + 2 * qc;
            __nv_bfloat162 lo = __floats2bfloat162_rn(fast_tanh(C[mt][nt][0] + ab1s[c0]),
                                                      fast_tanh(C[mt][nt][1] + ab1s[c0 + 1]));
            __nv_bfloat162 hi = __floats2bfloat162_rn(fast_tanh(C[mt][nt][2] + ab1s[c0]),
                                                      fast_tanh(C[mt][nt][3] + ab1s[c0 + 1]));
            *reinterpret_cast<__nv_bfloat162*>(&Hs[r0 * LDHH + c0])       = lo;
            *reinterpret_cast<__nv_bfloat162*>(&Hs[(r0 + 8) * LDHH + c0]) = hi;
        }
    }
    __syncthreads();

    // ---- phase 2 (warps 0..7): P = h @ [Wmu | Wlv], K=256 ----
    if (warp < 8) {
        float P[2][4];
        #pragma unroll
        for (int g = 0; g < 2; g++)
            #pragma unroll
            for (int q = 0; q < 4; q++) P[g][q] = 0.f;

        #pragma unroll
        for (int kb = 0; kb < 16; kb++) {
            const int kb16 = kb * 16;
            unsigned int a[4];
            const __nv_bfloat16* ap = Hs + (warp * 16 + qr) * LDHH + kb16 + 2 * qc;
            a[0] = *reinterpret_cast<const unsigned int*>(ap);
            a[1] = *reinterpret_cast<const unsigned int*>(ap + 8 * LDHH);
            a[2] = *reinterpret_cast<const unsigned int*>(ap + 8);
            a[3] = *reinterpret_cast<const unsigned int*>(ap + 8 * LDHH + 8);
            unsigned int bm[2], bl[2];
            const __nv_bfloat16* bp = WC + qr * LDHH + kb16 + 2 * qc;
            bm[0] = *reinterpret_cast<const unsigned int*>(bp);
            bm[1] = *reinterpret_cast<const unsigned int*>(bp + 8);
            bl[0] = *reinterpret_cast<const unsigned int*>(bp + 8 * LDHH);
            bl[1] = *reinterpret_cast<const unsigned int*>(bp + 8 * LDHH + 8);
            MMA_BF16(P[0], a, bm);
            MMA_BF16(P[1], a, bl);
        }

        // PPO ratio epilogue
        const float HLOG2PI = 0.9189385332046727f;
        const int r0 = t0 + warp * 16 + qr;
        const int r1 = r0 + 8;
        const int a0i = 2 * qc;

        float2 act0 = *reinterpret_cast<const float2*>(&action[(size_t)r0 * AA + a0i]);
        float2 bet0 = *reinterpret_cast<const float2*>(&beta_lp[(size_t)r0 * AA + a0i]);
        float2 act1 = *reinterpret_cast<const float2*>(&action[(size_t)r1 * AA + a0i]);
        float2 bet1 = *reinterpret_cast<const float2*>(&beta_lp[(size_t)r1 * AA + a0i]);

        float mu00 = P[0][0] + bmus[a0i], mu01 = P[0][1] + bmus[a0i + 1];
        float lv00 = P[1][0] + blvs[a0i], lv01 = P[1][1] + blvs[a0i + 1];
        float mu10 = P[0][2] + bmus[a0i], mu11 = P[0][3] + bmus[a0i + 1];
        float lv10 = P[1][2] + blvs[a0i], lv11 = P[1][3] + blvs[a0i + 1];

        float d, s_lo, s_hi;
        d = act0.x - mu00; s_lo  = -0.5f * d * d * __expf(-lv00) - 0.5f * lv00 - HLOG2PI - bet0.x;
        d = act0.y - mu01; s_lo += -0.5f * d * d * __expf(-lv01) - 0.5f * lv01 - HLOG2PI - bet0.y;
        d = act1.x - mu10; s_hi  = -0.5f * d * d * __expf(-lv10) - 0.5f * lv10 - HLOG2PI - bet1.x;
        d = act1.y - mu11; s_hi += -0.5f * d * d * __expf(-lv11) - 0.5f * lv11 - HLOG2PI - bet1.y;

        s_lo += __shfl_xor_sync(0xffffffffu, s_lo, 1);
        s_lo += __shfl_xor_sync(0xffffffffu, s_lo, 2);
        s_hi += __shfl_xor_sync(0xffffffffu, s_hi, 1);
        s_hi += __shfl_xor_sync(0xffffffffu, s_hi, 2);

        if (qc == 0) {
            g_ratio[r0] = __expf(s_lo);
            g_ratio[r1] = __expf(s_hi);
        }
    }
}

// ---------------- GAE scan + advantage + partial stats ----------------
__global__ void scan_kernel()
{
    const int C = 256, W = 1024;
    const int chunk = blockIdx.x * 32 + threadIdx.x;
    const int t0 = chunk * C;
    const int start = min(TT, t0 + C + W);
    const float CFAC = (float)(0.99 * 0.95);

    float g = 0.f;
    double s = 0.0, s2 = 0.0;
    for (int t = start - 1; t >= t0; --t) {
        g = fmaf(CFAC, g, g_delta[t]);
        if (t < t0 + C) {
            float adv = g - g_v0[t];
            g_adv[t] = adv;
            s  += (double)adv;
            s2 += (double)adv * (double)adv;
        }
    }
    #pragma unroll
    for (int off = 16; off > 0; off >>= 1) {
        s  += __shfl_down_sync(0xffffffffu, s, off);
        s2 += __shfl_down_sync(0xffffffffu, s2, off);
    }
    if (threadIdx.x == 0) { g_part[blockIdx.x][0] = s; g_part[blockIdx.x][1] = s2; }
}

__global__ void stats_kernel()
{
    if (threadIdx.x == 0) {
        double S = 0.0, S2 = 0.0;
        for (int i = 0; i < 32; i++) { S += g_part[i][0]; S2 += g_part[i][1]; }
        double mean = S / (double)TT;
        double var  = (S2 - S * S / (double)TT) / (double)(TT - 1);
        g_mean  = (float)mean;
        g_isd   = (float)(1.0 / (sqrt(var) + 1e-7));
        g_closs = S2;
    }
}

__global__ void loss_kernel()
{
    const float mean = g_mean, isd = g_isd;
    double s = 0.0;
    for (int t = blockIdx.x * 256 + threadIdx.x; t < TT; t += 256 * 256) {
        float ratio = g_ratio[t];
        float ahat  = (g_adv[t] - mean) * isd;
        float rc    = fminf(fmaxf(ratio, 0.8f), 1.2f);
        s += (double)fminf(ratio * ahat, rc * ahat);
    }
    __shared__ double sh[256];
    sh[threadIdx.x] = s;
    __syncthreads();
    for (int off = 128; off > 0; off >>= 1) {
        if (threadIdx.x < off) sh[threadIdx.x] += sh[threadIdx.x + off];
        __syncthreads();
    }
    if (threadIdx.x == 0) g_lpart[blockIdx.x] = sh[0];
}

__global__ void final_kernel(float* __restrict__ out)
{
    __shared__ double sh[256];
    sh[threadIdx.x] = g_lpart[threadIdx.x];
    __syncthreads();
    for (int off = 128; off > 0; off >>= 1) {
        if (threadIdx.x < off) sh[threadIdx.x] += sh[threadIdx.x + off];
        __syncthreads();
    }
    if (threadIdx.x == 0) out[0] = (float)(g_closs - sh[0]);
}

// ---------------- launch ----------------
extern "C" void kernel_launch(void* const* d_in, const int* in_sizes, int n_in,
                              void* d_out, int out_size)
{
    const float* state      = (const float*)d_in[0];
    const float* next_state = (const float*)d_in[1];
    const float* action     = (const float*)d_in[2];
    const float* beta_lp    = (const float*)d_in[3];
    const float* reward     = (const float*)d_in[4];
    const float* W1         = (const float*)d_in[5];
    const float* b1         = (const float*)d_in[6];
    const float* Wmu        = (const float*)d_in[7];
    const float* bmu        = (const float*)d_in[8];
    const float* Wlv        = (const float*)d_in[9];
    const float* blv        = (const float*)d_in[10];
    const float* Wc1        = (const float*)d_in[11];
    const float* bc1        = (const float*)d_in[12];
    const float* Wc2        = (const float*)d_in[13];
    const float* bc2        = (const float*)d_in[14];
    float* out = (float*)d_out;

    cudaFuncSetAttribute(fwd_kernel, cudaFuncAttributeMaxDynamicSharedMemorySize, FWD_SMEM);

    prep_kernel<<<64, 256>>>(Wc1, W1, Wmu, Wlv);
    fwd_kernel<<<NBLK, 512, FWD_SMEM>>>(state, next_state, reward,
                                        bc1, Wc2, bc2, b1, bmu, blv, action, beta_lp);
    scan_kernel<<<32, 32>>>();
    stats_kernel<<<1, 32>>>();
    loss_kernel<<<256, 256>>>();
    final_kernel<<<1, 256>>>(out);
}

// round 11
// speedup vs baseline: 6.2521x; 1.0361x over previous
#include <cuda_runtime.h>
#include <cuda_bf16.h>
#include <cstdint>
#include <math.h>

#define TT 262144
#define DD 128
#define HH 256
#define AA 8
#define NBLK (TT / 128)

// ---------------- scratch (device globals; no allocation allowed) ----------------
__device__ float  g_v0[TT];
__device__ float  g_delta[TT];
__device__ float  g_adv[TT];
__device__ float  g_ratio[TT];
__device__ double g_part[32][2];
__device__ float  g_mean, g_isd;
__device__ double g_closs;
__device__ double g_lpart[256];

// pre-converted bf16 weights, [n][k] layout, pitch 136 (main) / 264 (heads)
__device__ __align__(16) __nv_bfloat16 g_Bc[256 * 136];   // Wc1
__device__ __align__(16) __nv_bfloat16 g_Bw[256 * 136];   // W1
__device__ __align__(16) __nv_bfloat16 g_Bp[16 * 264];    // [Wmu | Wlv]

__device__ __forceinline__ float fast_tanh(float x) {
    float y;
    asm("tanh.approx.f32 %0, %1;" : "=f"(y) : "f"(x));
    return y;
}
__device__ __forceinline__ unsigned int smem_u32(const void* p) {
    unsigned int a;
    asm("{ .reg .u64 t; cvta.to.shared.u64 t, %1; cvt.u32.u64 %0, t; }" : "=r"(a) : "l"(p));
    return a;
}

#define MMA_BF16(d, a, b) \
    asm volatile("mma.sync.aligned.m16n8k16.row.col.f32.bf16.bf16.f32 " \
                 "{%0,%1,%2,%3}, {%4,%5,%6,%7}, {%8,%9}, {%0,%1,%2,%3};" \
                 : "+f"((d)[0]), "+f"((d)[1]), "+f"((d)[2]), "+f"((d)[3]) \
                 : "r"((a)[0]), "r"((a)[1]), "r"((a)[2]), "r"((a)[3]), \
                   "r"((b)[0]), "r"((b)[1]))

#define LDSM_X4(r, addr) \
    asm volatile("ldmatrix.sync.aligned.m8n8.x4.shared.b16 {%0,%1,%2,%3}, [%4];" \
        : "=r"((r)[0]), "=r"((r)[1]), "=r"((r)[2]), "=r"((r)[3]) : "r"(addr))

__device__ __forceinline__ void cp_async16(void* dst, const void* src) {
    unsigned int s = (unsigned int)__cvta_generic_to_shared(dst);
    asm volatile("cp.async.cg.shared.global [%0], [%1], 16;\n" :: "r"(s), "l"(src));
}
#define CP_COMMIT() asm volatile("cp.async.commit_group;\n" ::: "memory")
#define CP_WAIT0()  asm volatile("cp.async.wait_group 0;\n" ::: "memory")

// ---------------- smem layout (bytes) ----------------
#define LDAH 136     // halves; 272B row pitch (odd 16B units -> LDSM conflict-free)
#define LDHH 264
#define SM_A0   0
#define SM_A1   34816
#define SM_BC   69632
#define SM_BW   139264
#define SM_WC   208896
#define SM_RED0 217344
#define SM_RED1 219392
#define FWD_SMEM 221440
#define SM_H    0            // h overlay: 128 x 264 halves = 67584B over A0+A1

// ---------------- prep: convert weights to bf16 [n][k] ----------------
__global__ void prep_kernel(const float* __restrict__ Wc1, const float* __restrict__ W1,
                            const float* __restrict__ Wmu, const float* __restrict__ Wlv)
{
    int g = blockIdx.x * 256 + threadIdx.x;                 // 16384 threads
    for (int i = g; i < 128 * 256; i += 16384) {
        int k = i >> 8, n = i & 255;
        g_Bc[n * LDAH + k] = __float2bfloat16(Wc1[i]);
        g_Bw[n * LDAH + k] = __float2bfloat16(W1[i]);
    }
    for (int i = g; i < 256 * 16; i += 16384) {
        int k = i >> 4, n = i & 15;
        float v = (n < 8) ? Wmu[k * 8 + n] : Wlv[k * 8 + (n - 8)];
        g_Bp[n * LDHH + k] = __float2bfloat16(v);
    }
}

// full-K (128) bf16 GEMM via ldmatrix fragments; warp tile 32x64
// aOff[2]/bOff[4]: per-lane byte offsets within the A/B regions
__device__ __forceinline__ void mma_full(
    float C[2][8][4], unsigned int aRegion, unsigned int bRegion,
    const unsigned int aOff[2], const unsigned int bOff[4])
{
    #pragma unroll
    for (int kb = 0; kb < 8; kb++) {
        const unsigned int koff = kb * 32;      // 16 halves = 32 bytes
        unsigned int a[2][4];
        LDSM_X4(a[0], aRegion + aOff[0] + koff);
        LDSM_X4(a[1], aRegion + aOff[1] + koff);
        unsigned int bb[4][4];
        #pragma unroll
        for (int p = 0; p < 4; p++) LDSM_X4(bb[p], bRegion + bOff[p] + koff);
        #pragma unroll
        for (int mt = 0; mt < 2; mt++)
            #pragma unroll
            for (int p = 0; p < 4; p++) {
                MMA_BF16(C[mt][2 * p],     a[mt], bb[p]);
                MMA_BF16(C[mt][2 * p + 1], a[mt], (bb[p] + 2));
            }
    }
}

// ---------------- fused forward ----------------
__global__ __launch_bounds__(512, 1) void fwd_kernel(
    const float* __restrict__ state, const float* __restrict__ next_state,
    const float* __restrict__ reward,
    const float* __restrict__ bc1, const float* __restrict__ Wc2, const float* __restrict__ bc2,
    const float* __restrict__ b1,  const float* __restrict__ bmu, const float* __restrict__ blv,
    const float* __restrict__ action, const float* __restrict__ beta_lp)
{
    extern __shared__ unsigned char dsm[];
    __shared__ float cb1s[256], cw2s[256], ab1s[256];
    __shared__ float bmus[8], blvs[8];

    const int tid = threadIdx.x;
    const int lane = tid & 31, warp = tid >> 5;
    const int wm = warp >> 2, wn = warp & 3;
    const int qr = lane >> 2, qc = lane & 3;
    const int lrow = lane & 7, lmat = lane >> 3;
    const int t0 = blockIdx.x * 128;

    const unsigned int sb = smem_u32(dsm);
    __nv_bfloat16* A0h = reinterpret_cast<__nv_bfloat16*>(dsm + SM_A0);
    __nv_bfloat16* A1h = reinterpret_cast<__nv_bfloat16*>(dsm + SM_A1);
    __nv_bfloat16* WC  = reinterpret_cast<__nv_bfloat16*>(dsm + SM_WC);
    __nv_bfloat16* Hs  = reinterpret_cast<__nv_bfloat16*>(dsm + SM_H);
    float* red0 = reinterpret_cast<float*>(dsm + SM_RED0);
    float* red1 = reinterpret_cast<float*>(dsm + SM_RED1);

    if (tid < 256) { cb1s[tid] = bc1[tid]; cw2s[tid] = Wc2[tid]; ab1s[tid] = b1[tid]; }
    if (tid < 8)   { bmus[tid] = bmu[tid]; blvs[tid] = blv[tid]; }

    // per-lane ldmatrix fragment offsets (bytes within region)
    unsigned int aOff[2], bOff[4];
    #pragma unroll
    for (int mt = 0; mt < 2; mt++)
        aOff[mt] = (unsigned int)((wm * 32 + mt * 16 + (lmat & 1) * 8 + lrow) * 272 + ((lmat >> 1) * 8) * 2);
    #pragma unroll
    for (int p = 0; p < 4; p++)
        bOff[p] = (unsigned int)((wn * 64 + p * 16 + (lmat >> 1) * 8 + lrow) * 272 + ((lmat & 1) * 8) * 2);

    // stage weights (identity bf16 copies, L2-hot)
    {
        const unsigned char* src_c = reinterpret_cast<const unsigned char*>(g_Bc);
        const unsigned char* src_w = reinterpret_cast<const unsigned char*>(g_Bw);
        const unsigned char* src_p = reinterpret_cast<const unsigned char*>(g_Bp);
        for (int i = tid; i < 4352; i += 512) cp_async16(dsm + SM_BC + i * 16, src_c + i * 16);
        for (int i = tid; i < 4352; i += 512) cp_async16(dsm + SM_BW + i * 16, src_w + i * 16);
        for (int i = tid; i < 528;  i += 512) cp_async16(dsm + SM_WC + i * 16, src_p + i * 16);
        CP_COMMIT();
    }

    // stage A tiles: f32 -> bf16, padded-136 layout
    const float* S0 = state + (size_t)t0 * DD;
    const float* S1 = next_state + (size_t)t0 * DD;
    #pragma unroll
    for (int q = 0; q < 8; q++) {
        int idx = tid + q * 512;
        int r = idx >> 5, c4 = idx & 31;
        float4 v0 = *reinterpret_cast<const float4*>(&S0[(size_t)r * DD + c4 * 4]);
        float4 v1 = *reinterpret_cast<const float4*>(&S1[(size_t)r * DD + c4 * 4]);
        *reinterpret_cast<__nv_bfloat162*>(&A0h[r * LDAH + c4 * 4])     = __floats2bfloat162_rn(v0.x, v0.y);
        *reinterpret_cast<__nv_bfloat162*>(&A0h[r * LDAH + c4 * 4 + 2]) = __floats2bfloat162_rn(v0.z, v0.w);
        *reinterpret_cast<__nv_bfloat162*>(&A1h[r * LDAH + c4 * 4])     = __floats2bfloat162_rn(v1.x, v1.y);
        *reinterpret_cast<__nv_bfloat162*>(&A1h[r * LDAH + c4 * 4 + 2]) = __floats2bfloat162_rn(v1.z, v1.w);
    }
    CP_WAIT0();
    __syncthreads();

    float C[2][8][4];

    // ---- ML0: critic(state); epilogue to registers, write red0 (no barrier) ----
    #pragma unroll
    for (int mt = 0; mt < 2; mt++)
        #pragma unroll
        for (int nt = 0; nt < 8; nt++)
            #pragma unroll
            for (int q = 0; q < 4; q++) C[mt][nt][q] = 0.f;
    mma_full(C, sb + SM_A0, sb + SM_BC, aOff, bOff);

    #pragma unroll
    for (int mt = 0; mt < 2; mt++) {
        float plo = 0.f, phi = 0.f;
        #pragma unroll
        for (int nt = 0; nt < 8; nt++) {
            int c0 = wn * 64 + nt * 8 + 2 * qc;
            plo = fmaf(fast_tanh(C[mt][nt][0] + cb1s[c0]),     cw2s[c0],     plo);
            plo = fmaf(fast_tanh(C[mt][nt][1] + cb1s[c0 + 1]), cw2s[c0 + 1], plo);
            phi = fmaf(fast_tanh(C[mt][nt][2] + cb1s[c0]),     cw2s[c0],     phi);
            phi = fmaf(fast_tanh(C[mt][nt][3] + cb1s[c0 + 1]), cw2s[c0 + 1], phi);
        }
        plo += __shfl_xor_sync(0xffffffffu, plo, 1);
        plo += __shfl_xor_sync(0xffffffffu, plo, 2);
        phi += __shfl_xor_sync(0xffffffffu, phi, 1);
        phi += __shfl_xor_sync(0xffffffffu, phi, 2);
        if (qc == 0) {
            red0[(wm * 32 + mt * 16 + qr) * 4 + wn]     = plo;
            red0[(wm * 32 + mt * 16 + qr + 8) * 4 + wn] = phi;
        }
    }

    // ---- ML1: critic(next_state); write red1 (no barrier) ----
    #pragma unroll
    for (int mt = 0; mt < 2; mt++)
        #pragma unroll
        for (int nt = 0; nt < 8; nt++)
            #pragma unroll
            for (int q = 0; q < 4; q++) C[mt][nt][q] = 0.f;
    mma_full(C, sb + SM_A1, sb + SM_BC, aOff, bOff);

    #pragma unroll
    for (int mt = 0; mt < 2; mt++) {
        float plo = 0.f, phi = 0.f;
        #pragma unroll
        for (int nt = 0; nt < 8; nt++) {
            int c0 = wn * 64 + nt * 8 + 2 * qc;
            plo = fmaf(fast_tanh(C[mt][nt][0] + cb1s[c0]),     cw2s[c0],     plo);
            plo = fmaf(fast_tanh(C[mt][nt][1] + cb1s[c0 + 1]), cw2s[c0 + 1], plo);
            phi = fmaf(fast_tanh(C[mt][nt][2] + cb1s[c0]),     cw2s[c0],     phi);
            phi = fmaf(fast_tanh(C[mt][nt][3] + cb1s[c0 + 1]), cw2s[c0 + 1], phi);
        }
        plo += __shfl_xor_sync(0xffffffffu, plo, 1);
        plo += __shfl_xor_sync(0xffffffffu, plo, 2);
        phi += __shfl_xor_sync(0xffffffffu, phi, 1);
        phi += __shfl_xor_sync(0xffffffffu, phi, 2);
        if (qc == 0) {
            red1[(wm * 32 + mt * 16 + qr) * 4 + wn]     = plo;
            red1[(wm * 32 + mt * 16 + qr + 8) * 4 + wn] = phi;
        }
    }

    // ---- ML2: actor layer 1 (no barrier before it) ----
    #pragma unroll
    for (int mt = 0; mt < 2; mt++)
        #pragma unroll
        for (int nt = 0; nt < 8; nt++)
            #pragma unroll
            for (int q = 0; q < 4; q++) C[mt][nt][q] = 0.f;
    mma_full(C, sb + SM_A0, sb + SM_BW, aOff, bOff);

    __syncthreads();   // everyone past ML2 (A0/A1 reads done; red0/red1 complete)

    // h = tanh(acc + b1) -> smem overlay of A0/A1
    #pragma unroll
    for (int mt = 0; mt < 2; mt++) {
        int r0 = wm * 32 + mt * 16 + qr;
        #pragma unroll
        for (int nt = 0; nt < 8; nt++) {
            int c0 = wn * 64 + nt * 8 + 2 * qc;
            *reinterpret_cast<__nv_bfloat162*>(&Hs[r0 * LDHH + c0]) =
                __floats2bfloat162_rn(fast_tanh(C[mt][nt][0] + ab1s[c0]),
                                      fast_tanh(C[mt][nt][1] + ab1s[c0 + 1]));
            *reinterpret_cast<__nv_bfloat162*>(&Hs[(r0 + 8) * LDHH + c0]) =
                __floats2bfloat162_rn(fast_tanh(C[mt][nt][2] + ab1s[c0]),
                                      fast_tanh(C[mt][nt][3] + ab1s[c0 + 1]));
        }
    }
    // v0 / delta from red0/red1
    if (tid < 128) {
        float v0 = red0[tid * 4] + red0[tid * 4 + 1] + red0[tid * 4 + 2] + red0[tid * 4 + 3] + bc2[0];
        float v1 = red1[tid * 4] + red1[tid * 4 + 1] + red1[tid * 4 + 2] + red1[tid * 4 + 3] + bc2[0];
        g_v0[t0 + tid] = v0;
        g_delta[t0 + tid] = reward[t0 + tid] + 0.99f * v1 - v0;
    }
    __syncthreads();

    // ---- phase 2 (warps 0..7): P = h @ [Wmu | Wlv], K=256 ----
    if (warp < 8) {
        float P[2][4];
        #pragma unroll
        for (int g = 0; g < 2; g++)
            #pragma unroll
            for (int q = 0; q < 4; q++) P[g][q] = 0.f;

        #pragma unroll
        for (int kb = 0; kb < 16; kb++) {
            const int kb16 = kb * 16;
            unsigned int a[4];
            const __nv_bfloat16* ap = Hs + (warp * 16 + qr) * LDHH + kb16 + 2 * qc;
            a[0] = *reinterpret_cast<const unsigned int*>(ap);
            a[1] = *reinterpret_cast<const unsigned int*>(ap + 8 * LDHH);
            a[2] = *reinterpret_cast<const unsigned int*>(ap + 8);
            a[3] = *reinterpret_cast<const unsigned int*>(ap + 8 * LDHH + 8);
            unsigned int bm[2], bl[2];
            const __nv_bfloat16* bp = WC + qr * LDHH + kb16 + 2 * qc;
            bm[0] = *reinterpret_cast<const unsigned int*>(bp);
            bm[1] = *reinterpret_cast<const unsigned int*>(bp + 8);
            bl[0] = *reinterpret_cast<const unsigned int*>(bp + 8 * LDHH);
            bl[1] = *reinterpret_cast<const unsigned int*>(bp + 8 * LDHH + 8);
            MMA_BF16(P[0], a, bm);
            MMA_BF16(P[1], a, bl);
        }

        const float HLOG2PI = 0.9189385332046727f;
        const int r0 = t0 + warp * 16 + qr;
        const int r1 = r0 + 8;
        const int a0i = 2 * qc;

        float2 act0 = *reinterpret_cast<const float2*>(&action[(size_t)r0 * AA + a0i]);
        float2 bet0 = *reinterpret_cast<const float2*>(&beta_lp[(size_t)r0 * AA + a0i]);
        float2 act1 = *reinterpret_cast<const float2*>(&action[(size_t)r1 * AA + a0i]);
        float2 bet1 = *reinterpret_cast<const float2*>(&beta_lp[(size_t)r1 * AA + a0i]);

        float mu00 = P[0][0] + bmus[a0i], mu01 = P[0][1] + bmus[a0i + 1];
        float lv00 = P[1][0] + blvs[a0i], lv01 = P[1][1] + blvs[a0i + 1];
        float mu10 = P[0][2] + bmus[a0i], mu11 = P[0][3] + bmus[a0i + 1];
        float lv10 = P[1][2] + blvs[a0i], lv11 = P[1][3] + blvs[a0i + 1];

        float d, s_lo, s_hi;
        d = act0.x - mu00; s_lo  = -0.5f * d * d * __expf(-lv00) - 0.5f * lv00 - HLOG2PI - bet0.x;
        d = act0.y - mu01; s_lo += -0.5f * d * d * __expf(-lv01) - 0.5f * lv01 - HLOG2PI - bet0.y;
        d = act1.x - mu10; s_hi  = -0.5f * d * d * __expf(-lv10) - 0.5f * lv10 - HLOG2PI - bet1.x;
        d = act1.y - mu11; s_hi += -0.5f * d * d * __expf(-lv11) - 0.5f * lv11 - HLOG2PI - bet1.y;

        s_lo += __shfl_xor_sync(0xffffffffu, s_lo, 1);
        s_lo += __shfl_xor_sync(0xffffffffu, s_lo, 2);
        s_hi += __shfl_xor_sync(0xffffffffu, s_hi, 1);
        s_hi += __shfl_xor_sync(0xffffffffu, s_hi, 2);

        if (qc == 0) {
            g_ratio[r0] = __expf(s_lo);
            g_ratio[r1] = __expf(s_hi);
        }
    }
}

// ---------------- GAE scan + advantage + partial stats ----------------
__global__ void scan_kernel()
{
    const int C = 256, W = 1024;
    const int chunk = blockIdx.x * 32 + threadIdx.x;
    const int t0 = chunk * C;
    const int start = min(TT, t0 + C + W);
    const float CFAC = (float)(0.99 * 0.95);

    float g = 0.f;
    double s = 0.0, s2 = 0.0;
    for (int t = start - 1; t >= t0; --t) {
        g = fmaf(CFAC, g, g_delta[t]);
        if (t < t0 + C) {
            float adv = g - g_v0[t];
            g_adv[t] = adv;
            s  += (double)adv;
            s2 += (double)adv * (double)adv;
        }
    }
    #pragma unroll
    for (int off = 16; off > 0; off >>= 1) {
        s  += __shfl_down_sync(0xffffffffu, s, off);
        s2 += __shfl_down_sync(0xffffffffu, s2, off);
    }
    if (threadIdx.x == 0) { g_part[blockIdx.x][0] = s; g_part[blockIdx.x][1] = s2; }
}

__global__ void stats_kernel()
{
    if (threadIdx.x == 0) {
        double S = 0.0, S2 = 0.0;
        for (int i = 0; i < 32; i++) { S += g_part[i][0]; S2 += g_part[i][1]; }
        double mean = S / (double)TT;
        double var  = (S2 - S * S / (double)TT) / (double)(TT - 1);
        g_mean  = (float)mean;
        g_isd   = (float)(1.0 / (sqrt(var) + 1e-7));
        g_closs = S2;
    }
}

__global__ void loss_kernel()
{
    const float mean = g_mean, isd = g_isd;
    double s = 0.0;
    for (int t = blockIdx.x * 256 + threadIdx.x; t < TT; t += 256 * 256) {
        float ratio = g_ratio[t];
        float ahat  = (g_adv[t] - mean) * isd;
        float rc    = fminf(fmaxf(ratio, 0.8f), 1.2f);
        s += (double)fminf(ratio * ahat, rc * ahat);
    }
    __shared__ double sh[256];
    sh[threadIdx.x] = s;
    __syncthreads();
    for (int off = 128; off > 0; off >>= 1) {
        if (threadIdx.x < off) sh[threadIdx.x] += sh[threadIdx.x + off];
        __syncthreads();
    }
    if (threadIdx.x == 0) g_lpart[blockIdx.x] = sh[0];
}

__global__ void final_kernel(float* __restrict__ out)
{
    __shared__ double sh[256];
    sh[threadIdx.x] = g_lpart[threadIdx.x];
    __syncthreads();
    for (int off = 128; off > 0; off >>= 1) {
        if (threadIdx.x < off) sh[threadIdx.x] += sh[threadIdx.x + off];
        __syncthreads();
    }
    if (threadIdx.x == 0) out[0] = (float)(g_closs - sh[0]);
}

// ---------------- launch ----------------
extern "C" void kernel_launch(void* const* d_in, const int* in_sizes, int n_in,
                              void* d_out, int out_size)
{
    const float* state      = (const float*)d_in[0];
    const float* next_state = (const float*)d_in[1];
    const float* action     = (const float*)d_in[2];
    const float* beta_lp    = (const float*)d_in[3];
    const float* reward     = (const float*)d_in[4];
    const float* W1         = (const float*)d_in[5];
    const float* b1         = (const float*)d_in[6];
    const float* Wmu        = (const float*)d_in[7];
    const float* bmu        = (const float*)d_in[8];
    const float* Wlv        = (const float*)d_in[9];
    const float* blv        = (const float*)d_in[10];
    const float* Wc1        = (const float*)d_in[11];
    const float* bc1        = (const float*)d_in[12];
    const float* Wc2        = (const float*)d_in[13];
    const float* bc2        = (const float*)d_in[14];
    float* out = (float*)d_out;

    cudaFuncSetAttribute(fwd_kernel, cudaFuncAttributeMaxDynamicSharedMemorySize, FWD_SMEM);

    prep_kernel<<<64, 256>>>(Wc1, W1, Wmu, Wlv);
    fwd_kernel<<<NBLK, 512, FWD_SMEM>>>(state, next_state, reward,
                                        bc1, Wc2, bc2, b1, bmu, blv, action, beta_lp);
    scan_kernel<<<32, 32>>>();
    stats_kernel<<<1, 32>>>();
    loss_kernel<<<256, 256>>>();
    final_kernel<<<1, 256>>>(out);
}

// round 13
// speedup vs baseline: 6.3678x; 1.0185x over previous
#include <cuda_runtime.h>
#include <cuda_bf16.h>
#include <cstdint>
#include <math.h>

#define TT 262144
#define DD 128
#define HH 256
#define AA 8
#define NB2 (TT / 64)      // 4096 blocks of 64 rows per flavor... (2048 critic + 2048 actor over 128-row pairs)

// ---------------- scratch (device globals; no allocation allowed) ----------------
__device__ float  g_v0[TT];
__device__ float  g_delta[TT];
__device__ float  g_adv[TT];
__device__ float  g_ratio[TT];
__device__ double g_part[32][2];
__device__ float  g_mean, g_isd;
__device__ double g_closs;
__device__ double g_lpart[256];

// pre-converted bf16 weights, [n][k] layout, pitch 136 (main) / 264 (heads)
__device__ __align__(16) __nv_bfloat16 g_Bc[256 * 136];   // Wc1
__device__ __align__(16) __nv_bfloat16 g_Bw[256 * 136];   // W1
__device__ __align__(16) __nv_bfloat16 g_Bp[16 * 264];    // [Wmu | Wlv]

__device__ __forceinline__ float fast_tanh(float x) {
    float y;
    asm("tanh.approx.f32 %0, %1;" : "=f"(y) : "f"(x));
    return y;
}
__device__ __forceinline__ unsigned int smem_u32(const void* p) {
    unsigned int a;
    asm("{ .reg .u64 t; cvta.to.shared.u64 t, %1; cvt.u32.u64 %0, t; }" : "=r"(a) : "l"(p));
    return a;
}

#define MMA_BF16(d, a, b) \
    asm volatile("mma.sync.aligned.m16n8k16.row.col.f32.bf16.bf16.f32 " \
                 "{%0,%1,%2,%3}, {%4,%5,%6,%7}, {%8,%9}, {%0,%1,%2,%3};" \
                 : "+f"((d)[0]), "+f"((d)[1]), "+f"((d)[2]), "+f"((d)[3]) \
                 : "r"((a)[0]), "r"((a)[1]), "r"((a)[2]), "r"((a)[3]), \
                   "r"((b)[0]), "r"((b)[1]))

#define LDSM_X4(r, addr) \
    asm volatile("ldmatrix.sync.aligned.m8n8.x4.shared.b16 {%0,%1,%2,%3}, [%4];" \
        : "=r"((r)[0]), "=r"((r)[1]), "=r"((r)[2]), "=r"((r)[3]) : "r"(addr))

__device__ __forceinline__ void cp_async16(void* dst, const void* src) {
    unsigned int s = (unsigned int)__cvta_generic_to_shared(dst);
    asm volatile("cp.async.cg.shared.global [%0], [%1], 16;\n" :: "r"(s), "l"(src));
}
#define CP_COMMIT() asm volatile("cp.async.commit_group;\n" ::: "memory")
#define CP_WAIT0()  asm volatile("cp.async.wait_group 0;\n" ::: "memory")

// ---------------- smem layout (bytes), per 64-row CTA ----------------
#define LDAH 136     // halves; 272B pitch (odd 16B units -> LDSM conflict-free)
#define LDHH 264
#define SM_A0   0                    // 64 x 136 bf16 = 17408
#define SM_A1   17408                // critic: A1.  actor: WC (8448)
#define SM_B    34816                // 256 x 136 bf16 = 69632 (BC or BW; actor H overlays)
#define SM_RED0 104448               // 64*4*4 = 1024
#define SM_RED1 105472               // 1024
#define FWD_SMEM 106496

// ---------------- prep: convert weights to bf16 [n][k] ----------------
__global__ void prep_kernel(const float* __restrict__ Wc1, const float* __restrict__ W1,
                            const float* __restrict__ Wmu, const float* __restrict__ Wlv)
{
    int g = blockIdx.x * 256 + threadIdx.x;                 // 16384 threads
    for (int i = g; i < 128 * 256; i += 16384) {
        int k = i >> 8, n = i & 255;
        g_Bc[n * LDAH + k] = __float2bfloat16(Wc1[i]);
        g_Bw[n * LDAH + k] = __float2bfloat16(W1[i]);
    }
    for (int i = g; i < 256 * 16; i += 16384) {
        int k = i >> 4, n = i & 15;
        float v = (n < 8) ? Wmu[k * 8 + n] : Wlv[k * 8 + (n - 8)];
        g_Bp[n * LDHH + k] = __float2bfloat16(v);
    }
}

// full-K (128) bf16 GEMM via ldmatrix fragments; warp tile 32x64 over a 64-row A tile
__device__ __forceinline__ void mma_full(
    float C[2][8][4], unsigned int aRegion, unsigned int bRegion,
    const unsigned int aOff[2], const unsigned int bOff[4])
{
    #pragma unroll
    for (int kb = 0; kb < 8; kb++) {
        const unsigned int koff = kb * 32;
        unsigned int a[2][4];
        LDSM_X4(a[0], aRegion + aOff[0] + koff);
        LDSM_X4(a[1], aRegion + aOff[1] + koff);
        unsigned int bb[4][4];
        #pragma unroll
        for (int p = 0; p < 4; p++) LDSM_X4(bb[p], bRegion + bOff[p] + koff);
        #pragma unroll
        for (int mt = 0; mt < 2; mt++)
            #pragma unroll
            for (int p = 0; p < 4; p++) {
                MMA_BF16(C[mt][2 * p],     a[mt], bb[p]);
                MMA_BF16(C[mt][2 * p + 1], a[mt], (bb[p] + 2));
            }
    }
}

// stage a 64-row f32 matrix as bf16 into smem (pitch 136), 256 threads
__device__ __forceinline__ void stage_A(__nv_bfloat16* dst, const float* __restrict__ src, int tid)
{
    #pragma unroll
    for (int q = 0; q < 8; q++) {
        int idx = tid + q * 256;             // 2048 float4
        int r = idx >> 5, c4 = idx & 31;
        float4 v = *reinterpret_cast<const float4*>(&src[(size_t)r * DD + c4 * 4]);
        *reinterpret_cast<__nv_bfloat162*>(&dst[r * LDAH + c4 * 4])     = __floats2bfloat162_rn(v.x, v.y);
        *reinterpret_cast<__nv_bfloat162*>(&dst[r * LDAH + c4 * 4 + 2]) = __floats2bfloat162_rn(v.z, v.w);
    }
}

// ---------------- fused forward: 2048 critic blocks + 2048 actor blocks, 64 rows each... x2 rows ----------------
__global__ __launch_bounds__(256, 2) void fwd_kernel(
    const float* __restrict__ state, const float* __restrict__ next_state,
    const float* __restrict__ reward,
    const float* __restrict__ bc1, const float* __restrict__ Wc2, const float* __restrict__ bc2,
    const float* __restrict__ b1,  const float* __restrict__ bmu, const float* __restrict__ blv,
    const float* __restrict__ action, const float* __restrict__ beta_lp)
{
    extern __shared__ unsigned char dsm[];
    __shared__ float bias1[256], w2s[256];    // critic: bc1/Wc2. actor: b1/(unused)
    __shared__ float bmus[8], blvs[8];

    const int tid = threadIdx.x;
    const int lane = tid & 31, warp = tid >> 5;
    const int wm = warp >> 2, wn = warp & 3;
    const int qr = lane >> 2, qc = lane & 3;
    const int lrow = lane & 7, lmat = lane >> 3;
    const bool is_critic = blockIdx.x < (TT / 64);
    const int t0 = (is_critic ? blockIdx.x : (blockIdx.x - TT / 64)) * 64;

    const unsigned int sb = smem_u32(dsm);
    __nv_bfloat16* A0h = reinterpret_cast<__nv_bfloat16*>(dsm + SM_A0);
    __nv_bfloat16* A1h = reinterpret_cast<__nv_bfloat16*>(dsm + SM_A1);
    __nv_bfloat16* WC  = reinterpret_cast<__nv_bfloat16*>(dsm + SM_A1);   // actor overlay
    __nv_bfloat16* Hs  = reinterpret_cast<__nv_bfloat16*>(dsm + SM_B);    // actor h overlay of B
    float* red0 = reinterpret_cast<float*>(dsm + SM_RED0);
    float* red1 = reinterpret_cast<float*>(dsm + SM_RED1);

    // per-lane ldmatrix fragment offsets (bytes)
    unsigned int aOff[2], bOff[4];
    #pragma unroll
    for (int mt = 0; mt < 2; mt++)
        aOff[mt] = (unsigned int)((wm * 32 + mt * 16 + (lmat & 1) * 8 + lrow) * 272 + ((lmat >> 1) * 8) * 2);
    #pragma unroll
    for (int p = 0; p < 4; p++)
        bOff[p] = (unsigned int)((wn * 64 + p * 16 + (lmat >> 1) * 8 + lrow) * 272 + ((lmat & 1) * 8) * 2);

    float C[2][8][4];

    if (is_critic) {
        if (tid < 256) { bias1[tid] = bc1[tid]; w2s[tid] = Wc2[tid]; }
        // stage Wc1 (identity bf16 copy) + A tiles
        const unsigned char* src_b = reinterpret_cast<const unsigned char*>(g_Bc);
        for (int i = tid; i < 4352; i += 256) cp_async16(dsm + SM_B + i * 16, src_b + i * 16);
        CP_COMMIT();
        stage_A(A0h, state + (size_t)t0 * DD, tid);
        stage_A(A1h, next_state + (size_t)t0 * DD, tid);
        CP_WAIT0();
        __syncthreads();

        // GEMM0: critic(state)
        #pragma unroll
        for (int mt = 0; mt < 2; mt++)
            #pragma unroll
            for (int nt = 0; nt < 8; nt++)
                #pragma unroll
                for (int q = 0; q < 4; q++) C[mt][nt][q] = 0.f;
        mma_full(C, sb + SM_A0, sb + SM_B, aOff, bOff);

        #pragma unroll
        for (int mt = 0; mt < 2; mt++) {
            float plo = 0.f, phi = 0.f;
            #pragma unroll
            for (int nt = 0; nt < 8; nt++) {
                int c0 = wn * 64 + nt * 8 + 2 * qc;
                plo = fmaf(fast_tanh(C[mt][nt][0] + bias1[c0]),     w2s[c0],     plo);
                plo = fmaf(fast_tanh(C[mt][nt][1] + bias1[c0 + 1]), w2s[c0 + 1], plo);
                phi = fmaf(fast_tanh(C[mt][nt][2] + bias1[c0]),     w2s[c0],     phi);
                phi = fmaf(fast_tanh(C[mt][nt][3] + bias1[c0 + 1]), w2s[c0 + 1], phi);
            }
            plo += __shfl_xor_sync(0xffffffffu, plo, 1);
            plo += __shfl_xor_sync(0xffffffffu, plo, 2);
            phi += __shfl_xor_sync(0xffffffffu, phi, 1);
            phi += __shfl_xor_sync(0xffffffffu, phi, 2);
            if (qc == 0) {
                red0[(wm * 32 + mt * 16 + qr) * 4 + wn]     = plo;
                red0[(wm * 32 + mt * 16 + qr + 8) * 4 + wn] = phi;
            }
        }

        // GEMM1: critic(next_state)
        #pragma unroll
        for (int mt = 0; mt < 2; mt++)
            #pragma unroll
            for (int nt = 0; nt < 8; nt++)
                #pragma unroll
                for (int q = 0; q < 4; q++) C[mt][nt][q] = 0.f;
        mma_full(C, sb + SM_A1, sb + SM_B, aOff, bOff);

        #pragma unroll
        for (int mt = 0; mt < 2; mt++) {
            float plo = 0.f, phi = 0.f;
            #pragma unroll
            for (int nt = 0; nt < 8; nt++) {
                int c0 = wn * 64 + nt * 8 + 2 * qc;
                plo = fmaf(fast_tanh(C[mt][nt][0] + bias1[c0]),     w2s[c0],     plo);
                plo = fmaf(fast_tanh(C[mt][nt][1] + bias1[c0 + 1]), w2s[c0 + 1], plo);
                phi = fmaf(fast_tanh(C[mt][nt][2] + bias1[c0]),     w2s[c0],     phi);
                phi = fmaf(fast_tanh(C[mt][nt][3] + bias1[c0 + 1]), w2s[c0 + 1], phi);
            }
            plo += __shfl_xor_sync(0xffffffffu, plo, 1);
            plo += __shfl_xor_sync(0xffffffffu, plo, 2);
            phi += __shfl_xor_sync(0xffffffffu, phi, 1);
            phi += __shfl_xor_sync(0xffffffffu, phi, 2);
            if (qc == 0) {
                red1[(wm * 32 + mt * 16 + qr) * 4 + wn]     = plo;
                red1[(wm * 32 + mt * 16 + qr + 8) * 4 + wn] = phi;
            }
        }
        __syncthreads();
        if (tid < 64) {
            float v0 = red0[tid * 4] + red0[tid * 4 + 1] + red0[tid * 4 + 2] + red0[tid * 4 + 3] + bc2[0];
            float v1 = red1[tid * 4] + red1[tid * 4 + 1] + red1[tid * 4 + 2] + red1[tid * 4 + 3] + bc2[0];
            g_v0[t0 + tid] = v0;
            g_delta[t0 + tid] = reward[t0 + tid] + 0.99f * v1 - v0;
        }
    } else {
        // ---------------- actor block ----------------
        if (tid < 256) bias1[tid] = b1[tid];
        if (tid < 8)   { bmus[tid] = bmu[tid]; blvs[tid] = blv[tid]; }
        const unsigned char* src_b = reinterpret_cast<const unsigned char*>(g_Bw);
        const unsigned char* src_p = reinterpret_cast<const unsigned char*>(g_Bp);
        for (int i = tid; i < 4352; i += 256) cp_async16(dsm + SM_B + i * 16, src_b + i * 16);
        for (int i = tid; i < 528;  i += 256) cp_async16(dsm + SM_A1 + i * 16, src_p + i * 16);
        CP_COMMIT();
        stage_A(A0h, state + (size_t)t0 * DD, tid);
        CP_WAIT0();
        __syncthreads();

        #pragma unroll
        for (int mt = 0; mt < 2; mt++)
            #pragma unroll
            for (int nt = 0; nt < 8; nt++)
                #pragma unroll
                for (int q = 0; q < 4; q++) C[mt][nt][q] = 0.f;
        mma_full(C, sb + SM_A0, sb + SM_B, aOff, bOff);

        __syncthreads();   // everyone done reading BW before H overlay

        // h = tanh(acc + b1) -> Hs (overlay of BW), pitch 264
        #pragma unroll
        for (int mt = 0; mt < 2; mt++) {
            int r0 = wm * 32 + mt * 16 + qr;
            #pragma unroll
            for (int nt = 0; nt < 8; nt++) {
                int c0 = wn * 64 + nt * 8 + 2 * qc;
                *reinterpret_cast<__nv_bfloat162*>(&Hs[r0 * LDHH + c0]) =
                    __floats2bfloat162_rn(fast_tanh(C[mt][nt][0] + bias1[c0]),
                                          fast_tanh(C[mt][nt][1] + bias1[c0 + 1]));
                *reinterpret_cast<__nv_bfloat162*>(&Hs[(r0 + 8) * LDHH + c0]) =
                    __floats2bfloat162_rn(fast_tanh(C[mt][nt][2] + bias1[c0]),
                                          fast_tanh(C[mt][nt][3] + bias1[c0 + 1]));
            }
        }
        __syncthreads();

        // phase 2 (warps 0..3): P = h @ [Wmu | Wlv], K=256
        if (warp < 4) {
            float P[2][4];
            #pragma unroll
            for (int g = 0; g < 2; g++)
                #pragma unroll
                for (int q = 0; q < 4; q++) P[g][q] = 0.f;

            #pragma unroll
            for (int kb = 0; kb < 16; kb++) {
                const int kb16 = kb * 16;
                unsigned int a[4];
                const __nv_bfloat16* ap = Hs + (warp * 16 + qr) * LDHH + kb16 + 2 * qc;
                a[0] = *reinterpret_cast<const unsigned int*>(ap);
                a[1] = *reinterpret_cast<const unsigned int*>(ap + 8 * LDHH);
                a[2] = *reinterpret_cast<const unsigned int*>(ap + 8);
                a[3] = *reinterpret_cast<const unsigned int*>(ap + 8 * LDHH + 8);
                unsigned int bm[2], bl[2];
                const __nv_bfloat16* bp = WC + qr * LDHH + kb16 + 2 * qc;
                bm[0] = *reinterpret_cast<const unsigned int*>(bp);
                bm[1] = *reinterpret_cast<const unsigned int*>(bp + 8);
                bl[0] = *reinterpret_cast<const unsigned int*>(bp + 8 * LDHH);
                bl[1] = *reinterpret_cast<const unsigned int*>(bp + 8 * LDHH + 8);
                MMA_BF16(P[0], a, bm);
                MMA_BF16(P[1], a, bl);
            }

            const float HLOG2PI = 0.9189385332046727f;
            const int r0 = t0 + warp * 16 + qr;
            const int r1 = r0 + 8;
            const int a0i = 2 * qc;

            float2 act0 = *reinterpret_cast<const float2*>(&action[(size_t)r0 * AA + a0i]);
            float2 bet0 = *reinterpret_cast<const float2*>(&beta_lp[(size_t)r0 * AA + a0i]);
            float2 act1 = *reinterpret_cast<const float2*>(&action[(size_t)r1 * AA + a0i]);
            float2 bet1 = *reinterpret_cast<const float2*>(&beta_lp[(size_t)r1 * AA + a0i]);

            float mu00 = P[0][0] + bmus[a0i], mu01 = P[0][1] + bmus[a0i + 1];
            float lv00 = P[1][0] + blvs[a0i], lv01 = P[1][1] + blvs[a0i + 1];
            float mu10 = P[0][2] + bmus[a0i], mu11 = P[0][3] + bmus[a0i + 1];
            float lv10 = P[1][2] + blvs[a0i], lv11 = P[1][3] + blvs[a0i + 1];

            float d, s_lo, s_hi;
            d = act0.x - mu00; s_lo  = -0.5f * d * d * __expf(-lv00) - 0.5f * lv00 - HLOG2PI - bet0.x;
            d = act0.y - mu01; s_lo += -0.5f * d * d * __expf(-lv01) - 0.5f * lv01 - HLOG2PI - bet0.y;
            d = act1.x - mu10; s_hi  = -0.5f * d * d * __expf(-lv10) - 0.5f * lv10 - HLOG2PI - bet1.x;
            d = act1.y - mu11; s_hi += -0.5f * d * d * __expf(-lv11) - 0.5f * lv11 - HLOG2PI - bet1.y;

            s_lo += __shfl_xor_sync(0xffffffffu, s_lo, 1);
            s_lo += __shfl_xor_sync(0xffffffffu, s_lo, 2);
            s_hi += __shfl_xor_sync(0xffffffffu, s_hi, 1);
            s_hi += __shfl_xor_sync(0xffffffffu, s_hi, 2);

            if (qc == 0) {
                g_ratio[r0] = __expf(s_lo);
                g_ratio[r1] = __expf(s_hi);
            }
        }
    }
}

// ---------------- GAE scan + advantage + partial stats ----------------
__global__ void scan_kernel()
{
    const int C = 256, W = 1024;
    const int chunk = blockIdx.x * 32 + threadIdx.x;
    const int t0 = chunk * C;
    const int start = min(TT, t0 + C + W);
    const float CFAC = (float)(0.99 * 0.95);

    float g = 0.f;
    double s = 0.0, s2 = 0.0;
    for (int t = start - 1; t >= t0; --t) {
        g = fmaf(CFAC, g, g_delta[t]);
        if (t < t0 + C) {
            float adv = g - g_v0[t];
            g_adv[t] = adv;
            s  += (double)adv;
            s2 += (double)adv * (double)adv;
        }
    }
    #pragma unroll
    for (int off = 16; off > 0; off >>= 1) {
        s  += __shfl_down_sync(0xffffffffu, s, off);
        s2 += __shfl_down_sync(0xffffffffu, s2, off);
    }
    if (threadIdx.x == 0) { g_part[blockIdx.x][0] = s; g_part[blockIdx.x][1] = s2; }
}

__global__ void stats_kernel()
{
    if (threadIdx.x == 0) {
        double S = 0.0, S2 = 0.0;
        for (int i = 0; i < 32; i++) { S += g_part[i][0]; S2 += g_part[i][1]; }
        double mean = S / (double)TT;
        double var  = (S2 - S * S / (double)TT) / (double)(TT - 1);
        g_mean  = (float)mean;
        g_isd   = (float)(1.0 / (sqrt(var) + 1e-7));
        g_closs = S2;
    }
}

__global__ void loss_kernel()
{
    const float mean = g_mean, isd = g_isd;
    double s = 0.0;
    for (int t = blockIdx.x * 256 + threadIdx.x; t < TT; t += 256 * 256) {
        float ratio = g_ratio[t];
        float ahat  = (g_adv[t] - mean) * isd;
        float rc    = fminf(fmaxf(ratio, 0.8f), 1.2f);
        s += (double)fminf(ratio * ahat, rc * ahat);
    }
    __shared__ double sh[256];
    sh[threadIdx.x] = s;
    __syncthreads();
    for (int off = 128; off > 0; off >>= 1) {
        if (threadIdx.x < off) sh[threadIdx.x] += sh[threadIdx.x + off];
        __syncthreads();
    }
    if (threadIdx.x == 0) g_lpart[blockIdx.x] = sh[0];
}

__global__ void final_kernel(float* __restrict__ out)
{
    __shared__ double sh[256];
    sh[threadIdx.x] = g_lpart[threadIdx.x];
    __syncthreads();
    for (int off = 128; off > 0; off >>= 1) {
        if (threadIdx.x < off) sh[threadIdx.x] += sh[threadIdx.x + off];
        __syncthreads();
    }
    if (threadIdx.x == 0) out[0] = (float)(g_closs - sh[0]);
}

// ---------------- launch ----------------
extern "C" void kernel_launch(void* const* d_in, const int* in_sizes, int n_in,
                              void* d_out, int out_size)
{
    const float* state      = (const float*)d_in[0];
    const float* next_state = (const float*)d_in[1];
    const float* action     = (const float*)d_in[2];
    const float* beta_lp    = (const float*)d_in[3];
    const float* reward     = (const float*)d_in[4];
    const float* W1         = (const float*)d_in[5];
    const float* b1         = (const float*)d_in[6];
    const float* Wmu        = (const float*)d_in[7];
    const float* bmu        = (const float*)d_in[8];
    const float* Wlv        = (const float*)d_in[9];
    const float* blv        = (const float*)d_in[10];
    const float* Wc1        = (const float*)d_in[11];
    const float* bc1        = (const float*)d_in[12];
    const float* Wc2        = (const float*)d_in[13];
    const float* bc2        = (const float*)d_in[14];
    float* out = (float*)d_out;

    cudaFuncSetAttribute(fwd_kernel, cudaFuncAttributeMaxDynamicSharedMemorySize, FWD_SMEM);

    prep_kernel<<<64, 256>>>(Wc1, W1, Wmu, Wlv);
    fwd_kernel<<<2 * (TT / 64), 256, FWD_SMEM>>>(state, next_state, reward,
                                                 bc1, Wc2, bc2, b1, bmu, blv, action, beta_lp);
    scan_kernel<<<32, 32>>>();
    stats_kernel<<<1, 32>>>();
    loss_kernel<<<256, 256>>>();
    final_kernel<<<1, 256>>>(out);
}

// round 15
// speedup vs baseline: 6.4401x; 1.0114x over previous
#include <cuda_runtime.h>
#include <cuda_bf16.h>
#include <cuda_fp8.h>
#include <cstdint>
#include <math.h>

#define TT 262144
#define DD 128
#define HH 256
#define AA 8

// ---------------- scratch (device globals; no allocation allowed) ----------------
__device__ float  g_v0[TT];
__device__ float  g_delta[TT];
__device__ float  g_adv[TT];
__device__ float  g_ratio[TT];
__device__ double g_part[32][2];
__device__ float  g_mean, g_isd;
__device__ double g_closs;
__device__ double g_lpart[256];

// pre-converted weights: fp8 e4m3 [n][k] pitch 144 (main GEMMs), bf16 [n][k] pitch 264 (heads)
__device__ __align__(16) unsigned char  g_Bc8[256 * 144];   // Wc1
__device__ __align__(16) unsigned char  g_Bw8[256 * 144];   // W1
__device__ __align__(16) __nv_bfloat16  g_Bp[16 * 264];     // [Wmu | Wlv]

__device__ __forceinline__ float fast_tanh(float x) {
    float y;
    asm("tanh.approx.f32 %0, %1;" : "=f"(y) : "f"(x));
    return y;
}
__device__ __forceinline__ unsigned int smem_u32(const void* p) {
    unsigned int a;
    asm("{ .reg .u64 t; cvta.to.shared.u64 t, %1; cvt.u32.u64 %0, t; }" : "=r"(a) : "l"(p));
    return a;
}

#define MMA_FP8(d, a, b) \
    asm volatile("mma.sync.aligned.m16n8k32.row.col.f32.e4m3.e4m3.f32 " \
                 "{%0,%1,%2,%3}, {%4,%5,%6,%7}, {%8,%9}, {%0,%1,%2,%3};" \
                 : "+f"((d)[0]), "+f"((d)[1]), "+f"((d)[2]), "+f"((d)[3]) \
                 : "r"((a)[0]), "r"((a)[1]), "r"((a)[2]), "r"((a)[3]), \
                   "r"((b)[0]), "r"((b)[1]))

#define MMA_BF16(d, a, b) \
    asm volatile("mma.sync.aligned.m16n8k16.row.col.f32.bf16.bf16.f32 " \
                 "{%0,%1,%2,%3}, {%4,%5,%6,%7}, {%8,%9}, {%0,%1,%2,%3};" \
                 : "+f"((d)[0]), "+f"((d)[1]), "+f"((d)[2]), "+f"((d)[3]) \
                 : "r"((a)[0]), "r"((a)[1]), "r"((a)[2]), "r"((a)[3]), \
                   "r"((b)[0]), "r"((b)[1]))

#define LDSM_X4(r, addr) \
    asm volatile("ldmatrix.sync.aligned.m8n8.x4.shared.b16 {%0,%1,%2,%3}, [%4];" \
        : "=r"((r)[0]), "=r"((r)[1]), "=r"((r)[2]), "=r"((r)[3]) : "r"(addr))

__device__ __forceinline__ void cp_async16(void* dst, const void* src) {
    unsigned int s = (unsigned int)__cvta_generic_to_shared(dst);
    asm volatile("cp.async.cg.shared.global [%0], [%1], 16;\n" :: "r"(s), "l"(src));
}
#define CP_COMMIT() asm volatile("cp.async.commit_group;\n" ::: "memory")
#define CP_WAIT0()  asm volatile("cp.async.wait_group 0;\n" ::: "memory")

// ---------------- smem layout (bytes), per 64-row CTA ----------------
// fp8 pitch 144B (9 x 16B, odd -> LDSM conflict-free); bf16 head pitch 264 halves
#define LP8  144
#define LDHH 264
#define SM_A0   0                    // 64 x 144 = 9216
#define SM_A1   9216                 // critic: A1 (9216). actor: WC bf16 (8448)
#define SM_B    18432                // 256 x 144 = 36864 (BC or BW; actor Hs overlays)
#define SM_RED0 55296                // 1024
#define SM_RED1 56320                // 1024
#define FWD_SMEM 57344

// ---------------- prep: convert weights ----------------
__global__ void prep_kernel(const float* __restrict__ Wc1, const float* __restrict__ W1,
                            const float* __restrict__ Wmu, const float* __restrict__ Wlv)
{
    int g = blockIdx.x * 256 + threadIdx.x;                 // 16384 threads
    for (int i = g; i < 128 * 256; i += 16384) {
        int k = i >> 8, n = i & 255;
        g_Bc8[n * LP8 + k] = __nv_fp8_e4m3(Wc1[i]).__x;
        g_Bw8[n * LP8 + k] = __nv_fp8_e4m3(W1[i]).__x;
    }
    for (int i = g; i < 256 * 16; i += 16384) {
        int k = i >> 4, n = i & 15;
        float v = (n < 8) ? Wmu[k * 8 + n] : Wlv[k * 8 + (n - 8)];
        g_Bp[n * LDHH + k] = __float2bfloat16(v);
    }
}

// full-K(128) fp8 GEMM via ldmatrix; warp tile 32x64 over a 64-row A tile
__device__ __forceinline__ void mma_full8(
    float C[2][8][4], unsigned int aRegion, unsigned int bRegion,
    const unsigned int aOff[2], const unsigned int bOff[4])
{
    #pragma unroll
    for (int kb = 0; kb < 4; kb++) {
        const unsigned int koff = kb * 32;      // 32 e4m3 = 32 bytes
        unsigned int a[2][4];
        LDSM_X4(a[0], aRegion + aOff[0] + koff);
        LDSM_X4(a[1], aRegion + aOff[1] + koff);
        unsigned int bb[4][4];
        #pragma unroll
        for (int p = 0; p < 4; p++) LDSM_X4(bb[p], bRegion + bOff[p] + koff);
        #pragma unroll
        for (int mt = 0; mt < 2; mt++)
            #pragma unroll
            for (int p = 0; p < 4; p++) {
                MMA_FP8(C[mt][2 * p],     a[mt], bb[p]);
                MMA_FP8(C[mt][2 * p + 1], a[mt], (bb[p] + 2));
            }
    }
}

// stage a 64-row f32 matrix as e4m3 into smem (pitch 144B), 256 threads
__device__ __forceinline__ void stage_A8(unsigned char* dst, const float* __restrict__ src, int tid)
{
    #pragma unroll
    for (int q = 0; q < 2; q++) {
        int s = tid + q * 256;                 // 512 segments of 16 floats
        int r = s >> 3, seg = s & 7;
        const float4* p = reinterpret_cast<const float4*>(src + (size_t)r * DD + seg * 16);
        float4 v0 = p[0], v1 = p[1], v2 = p[2], v3 = p[3];
        __nv_fp8x4_e4m3 b0(v0), b1(v1), b2(v2), b3(v3);
        uint4 out = make_uint4((unsigned int)b0.__x, (unsigned int)b1.__x,
                               (unsigned int)b2.__x, (unsigned int)b3.__x);
        *reinterpret_cast<uint4*>(dst + r * LP8 + seg * 16) = out;
    }
}

// ---------------- fused forward: 4096 critic blocks + 4096 actor blocks, 64 rows ----------------
__global__ __launch_bounds__(256, 2) void fwd_kernel(
    const float* __restrict__ state, const float* __restrict__ next_state,
    const float* __restrict__ reward,
    const float* __restrict__ bc1, const float* __restrict__ Wc2, const float* __restrict__ bc2,
    const float* __restrict__ b1,  const float* __restrict__ bmu, const float* __restrict__ blv,
    const float* __restrict__ action, const float* __restrict__ beta_lp)
{
    extern __shared__ unsigned char dsm[];
    __shared__ float bias1[256], w2s[256];
    __shared__ float bmus[8], blvs[8];

    const int tid = threadIdx.x;
    const int lane = tid & 31, warp = tid >> 5;
    const int wm = warp >> 2, wn = warp & 3;
    const int qr = lane >> 2, qc = lane & 3;
    const int lrow = lane & 7, lmat = lane >> 3;
    const bool is_critic = blockIdx.x < (TT / 64);
    const int t0 = (is_critic ? blockIdx.x : (blockIdx.x - TT / 64)) * 64;

    const unsigned int sb = smem_u32(dsm);
    unsigned char* A0b = dsm + SM_A0;
    unsigned char* A1b = dsm + SM_A1;
    __nv_bfloat16* WC  = reinterpret_cast<__nv_bfloat16*>(dsm + SM_A1);   // actor overlay
    __nv_bfloat16* Hs  = reinterpret_cast<__nv_bfloat16*>(dsm + SM_B);    // actor h overlay of B
    float* red0 = reinterpret_cast<float*>(dsm + SM_RED0);
    float* red1 = reinterpret_cast<float*>(dsm + SM_RED1);

    // per-lane ldmatrix fragment offsets (bytes, pitch 144)
    unsigned int aOff[2], bOff[4];
    #pragma unroll
    for (int mt = 0; mt < 2; mt++)
        aOff[mt] = (unsigned int)((wm * 32 + mt * 16 + (lmat & 1) * 8 + lrow) * LP8 + (lmat >> 1) * 16);
    #pragma unroll
    for (int p = 0; p < 4; p++)
        bOff[p] = (unsigned int)((wn * 64 + p * 16 + (lmat >> 1) * 8 + lrow) * LP8 + (lmat & 1) * 16);

    float C[2][8][4];

    if (is_critic) {
        if (tid < 256) { bias1[tid] = bc1[tid]; w2s[tid] = Wc2[tid]; }
        for (int i = tid; i < 2304; i += 256) cp_async16(dsm + SM_B + i * 16, g_Bc8 + i * 16);
        CP_COMMIT();
        stage_A8(A0b, state + (size_t)t0 * DD, tid);
        stage_A8(A1b, next_state + (size_t)t0 * DD, tid);
        CP_WAIT0();
        __syncthreads();

        // GEMM0: critic(state)
        #pragma unroll
        for (int mt = 0; mt < 2; mt++)
            #pragma unroll
            for (int nt = 0; nt < 8; nt++)
                #pragma unroll
                for (int q = 0; q < 4; q++) C[mt][nt][q] = 0.f;
        mma_full8(C, sb + SM_A0, sb + SM_B, aOff, bOff);

        #pragma unroll
        for (int mt = 0; mt < 2; mt++) {
            float plo = 0.f, phi = 0.f;
            #pragma unroll
            for (int nt = 0; nt < 8; nt++) {
                int c0 = wn * 64 + nt * 8 + 2 * qc;
                plo = fmaf(fast_tanh(C[mt][nt][0] + bias1[c0]),     w2s[c0],     plo);
                plo = fmaf(fast_tanh(C[mt][nt][1] + bias1[c0 + 1]), w2s[c0 + 1], plo);
                phi = fmaf(fast_tanh(C[mt][nt][2] + bias1[c0]),     w2s[c0],     phi);
                phi = fmaf(fast_tanh(C[mt][nt][3] + bias1[c0 + 1]), w2s[c0 + 1], phi);
            }
            plo += __shfl_xor_sync(0xffffffffu, plo, 1);
            plo += __shfl_xor_sync(0xffffffffu, plo, 2);
            phi += __shfl_xor_sync(0xffffffffu, phi, 1);
            phi += __shfl_xor_sync(0xffffffffu, phi, 2);
            if (qc == 0) {
                red0[(wm * 32 + mt * 16 + qr) * 4 + wn]     = plo;
                red0[(wm * 32 + mt * 16 + qr + 8) * 4 + wn] = phi;
            }
        }

        // GEMM1: critic(next_state)
        #pragma unroll
        for (int mt = 0; mt < 2; mt++)
            #pragma unroll
            for (int nt = 0; nt < 8; nt++)
                #pragma unroll
                for (int q = 0; q < 4; q++) C[mt][nt][q] = 0.f;
        mma_full8(C, sb + SM_A1, sb + SM_B, aOff, bOff);

        #pragma unroll
        for (int mt = 0; mt < 2; mt++) {
            float plo = 0.f, phi = 0.f;
            #pragma unroll
            for (int nt = 0; nt < 8; nt++) {
                int c0 = wn * 64 + nt * 8 + 2 * qc;
                plo = fmaf(fast_tanh(C[mt][nt][0] + bias1[c0]),     w2s[c0],     plo);
                plo = fmaf(fast_tanh(C[mt][nt][1] + bias1[c0 + 1]), w2s[c0 + 1], plo);
                phi = fmaf(fast_tanh(C[mt][nt][2] + bias1[c0]),     w2s[c0],     phi);
                phi = fmaf(fast_tanh(C[mt][nt][3] + bias1[c0 + 1]), w2s[c0 + 1], phi);
            }
            plo += __shfl_xor_sync(0xffffffffu, plo, 1);
            plo += __shfl_xor_sync(0xffffffffu, plo, 2);
            phi += __shfl_xor_sync(0xffffffffu, phi, 1);
            phi += __shfl_xor_sync(0xffffffffu, phi, 2);
            if (qc == 0) {
                red1[(wm * 32 + mt * 16 + qr) * 4 + wn]     = plo;
                red1[(wm * 32 + mt * 16 + qr + 8) * 4 + wn] = phi;
            }
        }
        __syncthreads();
        if (tid < 64) {
            float v0 = red0[tid * 4] + red0[tid * 4 + 1] + red0[tid * 4 + 2] + red0[tid * 4 + 3] + bc2[0];
            float v1 = red1[tid * 4] + red1[tid * 4 + 1] + red1[tid * 4 + 2] + red1[tid * 4 + 3] + bc2[0];
            g_v0[t0 + tid] = v0;
            g_delta[t0 + tid] = reward[t0 + tid] + 0.99f * v1 - v0;
        }
    } else {
        // ---------------- actor block ----------------
        if (tid < 256) bias1[tid] = b1[tid];
        if (tid < 8)   { bmus[tid] = bmu[tid]; blvs[tid] = blv[tid]; }
        const unsigned char* src_p = reinterpret_cast<const unsigned char*>(g_Bp);
        for (int i = tid; i < 2304; i += 256) cp_async16(dsm + SM_B + i * 16, g_Bw8 + i * 16);
        for (int i = tid; i < 528;  i += 256) cp_async16(dsm + SM_A1 + i * 16, src_p + i * 16);
        CP_COMMIT();
        stage_A8(A0b, state + (size_t)t0 * DD, tid);
        CP_WAIT0();
        __syncthreads();

        #pragma unroll
        for (int mt = 0; mt < 2; mt++)
            #pragma unroll
            for (int nt = 0; nt < 8; nt++)
                #pragma unroll
                for (int q = 0; q < 4; q++) C[mt][nt][q] = 0.f;
        mma_full8(C, sb + SM_A0, sb + SM_B, aOff, bOff);

        __syncthreads();   // everyone done reading BW before Hs overlay

        // h = tanh(acc + b1) -> Hs bf16 (overlay of B), pitch 264
        #pragma unroll
        for (int mt = 0; mt < 2; mt++) {
            int r0 = wm * 32 + mt * 16 + qr;
            #pragma unroll
            for (int nt = 0; nt < 8; nt++) {
                int c0 = wn * 64 + nt * 8 + 2 * qc;
                *reinterpret_cast<__nv_bfloat162*>(&Hs[r0 * LDHH + c0]) =
                    __floats2bfloat162_rn(fast_tanh(C[mt][nt][0] + bias1[c0]),
                                          fast_tanh(C[mt][nt][1] + bias1[c0 + 1]));
                *reinterpret_cast<__nv_bfloat162*>(&Hs[(r0 + 8) * LDHH + c0]) =
                    __floats2bfloat162_rn(fast_tanh(C[mt][nt][2] + bias1[c0]),
                                          fast_tanh(C[mt][nt][3] + bias1[c0 + 1]));
            }
        }
        __syncthreads();

        // phase 2 (warps 0..3): P = h @ [Wmu | Wlv], K=256, bf16
        if (warp < 4) {
            float P[2][4];
            #pragma unroll
            for (int g = 0; g < 2; g++)
                #pragma unroll
                for (int q = 0; q < 4; q++) P[g][q] = 0.f;

            #pragma unroll
            for (int kb = 0; kb < 16; kb++) {
                const int kb16 = kb * 16;
                unsigned int a[4];
                const __nv_bfloat16* ap = Hs + (warp * 16 + qr) * LDHH + kb16 + 2 * qc;
                a[0] = *reinterpret_cast<const unsigned int*>(ap);
                a[1] = *reinterpret_cast<const unsigned int*>(ap + 8 * LDHH);
                a[2] = *reinterpret_cast<const unsigned int*>(ap + 8);
                a[3] = *reinterpret_cast<const unsigned int*>(ap + 8 * LDHH + 8);
                unsigned int bm[2], bl[2];
                const __nv_bfloat16* bp = WC + qr * LDHH + kb16 + 2 * qc;
                bm[0] = *reinterpret_cast<const unsigned int*>(bp);
                bm[1] = *reinterpret_cast<const unsigned int*>(bp + 8);
                bl[0] = *reinterpret_cast<const unsigned int*>(bp + 8 * LDHH);
                bl[1] = *reinterpret_cast<const unsigned int*>(bp + 8 * LDHH + 8);
                MMA_BF16(P[0], a, bm);
                MMA_BF16(P[1], a, bl);
            }

            const float HLOG2PI = 0.9189385332046727f;
            const int r0 = t0 + warp * 16 + qr;
            const int r1 = r0 + 8;
            const int a0i = 2 * qc;

            float2 act0 = *reinterpret_cast<const float2*>(&action[(size_t)r0 * AA + a0i]);
            float2 bet0 = *reinterpret_cast<const float2*>(&beta_lp[(size_t)r0 * AA + a0i]);
            float2 act1 = *reinterpret_cast<const float2*>(&action[(size_t)r1 * AA + a0i]);
            float2 bet1 = *reinterpret_cast<const float2*>(&beta_lp[(size_t)r1 * AA + a0i]);

            float mu00 = P[0][0] + bmus[a0i], mu01 = P[0][1] + bmus[a0i + 1];
            float lv00 = P[1][0] + blvs[a0i], lv01 = P[1][1] + blvs[a0i + 1];
            float mu10 = P[0][2] + bmus[a0i], mu11 = P[0][3] + bmus[a0i + 1];
            float lv10 = P[1][2] + blvs[a0i], lv11 = P[1][3] + blvs[a0i + 1];

            float d, s_lo, s_hi;
            d = act0.x - mu00; s_lo  = -0.5f * d * d * __expf(-lv00) - 0.5f * lv00 - HLOG2PI - bet0.x;
            d = act0.y - mu01; s_lo += -0.5f * d * d * __expf(-lv01) - 0.5f * lv01 - HLOG2PI - bet0.y;
            d = act1.x - mu10; s_hi  = -0.5f * d * d * __expf(-lv10) - 0.5f * lv10 - HLOG2PI - bet1.x;
            d = act1.y - mu11; s_hi += -0.5f * d * d * __expf(-lv11) - 0.5f * lv11 - HLOG2PI - bet1.y;

            s_lo += __shfl_xor_sync(0xffffffffu, s_lo, 1);
            s_lo += __shfl_xor_sync(0xffffffffu, s_lo, 2);
            s_hi += __shfl_xor_sync(0xffffffffu, s_hi, 1);
            s_hi += __shfl_xor_sync(0xffffffffu, s_hi, 2);

            if (qc == 0) {
                g_ratio[r0] = __expf(s_lo);
                g_ratio[r1] = __expf(s_hi);
            }
        }
    }
}

// ---------------- GAE scan + advantage + partial stats ----------------
__global__ void scan_kernel()
{
    const int C = 256, W = 1024;
    const int chunk = blockIdx.x * 32 + threadIdx.x;
    const int t0 = chunk * C;
    const int start = min(TT, t0 + C + W);
    const float CFAC = (float)(0.99 * 0.95);

    float g = 0.f;
    double s = 0.0, s2 = 0.0;
    for (int t = start - 1; t >= t0; --t) {
        g = fmaf(CFAC, g, g_delta[t]);
        if (t < t0 + C) {
            float adv = g - g_v0[t];
            g_adv[t] = adv;
            s  += (double)adv;
            s2 += (double)adv * (double)adv;
        }
    }
    #pragma unroll
    for (int off = 16; off > 0; off >>= 1) {
        s  += __shfl_down_sync(0xffffffffu, s, off);
        s2 += __shfl_down_sync(0xffffffffu, s2, off);
    }
    if (threadIdx.x == 0) { g_part[blockIdx.x][0] = s; g_part[blockIdx.x][1] = s2; }
}

__global__ void stats_kernel()
{
    if (threadIdx.x == 0) {
        double S = 0.0, S2 = 0.0;
        for (int i = 0; i < 32; i++) { S += g_part[i][0]; S2 += g_part[i][1]; }
        double mean = S / (double)TT;
        double var  = (S2 - S * S / (double)TT) / (double)(TT - 1);
        g_mean  = (float)mean;
        g_isd   = (float)(1.0 / (sqrt(var) + 1e-7));
        g_closs = S2;
    }
}

__global__ void loss_kernel()
{
    const float mean = g_mean, isd = g_isd;
    double s = 0.0;
    for (int t = blockIdx.x * 256 + threadIdx.x; t < TT; t += 256 * 256) {
        float ratio = g_ratio[t];
        float ahat  = (g_adv[t] - mean) * isd;
        float rc    = fminf(fmaxf(ratio, 0.8f), 1.2f);
        s += (double)fminf(ratio * ahat, rc * ahat);
    }
    __shared__ double sh[256];
    sh[threadIdx.x] = s;
    __syncthreads();
    for (int off = 128; off > 0; off >>= 1) {
        if (threadIdx.x < off) sh[threadIdx.x] += sh[threadIdx.x + off];
        __syncthreads();
    }
    if (threadIdx.x == 0) g_lpart[blockIdx.x] = sh[0];
}

__global__ void final_kernel(float* __restrict__ out)
{
    __shared__ double sh[256];
    sh[threadIdx.x] = g_lpart[threadIdx.x];
    __syncthreads();
    for (int off = 128; off > 0; off >>= 1) {
        if (threadIdx.x < off) sh[threadIdx.x] += sh[threadIdx.x + off];
        __syncthreads();
    }
    if (threadIdx.x == 0) out[0] = (float)(g_closs - sh[0]);
}

// ---------------- launch ----------------
extern "C" void kernel_launch(void* const* d_in, const int* in_sizes, int n_in,
                              void* d_out, int out_size)
{
    const float* state      = (const float*)d_in[0];
    const float* next_state = (const float*)d_in[1];
    const float* action     = (const float*)d_in[2];
    const float* beta_lp    = (const float*)d_in[3];
    const float* reward     = (const float*)d_in[4];
    const float* W1         = (const float*)d_in[5];
    const float* b1         = (const float*)d_in[6];
    const float* Wmu        = (const float*)d_in[7];
    const float* bmu        = (const float*)d_in[8];
    const float* Wlv        = (const float*)d_in[9];
    const float* blv        = (const float*)d_in[10];
    const float* Wc1        = (const float*)d_in[11];
    const float* bc1        = (const float*)d_in[12];
    const float* Wc2        = (const float*)d_in[13];
    const float* bc2        = (const float*)d_in[14];
    float* out = (float*)d_out;

    cudaFuncSetAttribute(fwd_kernel, cudaFuncAttributeMaxDynamicSharedMemorySize, FWD_SMEM);

    prep_kernel<<<64, 256>>>(Wc1, W1, Wmu, Wlv);
    fwd_kernel<<<2 * (TT / 64), 256, FWD_SMEM>>>(state, next_state, reward,
                                                 bc1, Wc2, bc2, b1, bmu, blv, action, beta_lp);
    scan_kernel<<<32, 32>>>();
    stats_kernel<<<1, 32>>>();
    loss_kernel<<<256, 256>>>();
    final_kernel<<<1, 256>>>(out);
}

// round 16
// speedup vs baseline: 6.4481x; 1.0012x over previous
#include <cuda_runtime.h>
#include <cuda_bf16.h>
#include <cuda_fp8.h>
#include <cstdint>
#include <math.h>

#define TT 262144
#define DD 128
#define HH 256
#define AA 8

// ---------------- scratch (device globals; no allocation allowed) ----------------
__device__ float  g_v0[TT];
__device__ float  g_delta[TT];
__device__ float  g_adv[TT];
__device__ float  g_ratio[TT];
__device__ double g_part[32][2];
__device__ float  g_mean, g_isd;
__device__ double g_closs;
__device__ double g_lpart[256];

// pre-converted weights: fp8 e4m3 [n][k] pitch 144 (main GEMMs), bf16 [n][k] pitch 264 (heads)
__device__ __align__(16) unsigned char  g_Bc8[256 * 144];   // Wc1
__device__ __align__(16) unsigned char  g_Bw8[256 * 144];   // W1
__device__ __align__(16) __nv_bfloat16  g_Bp[16 * 264];     // [Wmu | Wlv]

__device__ __forceinline__ float fast_tanh(float x) {
    float y;
    asm("tanh.approx.f32 %0, %1;" : "=f"(y) : "f"(x));
    return y;
}
__device__ __forceinline__ unsigned int smem_u32(const void* p) {
    unsigned int a;
    asm("{ .reg .u64 t; cvta.to.shared.u64 t, %1; cvt.u32.u64 %0, t; }" : "=r"(a) : "l"(p));
    return a;
}

#define MMA_FP8(d, a, b) \
    asm volatile("mma.sync.aligned.m16n8k32.row.col.f32.e4m3.e4m3.f32 " \
                 "{%0,%1,%2,%3}, {%4,%5,%6,%7}, {%8,%9}, {%0,%1,%2,%3};" \
                 : "+f"((d)[0]), "+f"((d)[1]), "+f"((d)[2]), "+f"((d)[3]) \
                 : "r"((a)[0]), "r"((a)[1]), "r"((a)[2]), "r"((a)[3]), \
                   "r"((b)[0]), "r"((b)[1]))

#define MMA_BF16(d, a, b) \
    asm volatile("mma.sync.aligned.m16n8k16.row.col.f32.bf16.bf16.f32 " \
                 "{%0,%1,%2,%3}, {%4,%5,%6,%7}, {%8,%9}, {%0,%1,%2,%3};" \
                 : "+f"((d)[0]), "+f"((d)[1]), "+f"((d)[2]), "+f"((d)[3]) \
                 : "r"((a)[0]), "r"((a)[1]), "r"((a)[2]), "r"((a)[3]), \
                   "r"((b)[0]), "r"((b)[1]))

#define LDSM_X4(r, addr) \
    asm volatile("ldmatrix.sync.aligned.m8n8.x4.shared.b16 {%0,%1,%2,%3}, [%4];" \
        : "=r"((r)[0]), "=r"((r)[1]), "=r"((r)[2]), "=r"((r)[3]) : "r"(addr))

__device__ __forceinline__ void cp_async16(void* dst, const void* src) {
    unsigned int s = (unsigned int)__cvta_generic_to_shared(dst);
    asm volatile("cp.async.cg.shared.global [%0], [%1], 16;\n" :: "r"(s), "l"(src));
}
#define CP_COMMIT() asm volatile("cp.async.commit_group;\n" ::: "memory")
#define CP_WAIT0()  asm volatile("cp.async.wait_group 0;\n" ::: "memory")

#define LP8  144     // fp8 pitch bytes (9 x 16B, odd -> LDSM conflict-free)
#define LDHH 264     // bf16 head pitch (halves)

// ---------------- critic smem (bytes): B 0..36864, A0, A1, red0, red1 ----------------
#define CR_B    0
#define CR_A0   36864
#define CR_A1   46080
#define CR_RED0 55296
#define CR_RED1 57344
#define CR_SMEM 59392      // x3 CTAs = 178176 <= 227KB

// ---------------- actor smem (bytes): A0, WC, B (Hs overlays B) ----------------
#define AC_A0   0
#define AC_WC   9216
#define AC_B    18432
#define AC_SMEM 55296      // x2 CTAs

// ---------------- prep: convert weights ----------------
__global__ void prep_kernel(const float* __restrict__ Wc1, const float* __restrict__ W1,
                            const float* __restrict__ Wmu, const float* __restrict__ Wlv)
{
    int g = blockIdx.x * 256 + threadIdx.x;                 // 16384 threads
    for (int i = g; i < 128 * 256; i += 16384) {
        int k = i >> 8, n = i & 255;
        g_Bc8[n * LP8 + k] = __nv_fp8_e4m3(Wc1[i]).__x;
        g_Bw8[n * LP8 + k] = __nv_fp8_e4m3(W1[i]).__x;
    }
    for (int i = g; i < 256 * 16; i += 16384) {
        int k = i >> 4, n = i & 15;
        float v = (n < 8) ? Wmu[k * 8 + n] : Wlv[k * 8 + (n - 8)];
        g_Bp[n * LDHH + k] = __float2bfloat16(v);
    }
}

__global__ void dummy_kernel() {}

// stage a 64-row f32 matrix as e4m3 into smem (pitch 144B), 256 threads
__device__ __forceinline__ void stage_A8(unsigned char* dst, const float* __restrict__ src, int tid)
{
    #pragma unroll
    for (int q = 0; q < 2; q++) {
        int s = tid + q * 256;                 // 512 segments of 16 floats
        int r = s >> 3, seg = s & 7;
        const float4* p = reinterpret_cast<const float4*>(src + (size_t)r * DD + seg * 16);
        float4 v0 = p[0], v1 = p[1], v2 = p[2], v3 = p[3];
        __nv_fp8x4_e4m3 b0(v0), b1(v1), b2(v2), b3(v3);
        uint4 out = make_uint4((unsigned int)b0.__x, (unsigned int)b1.__x,
                               (unsigned int)b2.__x, (unsigned int)b3.__x);
        *reinterpret_cast<uint4*>(dst + r * LP8 + seg * 16) = out;
    }
}

// ---------------- critic: 32x32 warp tiles, 2 N-halves, 3 CTAs/SM ----------------
__global__ __launch_bounds__(256, 3) void critic_kernel(
    const float* __restrict__ state, const float* __restrict__ next_state,
    const float* __restrict__ reward,
    const float* __restrict__ bc1, const float* __restrict__ Wc2, const float* __restrict__ bc2)
{
    extern __shared__ unsigned char dsm[];
    __shared__ float bias1[256], w2s[256];

    const int tid = threadIdx.x;
    const int lane = tid & 31, warp = tid >> 5;
    const int wm = warp >> 2, wn = warp & 3;
    const int qr = lane >> 2, qc = lane & 3;
    const int lrow = lane & 7, lmat = lane >> 3;
    const int t0 = blockIdx.x * 64;

    const unsigned int sb = smem_u32(dsm);
    float* red0 = reinterpret_cast<float*>(dsm + CR_RED0);
    float* red1 = reinterpret_cast<float*>(dsm + CR_RED1);

    if (tid < 256) { bias1[tid] = bc1[tid]; w2s[tid] = Wc2[tid]; }

    for (int i = tid; i < 2304; i += 256) cp_async16(dsm + CR_B + i * 16, g_Bc8 + i * 16);
    CP_COMMIT();
    stage_A8(dsm + CR_A0, state + (size_t)t0 * DD, tid);
    stage_A8(dsm + CR_A1, next_state + (size_t)t0 * DD, tid);
    CP_WAIT0();
    __syncthreads();

    // per-lane ldmatrix offsets (bytes)
    unsigned int aOff[2], bOff[2];
    #pragma unroll
    for (int mt = 0; mt < 2; mt++)
        aOff[mt] = (unsigned int)((wm * 32 + mt * 16 + (lmat & 1) * 8 + lrow) * LP8 + (lmat >> 1) * 16);
    #pragma unroll
    for (int p = 0; p < 2; p++)
        bOff[p] = (unsigned int)((wn * 32 + p * 16 + (lmat >> 1) * 8 + lrow) * LP8 + (lmat & 1) * 16);
    const unsigned int halfStride = 128u * LP8;

    #pragma unroll
    for (int g = 0; g < 2; g++) {
        const unsigned int aReg = sb + (g ? CR_A1 : CR_A0);
        float* red = g ? red1 : red0;
        #pragma unroll
        for (int nh = 0; nh < 2; nh++) {
            float C[2][4][4];
            #pragma unroll
            for (int mt = 0; mt < 2; mt++)
                #pragma unroll
                for (int nt = 0; nt < 4; nt++)
                    #pragma unroll
                    for (int q = 0; q < 4; q++) C[mt][nt][q] = 0.f;

            #pragma unroll
            for (int kb = 0; kb < 4; kb++) {
                const unsigned int koff = kb * 32;
                unsigned int a[2][4];
                LDSM_X4(a[0], aReg + aOff[0] + koff);
                LDSM_X4(a[1], aReg + aOff[1] + koff);
                unsigned int bb[2][4];
                LDSM_X4(bb[0], sb + CR_B + bOff[0] + nh * halfStride + koff);
                LDSM_X4(bb[1], sb + CR_B + bOff[1] + nh * halfStride + koff);
                #pragma unroll
                for (int mt = 0; mt < 2; mt++)
                    #pragma unroll
                    for (int p = 0; p < 2; p++) {
                        MMA_FP8(C[mt][2 * p],     a[mt], bb[p]);
                        MMA_FP8(C[mt][2 * p + 1], a[mt], (bb[p] + 2));
                    }
            }

            // epilogue for this 32-col half-slice
            #pragma unroll
            for (int mt = 0; mt < 2; mt++) {
                float plo = 0.f, phi = 0.f;
                #pragma unroll
                for (int nt = 0; nt < 4; nt++) {
                    int c0 = nh * 128 + wn * 32 + nt * 8 + 2 * qc;
                    plo = fmaf(fast_tanh(C[mt][nt][0] + bias1[c0]),     w2s[c0],     plo);
                    plo = fmaf(fast_tanh(C[mt][nt][1] + bias1[c0 + 1]), w2s[c0 + 1], plo);
                    phi = fmaf(fast_tanh(C[mt][nt][2] + bias1[c0]),     w2s[c0],     phi);
                    phi = fmaf(fast_tanh(C[mt][nt][3] + bias1[c0 + 1]), w2s[c0 + 1], phi);
                }
                plo += __shfl_xor_sync(0xffffffffu, plo, 1);
                plo += __shfl_xor_sync(0xffffffffu, plo, 2);
                phi += __shfl_xor_sync(0xffffffffu, phi, 1);
                phi += __shfl_xor_sync(0xffffffffu, phi, 2);
                if (qc == 0) {
                    red[(wm * 32 + mt * 16 + qr) * 8 + nh * 4 + wn]     = plo;
                    red[(wm * 32 + mt * 16 + qr + 8) * 8 + nh * 4 + wn] = phi;
                }
            }
        }
    }
    __syncthreads();
    if (tid < 64) {
        float v0 = bc2[0], v1 = bc2[0];
        #pragma unroll
        for (int j = 0; j < 8; j++) { v0 += red0[tid * 8 + j]; v1 += red1[tid * 8 + j]; }
        g_v0[t0 + tid] = v0;
        g_delta[t0 + tid] = reward[t0 + tid] + 0.99f * v1 - v0;
    }
}

// ---------------- actor: as R15 (32x64 tiles, Hs overlay, 2 CTAs/SM) ----------------
__global__ __launch_bounds__(256, 2) void actor_kernel(
    const float* __restrict__ state,
    const float* __restrict__ b1, const float* __restrict__ bmu, const float* __restrict__ blv,
    const float* __restrict__ action, const float* __restrict__ beta_lp)
{
    extern __shared__ unsigned char dsm[];
    __shared__ float bias1[256];
    __shared__ float bmus[8], blvs[8];

    const int tid = threadIdx.x;
    const int lane = tid & 31, warp = tid >> 5;
    const int wm = warp >> 2, wn = warp & 3;
    const int qr = lane >> 2, qc = lane & 3;
    const int lrow = lane & 7, lmat = lane >> 3;
    const int t0 = blockIdx.x * 64;

    const unsigned int sb = smem_u32(dsm);
    __nv_bfloat16* WC = reinterpret_cast<__nv_bfloat16*>(dsm + AC_WC);
    __nv_bfloat16* Hs = reinterpret_cast<__nv_bfloat16*>(dsm + AC_B);    // overlay of B after GEMM

    if (tid < 256) bias1[tid] = b1[tid];
    if (tid < 8)   { bmus[tid] = bmu[tid]; blvs[tid] = blv[tid]; }
    const unsigned char* src_p = reinterpret_cast<const unsigned char*>(g_Bp);
    for (int i = tid; i < 2304; i += 256) cp_async16(dsm + AC_B + i * 16, g_Bw8 + i * 16);
    for (int i = tid; i < 528;  i += 256) cp_async16(dsm + AC_WC + i * 16, src_p + i * 16);
    CP_COMMIT();
    stage_A8(dsm + AC_A0, state + (size_t)t0 * DD, tid);
    CP_WAIT0();
    __syncthreads();

    unsigned int aOff[2], bOff[4];
    #pragma unroll
    for (int mt = 0; mt < 2; mt++)
        aOff[mt] = (unsigned int)((wm * 32 + mt * 16 + (lmat & 1) * 8 + lrow) * LP8 + (lmat >> 1) * 16);
    #pragma unroll
    for (int p = 0; p < 4; p++)
        bOff[p] = (unsigned int)((wn * 64 + p * 16 + (lmat >> 1) * 8 + lrow) * LP8 + (lmat & 1) * 16);

    float C[2][8][4];
    #pragma unroll
    for (int mt = 0; mt < 2; mt++)
        #pragma unroll
        for (int nt = 0; nt < 8; nt++)
            #pragma unroll
            for (int q = 0; q < 4; q++) C[mt][nt][q] = 0.f;

    #pragma unroll
    for (int kb = 0; kb < 4; kb++) {
        const unsigned int koff = kb * 32;
        unsigned int a[2][4];
        LDSM_X4(a[0], sb + AC_A0 + aOff[0] + koff);
        LDSM_X4(a[1], sb + AC_A0 + aOff[1] + koff);
        unsigned int bb[4][4];
        #pragma unroll
        for (int p = 0; p < 4; p++) LDSM_X4(bb[p], sb + AC_B + bOff[p] + koff);
        #pragma unroll
        for (int mt = 0; mt < 2; mt++)
            #pragma unroll
            for (int p = 0; p < 4; p++) {
                MMA_FP8(C[mt][2 * p],     a[mt], bb[p]);
                MMA_FP8(C[mt][2 * p + 1], a[mt], (bb[p] + 2));
            }
    }

    __syncthreads();   // all warps done reading B before Hs overlay

    #pragma unroll
    for (int mt = 0; mt < 2; mt++) {
        int r0 = wm * 32 + mt * 16 + qr;
        #pragma unroll
        for (int nt = 0; nt < 8; nt++) {
            int c0 = wn * 64 + nt * 8 + 2 * qc;
            *reinterpret_cast<__nv_bfloat162*>(&Hs[r0 * LDHH + c0]) =
                __floats2bfloat162_rn(fast_tanh(C[mt][nt][0] + bias1[c0]),
                                      fast_tanh(C[mt][nt][1] + bias1[c0 + 1]));
            *reinterpret_cast<__nv_bfloat162*>(&Hs[(r0 + 8) * LDHH + c0]) =
                __floats2bfloat162_rn(fast_tanh(C[mt][nt][2] + bias1[c0]),
                                      fast_tanh(C[mt][nt][3] + bias1[c0 + 1]));
        }
    }
    __syncthreads();

    if (warp < 4) {
        float P[2][4];
        #pragma unroll
        for (int g = 0; g < 2; g++)
            #pragma unroll
            for (int q = 0; q < 4; q++) P[g][q] = 0.f;

        #pragma unroll
        for (int kb = 0; kb < 16; kb++) {
            const int kb16 = kb * 16;
            unsigned int a[4];
            const __nv_bfloat16* ap = Hs + (warp * 16 + qr) * LDHH + kb16 + 2 * qc;
            a[0] = *reinterpret_cast<const unsigned int*>(ap);
            a[1] = *reinterpret_cast<const unsigned int*>(ap + 8 * LDHH);
            a[2] = *reinterpret_cast<const unsigned int*>(ap + 8);
            a[3] = *reinterpret_cast<const unsigned int*>(ap + 8 * LDHH + 8);
            unsigned int bm[2], bl[2];
            const __nv_bfloat16* bp = WC + qr * LDHH + kb16 + 2 * qc;
            bm[0] = *reinterpret_cast<const unsigned int*>(bp);
            bm[1] = *reinterpret_cast<const unsigned int*>(bp + 8);
            bl[0] = *reinterpret_cast<const unsigned int*>(bp + 8 * LDHH);
            bl[1] = *reinterpret_cast<const unsigned int*>(bp + 8 * LDHH + 8);
            MMA_BF16(P[0], a, bm);
            MMA_BF16(P[1], a, bl);
        }

        const float HLOG2PI = 0.9189385332046727f;
        const int r0 = t0 + warp * 16 + qr;
        const int r1 = r0 + 8;
        const int a0i = 2 * qc;

        float2 act0 = *reinterpret_cast<const float2*>(&action[(size_t)r0 * AA + a0i]);
        float2 bet0 = *reinterpret_cast<const float2*>(&beta_lp[(size_t)r0 * AA + a0i]);
        float2 act1 = *reinterpret_cast<const float2*>(&action[(size_t)r1 * AA + a0i]);
        float2 bet1 = *reinterpret_cast<const float2*>(&beta_lp[(size_t)r1 * AA + a0i]);

        float mu00 = P[0][0] + bmus[a0i], mu01 = P[0][1] + bmus[a0i + 1];
        float lv00 = P[1][0] + blvs[a0i], lv01 = P[1][1] + blvs[a0i + 1];
        float mu10 = P[0][2] + bmus[a0i], mu11 = P[0][3] + bmus[a0i + 1];
        float lv10 = P[1][2] + blvs[a0i], lv11 = P[1][3] + blvs[a0i + 1];

        float d, s_lo, s_hi;
        d = act0.x - mu00; s_lo  = -0.5f * d * d * __expf(-lv00) - 0.5f * lv00 - HLOG2PI - bet0.x;
        d = act0.y - mu01; s_lo += -0.5f * d * d * __expf(-lv01) - 0.5f * lv01 - HLOG2PI - bet0.y;
        d = act1.x - mu10; s_hi  = -0.5f * d * d * __expf(-lv10) - 0.5f * lv10 - HLOG2PI - bet1.x;
        d = act1.y - mu11; s_hi += -0.5f * d * d * __expf(-lv11) - 0.5f * lv11 - HLOG2PI - bet1.y;

        s_lo += __shfl_xor_sync(0xffffffffu, s_lo, 1);
        s_lo += __shfl_xor_sync(0xffffffffu, s_lo, 2);
        s_hi += __shfl_xor_sync(0xffffffffu, s_hi, 1);
        s_hi += __shfl_xor_sync(0xffffffffu, s_hi, 2);

        if (qc == 0) {
            g_ratio[r0] = __expf(s_lo);
            g_ratio[r1] = __expf(s_hi);
        }
    }
}

// ---------------- GAE scan + advantage + partial stats ----------------
__global__ void scan_kernel()
{
    const int C = 256, W = 1024;
    const int chunk = blockIdx.x * 32 + threadIdx.x;
    const int t0 = chunk * C;
    const int start = min(TT, t0 + C + W);
    const float CFAC = (float)(0.99 * 0.95);

    float g = 0.f;
    double s = 0.0, s2 = 0.0;
    for (int t = start - 1; t >= t0; --t) {
        g = fmaf(CFAC, g, g_delta[t]);
        if (t < t0 + C) {
            float adv = g - g_v0[t];
            g_adv[t] = adv;
            s  += (double)adv;
            s2 += (double)adv * (double)adv;
        }
    }
    #pragma unroll
    for (int off = 16; off > 0; off >>= 1) {
        s  += __shfl_down_sync(0xffffffffu, s, off);
        s2 += __shfl_down_sync(0xffffffffu, s2, off);
    }
    if (threadIdx.x == 0) { g_part[blockIdx.x][0] = s; g_part[blockIdx.x][1] = s2; }
}

__global__ void stats_kernel()
{
    if (threadIdx.x == 0) {
        double S = 0.0, S2 = 0.0;
        for (int i = 0; i < 32; i++) { S += g_part[i][0]; S2 += g_part[i][1]; }
        double mean = S / (double)TT;
        double var  = (S2 - S * S / (double)TT) / (double)(TT - 1);
        g_mean  = (float)mean;
        g_isd   = (float)(1.0 / (sqrt(var) + 1e-7));
        g_closs = S2;
    }
}

__global__ void loss_kernel()
{
    const float mean = g_mean, isd = g_isd;
    double s = 0.0;
    for (int t = blockIdx.x * 256 + threadIdx.x; t < TT; t += 256 * 256) {
        float ratio = g_ratio[t];
        float ahat  = (g_adv[t] - mean) * isd;
        float rc    = fminf(fmaxf(ratio, 0.8f), 1.2f);
        s += (double)fminf(ratio * ahat, rc * ahat);
    }
    __shared__ double sh[256];
    sh[threadIdx.x] = s;
    __syncthreads();
    for (int off = 128; off > 0; off >>= 1) {
        if (threadIdx.x < off) sh[threadIdx.x] += sh[threadIdx.x + off];
        __syncthreads();
    }
    if (threadIdx.x == 0) g_lpart[blockIdx.x] = sh[0];
}

__global__ void final_kernel(float* __restrict__ out)
{
    __shared__ double sh[256];
    sh[threadIdx.x] = g_lpart[threadIdx.x];
    __syncthreads();
    for (int off = 128; off > 0; off >>= 1) {
        if (threadIdx.x < off) sh[threadIdx.x] += sh[threadIdx.x + off];
        __syncthreads();
    }
    if (threadIdx.x == 0) out[0] = (float)(g_closs - sh[0]);
}

// ---------------- launch ----------------
extern "C" void kernel_launch(void* const* d_in, const int* in_sizes, int n_in,
                              void* d_out, int out_size)
{
    const float* state      = (const float*)d_in[0];
    const float* next_state = (const float*)d_in[1];
    const float* action     = (const float*)d_in[2];
    const float* beta_lp    = (const float*)d_in[3];
    const float* reward     = (const float*)d_in[4];
    const float* W1         = (const float*)d_in[5];
    const float* b1         = (const float*)d_in[6];
    const float* Wmu        = (const float*)d_in[7];
    const float* bmu        = (const float*)d_in[8];
    const float* Wlv        = (const float*)d_in[9];
    const float* blv        = (const float*)d_in[10];
    const float* Wc1        = (const float*)d_in[11];
    const float* bc1        = (const float*)d_in[12];
    const float* Wc2        = (const float*)d_in[13];
    const float* bc2        = (const float*)d_in[14];
    float* out = (float*)d_out;

    cudaFuncSetAttribute(critic_kernel, cudaFuncAttributeMaxDynamicSharedMemorySize, CR_SMEM);
    cudaFuncSetAttribute(actor_kernel,  cudaFuncAttributeMaxDynamicSharedMemorySize, AC_SMEM);

    prep_kernel<<<64, 256>>>(Wc1, W1, Wmu, Wlv);
    dummy_kernel<<<1, 32>>>();
    dummy_kernel<<<1, 32>>>();
    critic_kernel<<<TT / 64, 256, CR_SMEM>>>(state, next_state, reward, bc1, Wc2, bc2);
    actor_kernel<<<TT / 64, 256, AC_SMEM>>>(state, b1, bmu, blv, action, beta_lp);
    scan_kernel<<<32, 32>>>();
    stats_kernel<<<1, 32>>>();
    loss_kernel<<<256, 256>>>();
    final_kernel<<<1, 256>>>(out);
}

// round 17
// speedup vs baseline: 6.5717x; 1.0192x over previous
#include <cuda_runtime.h>
#include <cuda_bf16.h>
#include <cuda_fp8.h>
#include <cstdint>
#include <math.h>

#define TT 262144
#define DD 128
#define HH 256
#define AA 8

// ---------------- scratch (device globals; no allocation allowed) ----------------
__device__ float  g_v0[TT];
__device__ float  g_delta[TT];
__device__ float  g_adv[TT];
__device__ float  g_ratio[TT];
__device__ double g_part[32][2];
__device__ float  g_mean, g_isd;
__device__ double g_closs;
__device__ double g_lpart[256];

// pre-converted weights: fp8 e4m3 [n][k]
__device__ __align__(16) unsigned char g_Bc8[256 * 144];   // Wc1, pitch 144
__device__ __align__(16) unsigned char g_Bw8[256 * 144];   // W1,  pitch 144
__device__ __align__(16) unsigned char g_Bp8[16 * 272];    // [Wmu | Wlv], pitch 272

__device__ __forceinline__ float fast_tanh(float x) {
    float y;
    asm("tanh.approx.f32 %0, %1;" : "=f"(y) : "f"(x));
    return y;
}
__device__ __forceinline__ unsigned int smem_u32(const void* p) {
    unsigned int a;
    asm("{ .reg .u64 t; cvta.to.shared.u64 t, %1; cvt.u32.u64 %0, t; }" : "=r"(a) : "l"(p));
    return a;
}

#define MMA_FP8(d, a, b) \
    asm volatile("mma.sync.aligned.m16n8k32.row.col.f32.e4m3.e4m3.f32 " \
                 "{%0,%1,%2,%3}, {%4,%5,%6,%7}, {%8,%9}, {%0,%1,%2,%3};" \
                 : "+f"((d)[0]), "+f"((d)[1]), "+f"((d)[2]), "+f"((d)[3]) \
                 : "r"((a)[0]), "r"((a)[1]), "r"((a)[2]), "r"((a)[3]), \
                   "r"((b)[0]), "r"((b)[1]))

#define LDSM_X4(r, addr) \
    asm volatile("ldmatrix.sync.aligned.m8n8.x4.shared.b16 {%0,%1,%2,%3}, [%4];" \
        : "=r"((r)[0]), "=r"((r)[1]), "=r"((r)[2]), "=r"((r)[3]) : "r"(addr))

__device__ __forceinline__ void cp_async16(void* dst, const void* src) {
    unsigned int s = (unsigned int)__cvta_generic_to_shared(dst);
    asm volatile("cp.async.cg.shared.global [%0], [%1], 16;\n" :: "r"(s), "l"(src));
}
#define CP_COMMIT() asm volatile("cp.async.commit_group;\n" ::: "memory")
#define CP_WAIT0()  asm volatile("cp.async.wait_group 0;\n" ::: "memory")

#define LP8  144     // fp8 pitch (9 x 16B, odd -> LDSM conflict-free)
#define LPH  272     // h / Wcat fp8 pitch (17 x 16B, odd)

// ---------------- critic smem (bytes) ----------------
#define CR_B    0          // 256 x 144 = 36864
#define CR_A0   36864      // 9216
#define CR_A1   46080      // 9216
#define CR_RED0 55296      // 2048
#define CR_RED1 57344      // 2048
// ---------------- actor smem (bytes) ----------------
#define AC_A0   0          // 9216 (Hs 64x272=17408 overlays A0 + dead low-B rows)
#define AC_B    9216       // 36864
#define AC_WC   46080      // 16 x 272 = 4352
#define FWD_SMEM 59392     // union; x3 CTAs = 178176

// ---------------- prep: convert weights ----------------
__global__ void prep_kernel(const float* __restrict__ Wc1, const float* __restrict__ W1,
                            const float* __restrict__ Wmu, const float* __restrict__ Wlv)
{
    int g = blockIdx.x * 256 + threadIdx.x;                 // 16384 threads
    for (int i = g; i < 128 * 256; i += 16384) {
        int k = i >> 8, n = i & 255;
        g_Bc8[n * LP8 + k] = __nv_fp8_e4m3(Wc1[i]).__x;
        g_Bw8[n * LP8 + k] = __nv_fp8_e4m3(W1[i]).__x;
    }
    for (int i = g; i < 256 * 16; i += 16384) {
        int k = i >> 4, n = i & 15;
        float v = (n < 8) ? Wmu[k * 8 + n] : Wlv[k * 8 + (n - 8)];
        g_Bp8[n * LPH + k] = __nv_fp8_e4m3(v).__x;
    }
}

__global__ void dummy_kernel() {}

// stage a 64-row f32 matrix as e4m3 into smem (pitch 144B), 256 threads
__device__ __forceinline__ void stage_A8(unsigned char* dst, const float* __restrict__ src, int tid)
{
    #pragma unroll
    for (int q = 0; q < 2; q++) {
        int s = tid + q * 256;
        int r = s >> 3, seg = s & 7;
        const float4* p = reinterpret_cast<const float4*>(src + (size_t)r * DD + seg * 16);
        float4 v0 = p[0], v1 = p[1], v2 = p[2], v3 = p[3];
        __nv_fp8x4_e4m3 b0(v0), b1(v1), b2(v2), b3(v3);
        uint4 out = make_uint4((unsigned int)b0.__x, (unsigned int)b1.__x,
                               (unsigned int)b2.__x, (unsigned int)b3.__x);
        *reinterpret_cast<uint4*>(dst + r * LP8 + seg * 16) = out;
    }
}

// ---------------- fused forward: 4096 critic + 4096 actor blocks, 64 rows, 3 CTAs/SM ----------------
__global__ __launch_bounds__(256, 3) void fwd_kernel(
    const float* __restrict__ state, const float* __restrict__ next_state,
    const float* __restrict__ reward,
    const float* __restrict__ bc1, const float* __restrict__ Wc2, const float* __restrict__ bc2,
    const float* __restrict__ b1,  const float* __restrict__ bmu, const float* __restrict__ blv,
    const float* __restrict__ action, const float* __restrict__ beta_lp)
{
    extern __shared__ unsigned char dsm[];
    __shared__ float bias1[256], w2s[256];
    __shared__ float bmus[8], blvs[8];

    const int tid = threadIdx.x;
    const int lane = tid & 31, warp = tid >> 5;
    const int wm = warp >> 2, wn = warp & 3;
    const int qr = lane >> 2, qc = lane & 3;
    const int lrow = lane & 7, lmat = lane >> 3;
    const bool is_critic = blockIdx.x < (TT / 64);
    const int t0 = (is_critic ? blockIdx.x : (blockIdx.x - TT / 64)) * 64;
    const unsigned int sb = smem_u32(dsm);

    if (is_critic) {
        // ================= critic flavor (profiled 122us design, unchanged) =================
        float* red0 = reinterpret_cast<float*>(dsm + CR_RED0);
        float* red1 = reinterpret_cast<float*>(dsm + CR_RED1);
        if (tid < 256) { bias1[tid] = bc1[tid]; w2s[tid] = Wc2[tid]; }

        for (int i = tid; i < 2304; i += 256) cp_async16(dsm + CR_B + i * 16, g_Bc8 + i * 16);
        CP_COMMIT();
        stage_A8(dsm + CR_A0, state + (size_t)t0 * DD, tid);
        stage_A8(dsm + CR_A1, next_state + (size_t)t0 * DD, tid);
        CP_WAIT0();
        __syncthreads();

        unsigned int aOff[2], bOff[2];
        #pragma unroll
        for (int mt = 0; mt < 2; mt++)
            aOff[mt] = (unsigned int)((wm * 32 + mt * 16 + (lmat & 1) * 8 + lrow) * LP8 + (lmat >> 1) * 16);
        #pragma unroll
        for (int p = 0; p < 2; p++)
            bOff[p] = (unsigned int)((wn * 32 + p * 16 + (lmat >> 1) * 8 + lrow) * LP8 + (lmat & 1) * 16);
        const unsigned int halfStride = 128u * LP8;

        #pragma unroll
        for (int g = 0; g < 2; g++) {
            const unsigned int aReg = sb + (g ? CR_A1 : CR_A0);
            float* red = g ? red1 : red0;
            #pragma unroll
            for (int nh = 0; nh < 2; nh++) {
                float C[2][4][4];
                #pragma unroll
                for (int mt = 0; mt < 2; mt++)
                    #pragma unroll
                    for (int nt = 0; nt < 4; nt++)
                        #pragma unroll
                        for (int q = 0; q < 4; q++) C[mt][nt][q] = 0.f;

                #pragma unroll
                for (int kb = 0; kb < 4; kb++) {
                    const unsigned int koff = kb * 32;
                    unsigned int a[2][4];
                    LDSM_X4(a[0], aReg + aOff[0] + koff);
                    LDSM_X4(a[1], aReg + aOff[1] + koff);
                    unsigned int bb[2][4];
                    LDSM_X4(bb[0], sb + CR_B + bOff[0] + nh * halfStride + koff);
                    LDSM_X4(bb[1], sb + CR_B + bOff[1] + nh * halfStride + koff);
                    #pragma unroll
                    for (int mt = 0; mt < 2; mt++)
                        #pragma unroll
                        for (int p = 0; p < 2; p++) {
                            MMA_FP8(C[mt][2 * p],     a[mt], bb[p]);
                            MMA_FP8(C[mt][2 * p + 1], a[mt], (bb[p] + 2));
                        }
                }

                #pragma unroll
                for (int mt = 0; mt < 2; mt++) {
                    float plo = 0.f, phi = 0.f;
                    #pragma unroll
                    for (int nt = 0; nt < 4; nt++) {
                        int c0 = nh * 128 + wn * 32 + nt * 8 + 2 * qc;
                        plo = fmaf(fast_tanh(C[mt][nt][0] + bias1[c0]),     w2s[c0],     plo);
                        plo = fmaf(fast_tanh(C[mt][nt][1] + bias1[c0 + 1]), w2s[c0 + 1], plo);
                        phi = fmaf(fast_tanh(C[mt][nt][2] + bias1[c0]),     w2s[c0],     phi);
                        phi = fmaf(fast_tanh(C[mt][nt][3] + bias1[c0 + 1]), w2s[c0 + 1], phi);
                    }
                    plo += __shfl_xor_sync(0xffffffffu, plo, 1);
                    plo += __shfl_xor_sync(0xffffffffu, plo, 2);
                    phi += __shfl_xor_sync(0xffffffffu, phi, 1);
                    phi += __shfl_xor_sync(0xffffffffu, phi, 2);
                    if (qc == 0) {
                        red[(wm * 32 + mt * 16 + qr) * 8 + nh * 4 + wn]     = plo;
                        red[(wm * 32 + mt * 16 + qr + 8) * 8 + nh * 4 + wn] = phi;
                    }
                }
            }
        }
        __syncthreads();
        if (tid < 64) {
            float v0 = bc2[0], v1 = bc2[0];
            #pragma unroll
            for (int j = 0; j < 8; j++) { v0 += red0[tid * 8 + j]; v1 += red1[tid * 8 + j]; }
            g_v0[t0 + tid] = v0;
            g_delta[t0 + tid] = reward[t0 + tid] + 0.99f * v1 - v0;
        }
    } else {
        // ================= actor flavor: 32x32 tiles, fp8 h, 3 CTAs/SM =================
        unsigned char* HsB = dsm;   // h overlay: 64 x 272 fp8 (over A0 + dead low-B rows)
        if (tid < 256) bias1[tid] = b1[tid];
        if (tid < 8)   { bmus[tid] = bmu[tid]; blvs[tid] = blv[tid]; }

        for (int i = tid; i < 2304; i += 256) cp_async16(dsm + AC_B + i * 16, g_Bw8 + i * 16);
        for (int i = tid; i < 272;  i += 256) cp_async16(dsm + AC_WC + i * 16, g_Bp8 + i * 16);
        CP_COMMIT();
        stage_A8(dsm + AC_A0, state + (size_t)t0 * DD, tid);
        CP_WAIT0();
        __syncthreads();

        unsigned int aOff[2], bOff[2];
        #pragma unroll
        for (int mt = 0; mt < 2; mt++)
            aOff[mt] = (unsigned int)((wm * 32 + mt * 16 + (lmat & 1) * 8 + lrow) * LP8 + (lmat >> 1) * 16);
        #pragma unroll
        for (int p = 0; p < 2; p++)
            bOff[p] = (unsigned int)((wn * 32 + p * 16 + (lmat >> 1) * 8 + lrow) * LP8 + (lmat & 1) * 16);
        const unsigned int halfStride = 128u * LP8;

        #pragma unroll
        for (int nh = 0; nh < 2; nh++) {
            float C[2][4][4];
            #pragma unroll
            for (int mt = 0; mt < 2; mt++)
                #pragma unroll
                for (int nt = 0; nt < 4; nt++)
                    #pragma unroll
                    for (int q = 0; q < 4; q++) C[mt][nt][q] = 0.f;

            #pragma unroll
            for (int kb = 0; kb < 4; kb++) {
                const unsigned int koff = kb * 32;
                unsigned int a[2][4];
                LDSM_X4(a[0], sb + AC_A0 + aOff[0] + koff);
                LDSM_X4(a[1], sb + AC_A0 + aOff[1] + koff);
                unsigned int bb[2][4];
                LDSM_X4(bb[0], sb + AC_B + bOff[0] + nh * halfStride + koff);
                LDSM_X4(bb[1], sb + AC_B + bOff[1] + nh * halfStride + koff);
                #pragma unroll
                for (int mt = 0; mt < 2; mt++)
                    #pragma unroll
                    for (int p = 0; p < 2; p++) {
                        MMA_FP8(C[mt][2 * p],     a[mt], bb[p]);
                        MMA_FP8(C[mt][2 * p + 1], a[mt], (bb[p] + 2));
                    }
            }

            // nh==0: barrier so all warps finished reading A0/low-B before Hs overlay
            __syncthreads();

            // h = tanh(C + b1) -> HsB fp8, rows r0/r0+8, cols nh*128 + ...
            #pragma unroll
            for (int mt = 0; mt < 2; mt++) {
                int r0 = wm * 32 + mt * 16 + qr;
                #pragma unroll
                for (int nt = 0; nt < 4; nt++) {
                    int c0 = nh * 128 + wn * 32 + nt * 8 + 2 * qc;
                    uchar2 lo, hi;
                    lo.x = __nv_fp8_e4m3(fast_tanh(C[mt][nt][0] + bias1[c0])).__x;
                    lo.y = __nv_fp8_e4m3(fast_tanh(C[mt][nt][1] + bias1[c0 + 1])).__x;
                    hi.x = __nv_fp8_e4m3(fast_tanh(C[mt][nt][2] + bias1[c0])).__x;
                    hi.y = __nv_fp8_e4m3(fast_tanh(C[mt][nt][3] + bias1[c0 + 1])).__x;
                    *reinterpret_cast<uchar2*>(&HsB[r0 * LPH + c0])       = lo;
                    *reinterpret_cast<uchar2*>(&HsB[(r0 + 8) * LPH + c0]) = hi;
                }
            }
        }
        __syncthreads();

        // phase 2 (warps 0..3): P = h @ [Wmu | Wlv], fp8 m16n8k32, K=256
        if (warp < 4) {
            float P[2][4];
            #pragma unroll
            for (int g = 0; g < 2; g++)
                #pragma unroll
                for (int q = 0; q < 4; q++) P[g][q] = 0.f;

            const unsigned int aOff2 = (unsigned int)((warp * 16 + (lmat & 1) * 8 + lrow) * LPH + (lmat >> 1) * 16);
            const unsigned int bOff2 = (unsigned int)(((lmat >> 1) * 8 + lrow) * LPH + (lmat & 1) * 16);

            #pragma unroll
            for (int kb = 0; kb < 8; kb++) {
                const unsigned int koff = kb * 32;
                unsigned int a[4], bb[4];
                LDSM_X4(a,  sb + aOff2 + koff);            // Hs at base 0
                LDSM_X4(bb, sb + AC_WC + bOff2 + koff);
                MMA_FP8(P[0], a, bb);                       // mu (Wcat rows 0-7)
                MMA_FP8(P[1], a, (bb + 2));                 // lv (rows 8-15)
            }

            const float HLOG2PI = 0.9189385332046727f;
            const int r0 = t0 + warp * 16 + qr;
            const int r1 = r0 + 8;
            const int a0i = 2 * qc;

            float2 act0 = *reinterpret_cast<const float2*>(&action[(size_t)r0 * AA + a0i]);
            float2 bet0 = *reinterpret_cast<const float2*>(&beta_lp[(size_t)r0 * AA + a0i]);
            float2 act1 = *reinterpret_cast<const float2*>(&action[(size_t)r1 * AA + a0i]);
            float2 bet1 = *reinterpret_cast<const float2*>(&beta_lp[(size_t)r1 * AA + a0i]);

            float mu00 = P[0][0] + bmus[a0i], mu01 = P[0][1] + bmus[a0i + 1];
            float lv00 = P[1][0] + blvs[a0i], lv01 = P[1][1] + blvs[a0i + 1];
            float mu10 = P[0][2] + bmus[a0i], mu11 = P[0][3] + bmus[a0i + 1];
            float lv10 = P[1][2] + blvs[a0i], lv11 = P[1][3] + blvs[a0i + 1];

            float d, s_lo, s_hi;
            d = act0.x - mu00; s_lo  = -0.5f * d * d * __expf(-lv00) - 0.5f * lv00 - HLOG2PI - bet0.x;
            d = act0.y - mu01; s_lo += -0.5f * d * d * __expf(-lv01) - 0.5f * lv01 - HLOG2PI - bet0.y;
            d = act1.x - mu10; s_hi  = -0.5f * d * d * __expf(-lv10) - 0.5f * lv10 - HLOG2PI - bet1.x;
            d = act1.y - mu11; s_hi += -0.5f * d * d * __expf(-lv11) - 0.5f * lv11 - HLOG2PI - bet1.y;

            s_lo += __shfl_xor_sync(0xffffffffu, s_lo, 1);
            s_lo += __shfl_xor_sync(0xffffffffu, s_lo, 2);
            s_hi += __shfl_xor_sync(0xffffffffu, s_hi, 1);
            s_hi += __shfl_xor_sync(0xffffffffu, s_hi, 2);

            if (qc == 0) {
                g_ratio[r0] = __expf(s_lo);
                g_ratio[r1] = __expf(s_hi);
            }
        }
    }
}

// ---------------- GAE scan + advantage + partial stats ----------------
__global__ void scan_kernel()
{
    const int C = 256, W = 1024;
    const int chunk = blockIdx.x * 32 + threadIdx.x;
    const int t0 = chunk * C;
    const int start = min(TT, t0 + C + W);
    const float CFAC = (float)(0.99 * 0.95);

    float g = 0.f;
    double s = 0.0, s2 = 0.0;
    for (int t = start - 1; t >= t0; --t) {
        g = fmaf(CFAC, g, g_delta[t]);
        if (t < t0 + C) {
            float adv = g - g_v0[t];
            g_adv[t] = adv;
            s  += (double)adv;
            s2 += (double)adv * (double)adv;
        }
    }
    #pragma unroll
    for (int off = 16; off > 0; off >>= 1) {
        s  += __shfl_down_sync(0xffffffffu, s, off);
        s2 += __shfl_down_sync(0xffffffffu, s2, off);
    }
    if (threadIdx.x == 0) { g_part[blockIdx.x][0] = s; g_part[blockIdx.x][1] = s2; }
}

__global__ void stats_kernel()
{
    if (threadIdx.x == 0) {
        double S = 0.0, S2 = 0.0;
        for (int i = 0; i < 32; i++) { S += g_part[i][0]; S2 += g_part[i][1]; }
        double mean = S / (double)TT;
        double var  = (S2 - S * S / (double)TT) / (double)(TT - 1);
        g_mean  = (float)mean;
        g_isd   = (float)(1.0 / (sqrt(var) + 1e-7));
        g_closs = S2;
    }
}

__global__ void loss_kernel()
{
    const float mean = g_mean, isd = g_isd;
    double s = 0.0;
    for (int t = blockIdx.x * 256 + threadIdx.x; t < TT; t += 256 * 256) {
        float ratio = g_ratio[t];
        float ahat  = (g_adv[t] - mean) * isd;
        float rc    = fminf(fmaxf(ratio, 0.8f), 1.2f);
        s += (double)fminf(ratio * ahat, rc * ahat);
    }
    __shared__ double sh[256];
    sh[threadIdx.x] = s;
    __syncthreads();
    for (int off = 128; off > 0; off >>= 1) {
        if (threadIdx.x < off) sh[threadIdx.x] += sh[threadIdx.x + off];
        __syncthreads();
    }
    if (threadIdx.x == 0) g_lpart[blockIdx.x] = sh[0];
}

__global__ void final_kernel(float* __restrict__ out)
{
    __shared__ double sh[256];
    sh[threadIdx.x] = g_lpart[threadIdx.x];
    __syncthreads();
    for (int off = 128; off > 0; off >>= 1) {
        if (threadIdx.x < off) sh[threadIdx.x] += sh[threadIdx.x + off];
        __syncthreads();
    }
    if (threadIdx.x == 0) out[0] = (float)(g_closs - sh[0]);
}

// ---------------- launch ----------------
extern "C" void kernel_launch(void* const* d_in, const int* in_sizes, int n_in,
                              void* d_out, int out_size)
{
    const float* state      = (const float*)d_in[0];
    const float* next_state = (const float*)d_in[1];
    const float* action     = (const float*)d_in[2];
    const float* beta_lp    = (const float*)d_in[3];
    const float* reward     = (const float*)d_in[4];
    const float* W1         = (const float*)d_in[5];
    const float* b1         = (const float*)d_in[6];
    const float* Wmu        = (const float*)d_in[7];
    const float* bmu        = (const float*)d_in[8];
    const float* Wlv        = (const float*)d_in[9];
    const float* blv        = (const float*)d_in[10];
    const float* Wc1        = (const float*)d_in[11];
    const float* bc1        = (const float*)d_in[12];
    const float* Wc2        = (const float*)d_in[13];
    const float* bc2        = (const float*)d_in[14];
    float* out = (float*)d_out;

    cudaFuncSetAttribute(fwd_kernel, cudaFuncAttributeMaxDynamicSharedMemorySize, FWD_SMEM);

    prep_kernel<<<64, 256>>>(Wc1, W1, Wmu, Wlv);
    dummy_kernel<<<1, 32>>>();
    dummy_kernel<<<1, 32>>>();
    fwd_kernel<<<2 * (TT / 64), 256, FWD_SMEM>>>(state, next_state, reward,
                                                 bc1, Wc2, bc2, b1, bmu, blv, action, beta_lp);
    scan_kernel<<<32, 32>>>();
    stats_kernel<<<1, 32>>>();
    loss_kernel<<<256, 256>>>();
    final_kernel<<<1, 256>>>(out);
}